// round 5
// baseline (speedup 1.0000x reference)
#include <cuda_runtime.h>
#include <math.h>

#define BB   2
#define TT   1024
#define DD   768
#define LL   4
#define HH   12
#define HDD  64
#define VV   50257
#define MTOK (BB * TT)   // 2048 token rows

// ---------------- scratch (allocation-free: __device__ globals) ----------------
__device__ float g_x  [MTOK * DD];        // residual stream
__device__ float g_h  [MTOK * DD];        // layernorm output
__device__ float g_qkv[MTOK * 3 * DD];    // qkv projection
__device__ float g_att[MTOK * DD];        // attention output
__device__ float g_mlp[MTOK * 4 * DD];    // mlp hidden

// ---------------- embedding: x = wte[ids] + wpe[t] ----------------
__global__ void embed_k(const int* __restrict__ ids, const float* __restrict__ wte,
                        const float* __restrict__ wpe, float* __restrict__ x) {
    int row = blockIdx.x;          // 0..2047
    int t   = row % TT;
    int id  = ids[row];
    const float* we = wte + (size_t)id * DD;
    const float* pe = wpe + (size_t)t * DD;
    float* xr = x + (size_t)row * DD;
    for (int d = threadIdx.x; d < DD; d += blockDim.x)
        xr[d] = we[d] + pe[d];
}

// ---------------- layernorm: one block per row ----------------
__global__ __launch_bounds__(256) void ln_k(const float* __restrict__ x,
                                            const float* __restrict__ g,
                                            const float* __restrict__ b,
                                            float* __restrict__ y) {
    int row = blockIdx.x;
    const float* xr = x + (size_t)row * DD;
    float s = 0.f, ss = 0.f;
    for (int d = threadIdx.x; d < DD; d += 256) {
        float v = xr[d];
        s += v; ss += v * v;
    }
    __shared__ float rs[8], rss[8];
    #pragma unroll
    for (int o = 16; o; o >>= 1) {
        s  += __shfl_xor_sync(0xffffffffu, s,  o);
        ss += __shfl_xor_sync(0xffffffffu, ss, o);
    }
    int w = threadIdx.x >> 5;
    if ((threadIdx.x & 31) == 0) { rs[w] = s; rss[w] = ss; }
    __syncthreads();
    if (threadIdx.x < 32) {
        s  = (threadIdx.x < 8) ? rs[threadIdx.x]  : 0.f;
        ss = (threadIdx.x < 8) ? rss[threadIdx.x] : 0.f;
        #pragma unroll
        for (int o = 4; o; o >>= 1) {
            s  += __shfl_xor_sync(0xffffffffu, s,  o);
            ss += __shfl_xor_sync(0xffffffffu, ss, o);
        }
        if (threadIdx.x == 0) { rs[0] = s; rss[0] = ss; }
    }
    __syncthreads();
    float mu  = rs[0]  * (1.f / DD);
    float var = rss[0] * (1.f / DD) - mu * mu;
    float inv = rsqrtf(var + 1e-5f);
    float* yr = y + (size_t)row * DD;
    for (int d = threadIdx.x; d < DD; d += 256)
        yr[d] = g[d] * (xr[d] - mu) * inv + b[d];
}

// ---------------- generic NN GEMM: C = A(MxK) @ W(KxN) with fused epilogue ----------------
// Requires: M % 64 == 0, N % 64 == 0, K % 16 == 0, N % 4 == 0 (true for all in-layer GEMMs)
#define EPI_BIAS      1
#define EPI_BIAS_GELU 2
#define EPI_BIAS_RES  3

__device__ __forceinline__ float gelu_exact(float v) {
    return 0.5f * v * (1.0f + erff(v * 0.70710678118654752440f));
}

template <int EPI>
__global__ __launch_bounds__(256) void gemm_nn(const float* __restrict__ A,
                                               const float* __restrict__ W,
                                               const float* __restrict__ bias,
                                               const float* __restrict__ res,
                                               float* __restrict__ C,
                                               int M, int N, int K) {
    __shared__ float As[16][64];   // [k][m]
    __shared__ float Ws[16][64];   // [k][n]
    int tid = threadIdx.x;
    int tx = tid & 15, ty = tid >> 4;          // 16 x 16
    int row0 = blockIdx.y * 64, col0 = blockIdx.x * 64;

    float acc[4][4];
    #pragma unroll
    for (int i = 0; i < 4; i++)
        #pragma unroll
        for (int j = 0; j < 4; j++) acc[i][j] = 0.f;

    int ar = tid >> 2;            // 0..63  (m within tile)
    int ac = (tid & 3) * 4;       // 0,4,8,12 (k within tile)
    int wr = tid >> 4;            // 0..15  (k within tile)
    int wc = (tid & 15) * 4;      // n within tile

    for (int k0 = 0; k0 < K; k0 += 16) {
        float4 av = *(const float4*)&A[(size_t)(row0 + ar) * K + k0 + ac];
        As[ac + 0][ar] = av.x; As[ac + 1][ar] = av.y;
        As[ac + 2][ar] = av.z; As[ac + 3][ar] = av.w;
        float4 wv = *(const float4*)&W[(size_t)(k0 + wr) * N + col0 + wc];
        *(float4*)&Ws[wr][wc] = wv;
        __syncthreads();
        #pragma unroll
        for (int kk = 0; kk < 16; kk++) {
            float4 a4 = *(const float4*)&As[kk][ty * 4];
            float4 b4 = *(const float4*)&Ws[kk][tx * 4];
            float a[4] = {a4.x, a4.y, a4.z, a4.w};
            float b[4] = {b4.x, b4.y, b4.z, b4.w};
            #pragma unroll
            for (int i = 0; i < 4; i++)
                #pragma unroll
                for (int j = 0; j < 4; j++)
                    acc[i][j] = fmaf(a[i], b[j], acc[i][j]);
        }
        __syncthreads();
    }

    #pragma unroll
    for (int i = 0; i < 4; i++) {
        int row = row0 + ty * 4 + i;
        #pragma unroll
        for (int j = 0; j < 4; j++) {
            int col = col0 + tx * 4 + j;
            float v = acc[i][j] + bias[col];
            if (EPI == EPI_BIAS_GELU) v = gelu_exact(v);
            if (EPI == EPI_BIAS_RES)  v += res[(size_t)row * N + col];
            C[(size_t)row * N + col] = v;
        }
    }
}

// ---------------- NT GEMM for lm_head: C[m,n] = sum_k A[m,k]*B[n,k] ----------------
// M % 64 == 0, K % 16 == 0; N arbitrary (bounds-checked).
__global__ __launch_bounds__(256) void gemm_nt(const float* __restrict__ A,
                                               const float* __restrict__ B,
                                               float* __restrict__ C,
                                               int M, int N, int K) {
    __shared__ float As[64][17];
    __shared__ float Bs[64][17];
    int tid = threadIdx.x;
    int tx = tid & 15, ty = tid >> 4;
    int row0 = blockIdx.y * 64, col0 = blockIdx.x * 64;

    float acc[4][4];
    #pragma unroll
    for (int i = 0; i < 4; i++)
        #pragma unroll
        for (int j = 0; j < 4; j++) acc[i][j] = 0.f;

    int r = tid >> 2;             // 0..63
    int c = (tid & 3) * 4;        // k offset

    for (int k0 = 0; k0 < K; k0 += 16) {
        float4 av = *(const float4*)&A[(size_t)(row0 + r) * K + k0 + c];
        As[r][c + 0] = av.x; As[r][c + 1] = av.y; As[r][c + 2] = av.z; As[r][c + 3] = av.w;
        int n = col0 + r;
        if (n < N) {
            float4 bv = *(const float4*)&B[(size_t)n * K + k0 + c];
            Bs[r][c + 0] = bv.x; Bs[r][c + 1] = bv.y; Bs[r][c + 2] = bv.z; Bs[r][c + 3] = bv.w;
        } else {
            Bs[r][c + 0] = 0.f; Bs[r][c + 1] = 0.f; Bs[r][c + 2] = 0.f; Bs[r][c + 3] = 0.f;
        }
        __syncthreads();
        #pragma unroll
        for (int kk = 0; kk < 16; kk++) {
            float a[4], b[4];
            #pragma unroll
            for (int i = 0; i < 4; i++) a[i] = As[ty * 4 + i][kk];
            #pragma unroll
            for (int j = 0; j < 4; j++) b[j] = Bs[tx * 4 + j][kk];
            #pragma unroll
            for (int i = 0; i < 4; i++)
                #pragma unroll
                for (int j = 0; j < 4; j++)
                    acc[i][j] = fmaf(a[i], b[j], acc[i][j]);
        }
        __syncthreads();
    }

    #pragma unroll
    for (int i = 0; i < 4; i++) {
        int row = row0 + ty * 4 + i;
        #pragma unroll
        for (int j = 0; j < 4; j++) {
            int col = col0 + tx * 4 + j;
            if (col < N)
                C[(size_t)row * N + col] = acc[i][j];
        }
    }
}

// ---------------- causal flash attention ----------------
// grid (T/64, H, B), 64 threads; thread = one query; K/V tiles in SMEM.
__global__ __launch_bounds__(64) void attn_k(const float* __restrict__ qkv,
                                             float* __restrict__ out) {
    int qt   = blockIdx.x;       // query tile 0..15
    int h    = blockIdx.y;
    int b    = blockIdx.z;
    int lane = threadIdx.x;      // 0..63
    int q    = qt * 64 + lane;

    __shared__ float Ks[64][64];
    __shared__ float Vs[64][64];

    const float* qp = &qkv[(size_t)(b * TT + q) * (3 * DD) + h * HDD];
    float qv[64];
    #pragma unroll
    for (int i = 0; i < 16; i++) {
        float4 t = ((const float4*)qp)[i];
        qv[4 * i + 0] = t.x; qv[4 * i + 1] = t.y; qv[4 * i + 2] = t.z; qv[4 * i + 3] = t.w;
    }

    float acc[64];
    #pragma unroll
    for (int d = 0; d < 64; d++) acc[d] = 0.f;
    float m = -1e30f, l = 0.f;
    const float scale = 0.125f;  // 1/sqrt(64)

    for (int kt = 0; kt <= qt; kt++) {
        const float* kp = &qkv[(size_t)(b * TT + kt * 64 + lane) * (3 * DD) + DD + h * HDD];
        const float* vp = kp + DD;
        #pragma unroll
        for (int i = 0; i < 16; i++) {
            ((float4*)Ks[lane])[i] = ((const float4*)kp)[i];
            ((float4*)Vs[lane])[i] = ((const float4*)vp)[i];
        }
        __syncthreads();

        int jmax = (kt == qt) ? lane : 63;
        for (int j = 0; j <= jmax; j++) {
            float s = 0.f;
            #pragma unroll
            for (int d = 0; d < 64; d++) s = fmaf(qv[d], Ks[j][d], s);
            s *= scale;
            float mn   = fmaxf(m, s);
            float corr = __expf(m - mn);
            float p    = __expf(s - mn);
            l = l * corr + p;
            #pragma unroll
            for (int d = 0; d < 64; d++)
                acc[d] = fmaf(acc[d], corr, p * Vs[j][d]);
            m = mn;
        }
        __syncthreads();
    }

    float invl = 1.f / l;
    float* op = &out[(size_t)(b * TT + q) * DD + h * HDD];
    #pragma unroll
    for (int d = 0; d < 64; d++) op[d] = acc[d] * invl;
}

// ---------------- launch ----------------
extern "C" void kernel_launch(void* const* d_in, const int* in_sizes, int n_in,
                              void* d_out, int out_size) {
    const int*   ids    = (const int*)  d_in[0];
    const float* wte    = (const float*)d_in[1];
    const float* wpe    = (const float*)d_in[2];
    const float* ln1_g  = (const float*)d_in[3];
    const float* ln1_b  = (const float*)d_in[4];
    const float* attn_w = (const float*)d_in[5];
    const float* attn_b = (const float*)d_in[6];
    const float* proj_w = (const float*)d_in[7];
    const float* proj_b = (const float*)d_in[8];
    const float* ln2_g  = (const float*)d_in[9];
    const float* ln2_b  = (const float*)d_in[10];
    const float* fc_w   = (const float*)d_in[11];
    const float* fc_b   = (const float*)d_in[12];
    const float* out_w  = (const float*)d_in[13];
    const float* out_b  = (const float*)d_in[14];
    const float* lnf_g  = (const float*)d_in[15];
    const float* lnf_b  = (const float*)d_in[16];
    float* logits = (float*)d_out;

    float *x, *h, *qkv, *att, *mlp;
    cudaGetSymbolAddress((void**)&x,   g_x);
    cudaGetSymbolAddress((void**)&h,   g_h);
    cudaGetSymbolAddress((void**)&qkv, g_qkv);
    cudaGetSymbolAddress((void**)&att, g_att);
    cudaGetSymbolAddress((void**)&mlp, g_mlp);

    embed_k<<<MTOK, 256>>>(ids, wte, wpe, x);

    for (int l = 0; l < LL; l++) {
        // attention block
        ln_k<<<MTOK, 256>>>(x, ln1_g + l * DD, ln1_b + l * DD, h);
        gemm_nn<EPI_BIAS><<<dim3(3 * DD / 64, MTOK / 64), 256>>>(
            h, attn_w + (size_t)l * DD * 3 * DD, attn_b + (size_t)l * 3 * DD,
            nullptr, qkv, MTOK, 3 * DD, DD);
        attn_k<<<dim3(TT / 64, HH, BB), 64>>>(qkv, att);
        gemm_nn<EPI_BIAS_RES><<<dim3(DD / 64, MTOK / 64), 256>>>(
            att, proj_w + (size_t)l * DD * DD, proj_b + (size_t)l * DD,
            x, x, MTOK, DD, DD);
        // mlp block
        ln_k<<<MTOK, 256>>>(x, ln2_g + l * DD, ln2_b + l * DD, h);
        gemm_nn<EPI_BIAS_GELU><<<dim3(4 * DD / 64, MTOK / 64), 256>>>(
            h, fc_w + (size_t)l * DD * 4 * DD, fc_b + (size_t)l * 4 * DD,
            nullptr, mlp, MTOK, 4 * DD, DD);
        gemm_nn<EPI_BIAS_RES><<<dim3(DD / 64, MTOK / 64), 256>>>(
            mlp, out_w + (size_t)l * 4 * DD * DD, out_b + (size_t)l * DD,
            x, x, MTOK, DD, 4 * DD);
    }

    ln_k<<<MTOK, 256>>>(x, lnf_g, lnf_b, h);
    gemm_nt<<<dim3((VV + 63) / 64, MTOK / 64), 256>>>(h, wte, logits, MTOK, VV, DD);
}

// round 9
// speedup vs baseline: 1.9754x; 1.9754x over previous
#include <cuda_runtime.h>
#include <cuda_bf16.h>
#include <cstdint>
#include <math.h>

#define BB   2
#define TT   1024
#define DD   768
#define LL   4
#define HH   12
#define HDD  64
#define VV   50257
#define MTOK (BB * TT)   // 2048 token rows

// ---------------- scratch (allocation-free: __device__ globals) ----------------
__device__ float g_x  [MTOK * DD];
__device__ float g_h  [MTOK * DD];
__device__ float g_qkv[MTOK * 3 * DD];
__device__ float g_att[MTOK * DD];
__device__ float g_mlp[MTOK * 4 * DD];

// ============================ helpers ============================
__device__ __forceinline__ uint32_t smem_u32(const void* p) {
    uint32_t a;
    asm("{ .reg .u64 t; cvta.to.shared.u64 t, %1; cvt.u32.u64 %0, t; }" : "=r"(a) : "l"(p));
    return a;
}

__device__ __forceinline__ void ldm_x4(uint32_t* r, uint32_t addr) {
    asm volatile("ldmatrix.sync.aligned.m8n8.x4.shared.b16 {%0,%1,%2,%3}, [%4];"
                 : "=r"(r[0]), "=r"(r[1]), "=r"(r[2]), "=r"(r[3]) : "r"(addr));
}
__device__ __forceinline__ void ldm_x4_t(uint32_t* r, uint32_t addr) {
    asm volatile("ldmatrix.sync.aligned.m8n8.x4.trans.shared.b16 {%0,%1,%2,%3}, [%4];"
                 : "=r"(r[0]), "=r"(r[1]), "=r"(r[2]), "=r"(r[3]) : "r"(addr));
}
__device__ __forceinline__ void mma_bf16(float* c, const uint32_t* a, const uint32_t* b) {
    asm volatile(
        "mma.sync.aligned.m16n8k16.row.col.f32.bf16.bf16.f32 "
        "{%0,%1,%2,%3}, {%4,%5,%6,%7}, {%8,%9}, {%0,%1,%2,%3};"
        : "+f"(c[0]), "+f"(c[1]), "+f"(c[2]), "+f"(c[3])
        : "r"(a[0]), "r"(a[1]), "r"(a[2]), "r"(a[3]), "r"(b[0]), "r"(b[1]));
}

// split fp32 pair into packed bf16x2 hi + packed bf16x2 lo (element order: x low half)
__device__ __forceinline__ void split_pack(float x, float y, uint32_t& hi, uint32_t& lo) {
    __nv_bfloat162 h = __floats2bfloat162_rn(x, y);
    float2 hf = __bfloat1622float2(h);
    __nv_bfloat162 l = __floats2bfloat162_rn(x - hf.x, y - hf.y);
    hi = *reinterpret_cast<uint32_t*>(&h);
    lo = *reinterpret_cast<uint32_t*>(&l);
}

__device__ __forceinline__ float gelu_exact(float v) {
    return 0.5f * v * (1.0f + erff(v * 0.70710678118654752440f));
}

// ============================ mma.sync bf16x3 GEMM ============================
// C[M,N] = A[M,K] @ B + epilogue, 3x-split bf16 for ~fp32 accuracy.
//   WKN=true : B = W[K,N] (N contiguous)
//   WKN=false: B = B[N,K] (K contiguous)  -- lm-head (wte), N bounds-checked
// CTA tile 128x128, K-step 32, 8 warps (warp tile 32x64), double-buffered SMEM.
#define EPI_NONE      0
#define EPI_BIAS      1
#define EPI_BIAS_GELU 2
#define EPI_BIAS_RES  3

#define A_STRIDE 80      // bytes per A smem row: 32 bf16 (64B) + 16B pad (odd multiple of 16)
#define B_STRIDE 272     // bytes per B smem row: 128 bf16 (256B) + 16B pad
#define A_HI_OFF 0
#define A_LO_OFF (128 * A_STRIDE)            // 10240
#define B_HI_OFF (2 * 128 * A_STRIDE)        // 20480
#define B_LO_OFF (B_HI_OFF + 32 * B_STRIDE)  // 29184
#define STAGE    (B_LO_OFF + 32 * B_STRIDE)  // 37888
#define GT_SMEM  (2 * STAGE)                 // 75776

template <int EPI, bool WKN>
__global__ __launch_bounds__(256)
void gemm_mma(const float* __restrict__ A, const float* __restrict__ B,
              const float* __restrict__ bias, const float* __restrict__ res,
              float* __restrict__ C, int N, int K) {
    extern __shared__ char sm[];
    const uint32_t sb = smem_u32(sm);

    int tid = threadIdx.x, lane = tid & 31, wid = tid >> 5;
    // lm-head: row tiles on x (fastest) so CTAs sharing a wte col-tile are adjacent -> L2 reuse
    int row0 = (WKN ? blockIdx.y : blockIdx.x) * 128;
    int col0 = (WKN ? blockIdx.x : blockIdx.y) * 128;

    int wr = wid >> 1, wc = wid & 1;        // 4x2 warp grid
    int mbase = wr * 32, nbase = wc * 64;   // warp tile 32x64

    float acc[2][8][4];
    #pragma unroll
    for (int a = 0; a < 2; a++)
        #pragma unroll
        for (int b = 0; b < 8; b++)
            #pragma unroll
            for (int c = 0; c < 4; c++) acc[a][b][c] = 0.f;

    const int nk = K >> 5;
    float4 pa[4], pb[4];

    auto ldg_tile = [&](int c) {
        int k0 = c << 5;
        #pragma unroll
        for (int g = 0; g < 4; g++) {
            int idx = g * 256 + tid;
            int m = idx >> 3, kk = (idx & 7) * 4;
            pa[g] = *(const float4*)&A[(size_t)(row0 + m) * K + k0 + kk];
        }
        if (WKN) {
            #pragma unroll
            for (int g = 0; g < 4; g++) {
                int idx = g * 256 + tid;
                int k = idx >> 5, nn = (idx & 31) * 4;
                pb[g] = *(const float4*)&B[(size_t)(k0 + k) * N + col0 + nn];
            }
        } else {
            #pragma unroll
            for (int g = 0; g < 4; g++) {
                int idx = g * 256 + tid;
                int n = idx >> 3, kk = (idx & 7) * 4;
                int gn = col0 + n;
                pb[g] = (gn < N) ? *(const float4*)&B[(size_t)gn * K + k0 + kk]
                                 : make_float4(0.f, 0.f, 0.f, 0.f);
            }
        }
    };

    auto sts_tile = [&](int buf) {
        char* st = sm + buf * STAGE;
        #pragma unroll
        for (int g = 0; g < 4; g++) {
            int idx = g * 256 + tid;
            int m = idx >> 3, kk = (idx & 7) * 4;
            uint32_t h0, l0, h1, l1;
            split_pack(pa[g].x, pa[g].y, h0, l0);
            split_pack(pa[g].z, pa[g].w, h1, l1);
            uint32_t off = (uint32_t)(m * A_STRIDE + kk * 2);
            *(uint2*)(st + A_HI_OFF + off) = make_uint2(h0, h1);
            *(uint2*)(st + A_LO_OFF + off) = make_uint2(l0, l1);
        }
        if (WKN) {
            #pragma unroll
            for (int g = 0; g < 4; g++) {
                int idx = g * 256 + tid;
                int k = idx >> 5, nn = (idx & 31) * 4;
                uint32_t h0, l0, h1, l1;
                split_pack(pb[g].x, pb[g].y, h0, l0);
                split_pack(pb[g].z, pb[g].w, h1, l1);
                uint32_t off = (uint32_t)(k * B_STRIDE + nn * 2);
                *(uint2*)(st + B_HI_OFF + off) = make_uint2(h0, h1);
                *(uint2*)(st + B_LO_OFF + off) = make_uint2(l0, l1);
            }
        } else {
            #pragma unroll
            for (int g = 0; g < 4; g++) {
                int idx = g * 256 + tid;
                int n = idx >> 3, kk = (idx & 7) * 4;
                float v[4] = {pb[g].x, pb[g].y, pb[g].z, pb[g].w};
                #pragma unroll
                for (int i = 0; i < 4; i++) {
                    __nv_bfloat16 h = __float2bfloat16(v[i]);
                    __nv_bfloat16 l = __float2bfloat16(v[i] - __bfloat162float(h));
                    uint32_t off = (uint32_t)((kk + i) * B_STRIDE + n * 2);
                    *(__nv_bfloat16*)(st + B_HI_OFF + off) = h;
                    *(__nv_bfloat16*)(st + B_LO_OFF + off) = l;
                }
            }
        }
    };

    auto compute = [&](int buf) {
        uint32_t st = sb + buf * STAGE;
        #pragma unroll
        for (int kk = 0; kk < 2; kk++) {
            uint32_t ah[2][4], al[2][4];
            #pragma unroll
            for (int mt = 0; mt < 2; mt++) {
                int r = mbase + mt * 16 + (lane & 15);
                uint32_t addr = st + A_HI_OFF + (uint32_t)(r * A_STRIDE)
                              + (uint32_t)(kk * 32 + (lane >> 4) * 16);
                ldm_x4(ah[mt], addr);
                ldm_x4(al[mt], addr + (A_LO_OFF - A_HI_OFF));
            }
            #pragma unroll
            for (int ng = 0; ng < 4; ng++) {
                uint32_t bh[4], bl[4];
                int krow = kk * 16 + (lane & 15);
                uint32_t baddr = st + B_HI_OFF + (uint32_t)(krow * B_STRIDE)
                               + (uint32_t)((nbase + ng * 16) * 2 + (lane >> 4) * 16);
                ldm_x4_t(bh, baddr);
                ldm_x4_t(bl, baddr + (B_LO_OFF - B_HI_OFF));
                #pragma unroll
                for (int mt = 0; mt < 2; mt++) {
                    #pragma unroll
                    for (int h2 = 0; h2 < 2; h2++) {
                        float* a = acc[mt][ng * 2 + h2];
                        mma_bf16(a, ah[mt], bh + 2 * h2);
                        mma_bf16(a, al[mt], bh + 2 * h2);
                        mma_bf16(a, ah[mt], bl + 2 * h2);
                    }
                }
            }
        }
    };

    ldg_tile(0);
    sts_tile(0);
    __syncthreads();
    for (int c = 0; c < nk; c++) {
        if (c + 1 < nk) ldg_tile(c + 1);
        compute(c & 1);
        if (c + 1 < nk) sts_tile((c + 1) & 1);
        __syncthreads();
    }

    // ---------------- epilogue: accumulators already in registers ----------------
    #pragma unroll
    for (int mt = 0; mt < 2; mt++) {
        #pragma unroll
        for (int nf = 0; nf < 8; nf++) {
            int col = col0 + nbase + nf * 8 + (lane & 3) * 2;
            int r   = row0 + mbase + mt * 16 + (lane >> 2);
            float v0 = acc[mt][nf][0], v1 = acc[mt][nf][1];
            float v2 = acc[mt][nf][2], v3 = acc[mt][nf][3];
            if (EPI >= 1) {
                float b0 = bias[col], b1 = bias[col + 1];
                v0 += b0; v1 += b1; v2 += b0; v3 += b1;
            }
            if (EPI == EPI_BIAS_GELU) {
                v0 = gelu_exact(v0); v1 = gelu_exact(v1);
                v2 = gelu_exact(v2); v3 = gelu_exact(v3);
            }
            if (EPI == EPI_BIAS_RES) {
                float2 ra = *(const float2*)&res[(size_t)r * N + col];
                float2 rb = *(const float2*)&res[(size_t)(r + 8) * N + col];
                v0 += ra.x; v1 += ra.y; v2 += rb.x; v3 += rb.y;
            }
            if (!WKN) {
                if (col < N) {
                    C[(size_t)r * N + col] = v0;
                    C[(size_t)(r + 8) * N + col] = v2;
                }
                if (col + 1 < N) {
                    C[(size_t)r * N + col + 1] = v1;
                    C[(size_t)(r + 8) * N + col + 1] = v3;
                }
            } else {
                *(float2*)&C[(size_t)r * N + col]       = make_float2(v0, v1);
                *(float2*)&C[(size_t)(r + 8) * N + col] = make_float2(v2, v3);
            }
        }
    }
}

// ---------------- embedding ----------------
__global__ void embed_k(const int* __restrict__ ids, const float* __restrict__ wte,
                        const float* __restrict__ wpe, float* __restrict__ x) {
    int row = blockIdx.x;
    int t   = row % TT;
    int id  = ids[row];
    const float* we = wte + (size_t)id * DD;
    const float* pe = wpe + (size_t)t * DD;
    float* xr = x + (size_t)row * DD;
    for (int d = threadIdx.x; d < DD; d += blockDim.x)
        xr[d] = we[d] + pe[d];
}

// ---------------- layernorm ----------------
__global__ __launch_bounds__(256) void ln_k(const float* __restrict__ x,
                                            const float* __restrict__ g,
                                            const float* __restrict__ b,
                                            float* __restrict__ y) {
    int row = blockIdx.x;
    const float* xr = x + (size_t)row * DD;
    float s = 0.f, ss = 0.f;
    for (int d = threadIdx.x; d < DD; d += 256) {
        float v = xr[d];
        s += v; ss += v * v;
    }
    __shared__ float rs[8], rss[8];
    #pragma unroll
    for (int o = 16; o; o >>= 1) {
        s  += __shfl_xor_sync(0xffffffffu, s,  o);
        ss += __shfl_xor_sync(0xffffffffu, ss, o);
    }
    int w = threadIdx.x >> 5;
    if ((threadIdx.x & 31) == 0) { rs[w] = s; rss[w] = ss; }
    __syncthreads();
    if (threadIdx.x < 32) {
        s  = (threadIdx.x < 8) ? rs[threadIdx.x]  : 0.f;
        ss = (threadIdx.x < 8) ? rss[threadIdx.x] : 0.f;
        #pragma unroll
        for (int o = 4; o; o >>= 1) {
            s  += __shfl_xor_sync(0xffffffffu, s,  o);
            ss += __shfl_xor_sync(0xffffffffu, ss, o);
        }
        if (threadIdx.x == 0) { rs[0] = s; rss[0] = ss; }
    }
    __syncthreads();
    float mu  = rs[0]  * (1.f / DD);
    float var = rss[0] * (1.f / DD) - mu * mu;
    float inv = rsqrtf(var + 1e-5f);
    float* yr = y + (size_t)row * DD;
    for (int d = threadIdx.x; d < DD; d += 256)
        yr[d] = g[d] * (xr[d] - mu) * inv + b[d];
}

// ---------------- causal flash attention (unchanged) ----------------
__global__ __launch_bounds__(64) void attn_k(const float* __restrict__ qkv,
                                             float* __restrict__ out) {
    int qt   = blockIdx.x;
    int h    = blockIdx.y;
    int b    = blockIdx.z;
    int lane = threadIdx.x;
    int q    = qt * 64 + lane;

    __shared__ float Ks[64][64];
    __shared__ float Vs[64][64];

    const float* qp = &qkv[(size_t)(b * TT + q) * (3 * DD) + h * HDD];
    float qv[64];
    #pragma unroll
    for (int i = 0; i < 16; i++) {
        float4 t = ((const float4*)qp)[i];
        qv[4 * i + 0] = t.x; qv[4 * i + 1] = t.y; qv[4 * i + 2] = t.z; qv[4 * i + 3] = t.w;
    }

    float acc[64];
    #pragma unroll
    for (int d = 0; d < 64; d++) acc[d] = 0.f;
    float m = -1e30f, l = 0.f;
    const float scale = 0.125f;

    for (int kt = 0; kt <= qt; kt++) {
        const float* kp = &qkv[(size_t)(b * TT + kt * 64 + lane) * (3 * DD) + DD + h * HDD];
        const float* vp = kp + DD;
        #pragma unroll
        for (int i = 0; i < 16; i++) {
            ((float4*)Ks[lane])[i] = ((const float4*)kp)[i];
            ((float4*)Vs[lane])[i] = ((const float4*)vp)[i];
        }
        __syncthreads();

        int jmax = (kt == qt) ? lane : 63;
        for (int j = 0; j <= jmax; j++) {
            float s = 0.f;
            #pragma unroll
            for (int d = 0; d < 64; d++) s = fmaf(qv[d], Ks[j][d], s);
            s *= scale;
            float mn   = fmaxf(m, s);
            float corr = __expf(m - mn);
            float p    = __expf(s - mn);
            l = l * corr + p;
            #pragma unroll
            for (int d = 0; d < 64; d++)
                acc[d] = fmaf(acc[d], corr, p * Vs[j][d]);
            m = mn;
        }
        __syncthreads();
    }

    float invl = 1.f / l;
    float* op = &out[(size_t)(b * TT + q) * DD + h * HDD];
    #pragma unroll
    for (int d = 0; d < 64; d++) op[d] = acc[d] * invl;
}

// ---------------- launch ----------------
extern "C" void kernel_launch(void* const* d_in, const int* in_sizes, int n_in,
                              void* d_out, int out_size) {
    const int*   ids    = (const int*)  d_in[0];
    const float* wte    = (const float*)d_in[1];
    const float* wpe    = (const float*)d_in[2];
    const float* ln1_g  = (const float*)d_in[3];
    const float* ln1_b  = (const float*)d_in[4];
    const float* attn_w = (const float*)d_in[5];
    const float* attn_b = (const float*)d_in[6];
    const float* proj_w = (const float*)d_in[7];
    const float* proj_b = (const float*)d_in[8];
    const float* ln2_g  = (const float*)d_in[9];
    const float* ln2_b  = (const float*)d_in[10];
    const float* fc_w   = (const float*)d_in[11];
    const float* fc_b   = (const float*)d_in[12];
    const float* out_w  = (const float*)d_in[13];
    const float* out_b  = (const float*)d_in[14];
    const float* lnf_g  = (const float*)d_in[15];
    const float* lnf_b  = (const float*)d_in[16];
    float* logits = (float*)d_out;

    float *x, *h, *qkv, *att, *mlp;
    cudaGetSymbolAddress((void**)&x,   g_x);
    cudaGetSymbolAddress((void**)&h,   g_h);
    cudaGetSymbolAddress((void**)&qkv, g_qkv);
    cudaGetSymbolAddress((void**)&att, g_att);
    cudaGetSymbolAddress((void**)&mlp, g_mlp);

    cudaFuncSetAttribute(gemm_mma<EPI_BIAS,      true >, cudaFuncAttributeMaxDynamicSharedMemorySize, GT_SMEM);
    cudaFuncSetAttribute(gemm_mma<EPI_BIAS_GELU, true >, cudaFuncAttributeMaxDynamicSharedMemorySize, GT_SMEM);
    cudaFuncSetAttribute(gemm_mma<EPI_BIAS_RES,  true >, cudaFuncAttributeMaxDynamicSharedMemorySize, GT_SMEM);
    cudaFuncSetAttribute(gemm_mma<EPI_NONE,      false>, cudaFuncAttributeMaxDynamicSharedMemorySize, GT_SMEM);

    embed_k<<<MTOK, 256>>>(ids, wte, wpe, x);

    for (int l = 0; l < LL; l++) {
        // attention block
        ln_k<<<MTOK, 256>>>(x, ln1_g + l * DD, ln1_b + l * DD, h);
        gemm_mma<EPI_BIAS, true><<<dim3(3 * DD / 128, MTOK / 128), 256, GT_SMEM>>>(
            h, attn_w + (size_t)l * DD * 3 * DD, attn_b + (size_t)l * 3 * DD,
            nullptr, qkv, 3 * DD, DD);
        attn_k<<<dim3(TT / 64, HH, BB), 64>>>(qkv, att);
        gemm_mma<EPI_BIAS_RES, true><<<dim3(DD / 128, MTOK / 128), 256, GT_SMEM>>>(
            att, proj_w + (size_t)l * DD * DD, proj_b + (size_t)l * DD,
            x, x, DD, DD);
        // mlp block
        ln_k<<<MTOK, 256>>>(x, ln2_g + l * DD, ln2_b + l * DD, h);
        gemm_mma<EPI_BIAS_GELU, true><<<dim3(4 * DD / 128, MTOK / 128), 256, GT_SMEM>>>(
            h, fc_w + (size_t)l * DD * 4 * DD, fc_b + (size_t)l * 4 * DD,
            nullptr, mlp, 4 * DD, DD);
        gemm_mma<EPI_BIAS_RES, true><<<dim3(DD / 128, MTOK / 128), 256, GT_SMEM>>>(
            mlp, out_w + (size_t)l * 4 * DD * DD, out_b + (size_t)l * DD,
            x, x, DD, 4 * DD);
    }

    ln_k<<<MTOK, 256>>>(x, lnf_g, lnf_b, h);
    // lm-head: grid.x = row tiles (16, fastest) so CTAs sharing a wte tile are adjacent
    gemm_mma<EPI_NONE, false><<<dim3(MTOK / 128, (VV + 127) / 128), 256, GT_SMEM>>>(
        h, wte, nullptr, nullptr, logits, VV, DD);
}

// round 10
// speedup vs baseline: 2.0319x; 1.0286x over previous
#include <cuda_runtime.h>
#include <cuda_bf16.h>
#include <cstdint>
#include <math.h>

#define BB   2
#define TT   1024
#define DD   768
#define LL   4
#define HH   12
#define HDD  64
#define VV   50257
#define MTOK (BB * TT)   // 2048 token rows

// ---------------- scratch (allocation-free: __device__ globals) ----------------
__device__ float g_x  [MTOK * DD];          // residual stream (fp32)
__device__ float g_qkv[MTOK * 3 * DD];      // qkv (fp32, read by attention)
// split bf16 activation planes (GEMM A operands)
__device__ __nv_bfloat16 g_hh [MTOK * DD],      g_hl [MTOK * DD];       // LN out
__device__ __nv_bfloat16 g_ath[MTOK * DD],      g_atl[MTOK * DD];       // attn out
__device__ __nv_bfloat16 g_mph[MTOK * 4 * DD],  g_mpl[MTOK * 4 * DD];   // gelu out
// split bf16 weight planes
__device__ __nv_bfloat16 g_wqh[LL * DD * 3 * DD], g_wql[LL * DD * 3 * DD];
__device__ __nv_bfloat16 g_wph[LL * DD * DD],     g_wpl[LL * DD * DD];
__device__ __nv_bfloat16 g_wfh[LL * DD * 4 * DD], g_wfl[LL * DD * 4 * DD];
__device__ __nv_bfloat16 g_woh[LL * 4 * DD * DD], g_wol[LL * 4 * DD * DD];
__device__ __nv_bfloat16 g_wth[VV * DD],          g_wtl[VV * DD];

// ============================ helpers ============================
__device__ __forceinline__ uint32_t smem_u32(const void* p) {
    uint32_t a;
    asm("{ .reg .u64 t; cvta.to.shared.u64 t, %1; cvt.u32.u64 %0, t; }" : "=r"(a) : "l"(p));
    return a;
}
__device__ __forceinline__ void ldm_x4(uint32_t* r, uint32_t addr) {
    asm volatile("ldmatrix.sync.aligned.m8n8.x4.shared.b16 {%0,%1,%2,%3}, [%4];"
                 : "=r"(r[0]), "=r"(r[1]), "=r"(r[2]), "=r"(r[3]) : "r"(addr));
}
__device__ __forceinline__ void ldm_x4_t(uint32_t* r, uint32_t addr) {
    asm volatile("ldmatrix.sync.aligned.m8n8.x4.trans.shared.b16 {%0,%1,%2,%3}, [%4];"
                 : "=r"(r[0]), "=r"(r[1]), "=r"(r[2]), "=r"(r[3]) : "r"(addr));
}
__device__ __forceinline__ void mma_bf16(float* c, const uint32_t* a, const uint32_t* b) {
    asm volatile(
        "mma.sync.aligned.m16n8k16.row.col.f32.bf16.bf16.f32 "
        "{%0,%1,%2,%3}, {%4,%5,%6,%7}, {%8,%9}, {%0,%1,%2,%3};"
        : "+f"(c[0]), "+f"(c[1]), "+f"(c[2]), "+f"(c[3])
        : "r"(a[0]), "r"(a[1]), "r"(a[2]), "r"(a[3]), "r"(b[0]), "r"(b[1]));
}
__device__ __forceinline__ void cp16(uint32_t dst, const void* src, uint32_t sz) {
    asm volatile("cp.async.cg.shared.global [%0], [%1], 16, %2;"
                 :: "r"(dst), "l"(src), "r"(sz) : "memory");
}
#define CP_COMMIT() asm volatile("cp.async.commit_group;" ::: "memory")
#define CP_WAIT(n)  asm volatile("cp.async.wait_group %0;" :: "n"(n) : "memory")

__device__ __forceinline__ float gelu_exact(float v) {
    return 0.5f * v * (1.0f + erff(v * 0.70710678118654752440f));
}
__device__ __forceinline__ void split2(float x, float y, __nv_bfloat162& h, __nv_bfloat162& l) {
    h = __floats2bfloat162_rn(x, y);
    float2 hf = __bfloat1622float2(h);
    l = __floats2bfloat162_rn(x - hf.x, y - hf.y);
}

// ---------------- weight split: fp32 -> bf16 hi/lo planes ----------------
__global__ __launch_bounds__(256) void split_w(const float* __restrict__ w,
                                               __nv_bfloat16* __restrict__ hi,
                                               __nv_bfloat16* __restrict__ lo, int n2) {
    int i = blockIdx.x * 256 + threadIdx.x;
    if (i < n2) {
        float2 v = ((const float2*)w)[i];
        __nv_bfloat162 h, l;
        split2(v.x, v.y, h, l);
        ((__nv_bfloat162*)hi)[i] = h;
        ((__nv_bfloat162*)lo)[i] = l;
    }
}

// ============================ mma.sync bf16x3 GEMM (pre-split operands) ============
// C[M,N] = A @ B + epilogue.  A: bf16 hi/lo planes [M,K] row-major.
//   WKN=true : B planes = W[K,N] (N contiguous), trans-ldmatrix
//   WKN=false: B planes = B[N,K] (K contiguous), non-trans ldmatrix (lm-head)
// CTA tile 128x128, K-step 32, 8 warps (32x64 each), cp.async double buffer.
#define EPI_NONE      0
#define EPI_BIAS      1
#define EPI_BIAS_GELU 2
#define EPI_BIAS_RES  3

template <int EPI, bool WKN, bool OSPLIT>
__global__ __launch_bounds__(256)
void gemm_bf16(const __nv_bfloat16* __restrict__ Ah, const __nv_bfloat16* __restrict__ Al,
               const __nv_bfloat16* __restrict__ Bh, const __nv_bfloat16* __restrict__ Bl,
               const float* __restrict__ bias, const float* __restrict__ res,
               float* __restrict__ C,
               __nv_bfloat16* __restrict__ Ch, __nv_bfloat16* __restrict__ Cl,
               int N, int K) {
    constexpr int AS   = 80;                    // A smem row stride (32 bf16 + pad)
    constexpr int BRS  = WKN ? 272 : 80;        // B smem row stride
    constexpr int BRN  = WKN ? 32  : 128;       // B smem rows
    constexpr int AHo  = 0;
    constexpr int ALo  = 128 * AS;              // 10240
    constexpr int BHo  = 2 * 128 * AS;          // 20480
    constexpr int BLo  = BHo + BRN * BRS;
    constexpr int STG  = BLo + BRN * BRS;

    extern __shared__ char sm[];
    const uint32_t sb = smem_u32(sm);

    int tid = threadIdx.x, lane = tid & 31, wid = tid >> 5;
    int row0 = (WKN ? blockIdx.y : blockIdx.x) * 128;
    int col0 = (WKN ? blockIdx.x : blockIdx.y) * 128;
    int wr = wid >> 1, wc = wid & 1;
    int mbase = wr * 32, nbase = wc * 64;

    float acc[2][8][4];
    #pragma unroll
    for (int a = 0; a < 2; a++)
        #pragma unroll
        for (int b = 0; b < 8; b++)
            #pragma unroll
            for (int c = 0; c < 4; c++) acc[a][b][c] = 0.f;

    const int nk = K >> 5;

    auto issue = [&](int c) {
        uint32_t st = sb + (uint32_t)(c & 1) * STG;
        int k0 = c << 5;
        // A planes: 128 rows x 64B, 512 16B-chunks per plane
        #pragma unroll
        for (int g = 0; g < 2; g++) {
            int ch  = g * 256 + tid;
            int r   = ch >> 2, off = ch & 3;
            size_t  so = (size_t)(row0 + r) * K + k0 + off * 8;
            uint32_t d = st + AHo + (uint32_t)(r * AS + off * 16);
            cp16(d,                 Ah + so, 16);
            cp16(d + (ALo - AHo),   Al + so, 16);
        }
        if (WKN) {
            // B: 32 k-rows x 256B
            #pragma unroll
            for (int g = 0; g < 2; g++) {
                int ch = g * 256 + tid;
                int kr = ch >> 4, off = ch & 15;
                size_t  so = (size_t)(k0 + kr) * N + col0 + off * 8;
                uint32_t d = st + BHo + (uint32_t)(kr * BRS + off * 16);
                cp16(d,               Bh + so, 16);
                cp16(d + (BLo - BHo), Bl + so, 16);
            }
        } else {
            // B: 128 n-rows x 64B (K-contig), bounds on n
            #pragma unroll
            for (int g = 0; g < 2; g++) {
                int ch = g * 256 + tid;
                int r  = ch >> 2, off = ch & 3;
                int gn = col0 + r;
                uint32_t sz = (gn < N) ? 16u : 0u;
                int gcl = (gn < N) ? gn : (N - 1);
                size_t  so = (size_t)gcl * K + k0 + off * 8;
                uint32_t d = st + BHo + (uint32_t)(r * BRS + off * 16);
                cp16(d,               Bh + so, sz);
                cp16(d + (BLo - BHo), Bl + so, sz);
            }
        }
        CP_COMMIT();
    };

    auto compute = [&](int buf) {
        uint32_t st = sb + (uint32_t)buf * STG;
        #pragma unroll
        for (int kk = 0; kk < 2; kk++) {
            uint32_t ah[2][4], al[2][4];
            #pragma unroll
            for (int mt = 0; mt < 2; mt++) {
                int r = mbase + mt * 16 + (lane & 15);
                uint32_t a = st + AHo + (uint32_t)(r * AS + kk * 32 + (lane >> 4) * 16);
                ldm_x4(ah[mt], a);
                ldm_x4(al[mt], a + (ALo - AHo));
            }
            #pragma unroll
            for (int ng = 0; ng < 4; ng++) {
                uint32_t bh[4], bl[4];
                uint32_t bsh[2][2], bsl[2][2];
                if (WKN) {
                    int krow = kk * 16 + (lane & 15);
                    uint32_t ba = st + BHo + (uint32_t)(krow * BRS
                                + (nbase + ng * 16) * 2 + (lane >> 4) * 16);
                    ldm_x4_t(bh, ba);
                    ldm_x4_t(bl, ba + (BLo - BHo));
                    bsh[0][0] = bh[0]; bsh[0][1] = bh[1]; bsh[1][0] = bh[2]; bsh[1][1] = bh[3];
                    bsl[0][0] = bl[0]; bsl[0][1] = bl[1]; bsl[1][0] = bl[2]; bsl[1][1] = bl[3];
                } else {
                    int nrow = nbase + ng * 16 + (lane & 15);
                    uint32_t ba = st + BHo + (uint32_t)(nrow * BRS + kk * 32 + (lane >> 4) * 16);
                    ldm_x4(bh, ba);
                    ldm_x4(bl, ba + (BLo - BHo));
                    bsh[0][0] = bh[0]; bsh[0][1] = bh[2]; bsh[1][0] = bh[1]; bsh[1][1] = bh[3];
                    bsl[0][0] = bl[0]; bsl[0][1] = bl[2]; bsl[1][0] = bl[1]; bsl[1][1] = bl[3];
                }
                #pragma unroll
                for (int mt = 0; mt < 2; mt++) {
                    #pragma unroll
                    for (int h2 = 0; h2 < 2; h2++) {
                        float* a = acc[mt][ng * 2 + h2];
                        mma_bf16(a, ah[mt], bsh[h2]);
                        mma_bf16(a, al[mt], bsh[h2]);
                        mma_bf16(a, ah[mt], bsl[h2]);
                    }
                }
            }
        }
    };

    issue(0);
    for (int c = 0; c < nk; c++) {
        if (c + 1 < nk) { issue(c + 1); CP_WAIT(1); }
        else            { CP_WAIT(0); }
        __syncthreads();
        compute(c & 1);
        __syncthreads();
    }

    // ---------------- epilogue (register accumulators) ----------------
    #pragma unroll
    for (int mt = 0; mt < 2; mt++) {
        #pragma unroll
        for (int nf = 0; nf < 8; nf++) {
            int col = col0 + nbase + nf * 8 + (lane & 3) * 2;
            int r   = row0 + mbase + mt * 16 + (lane >> 2);
            float v0 = acc[mt][nf][0], v1 = acc[mt][nf][1];
            float v2 = acc[mt][nf][2], v3 = acc[mt][nf][3];
            if (EPI >= 1) {
                float b0 = bias[col], b1 = bias[col + 1];
                v0 += b0; v1 += b1; v2 += b0; v3 += b1;
            }
            if (EPI == EPI_BIAS_GELU) {
                v0 = gelu_exact(v0); v1 = gelu_exact(v1);
                v2 = gelu_exact(v2); v3 = gelu_exact(v3);
            }
            if (EPI == EPI_BIAS_RES) {
                float2 ra = *(const float2*)&res[(size_t)r * N + col];
                float2 rb = *(const float2*)&res[(size_t)(r + 8) * N + col];
                v0 += ra.x; v1 += ra.y; v2 += rb.x; v3 += rb.y;
            }
            if (OSPLIT) {
                __nv_bfloat162 h, l;
                split2(v0, v1, h, l);
                *(__nv_bfloat162*)&Ch[(size_t)r * N + col] = h;
                *(__nv_bfloat162*)&Cl[(size_t)r * N + col] = l;
                split2(v2, v3, h, l);
                *(__nv_bfloat162*)&Ch[(size_t)(r + 8) * N + col] = h;
                *(__nv_bfloat162*)&Cl[(size_t)(r + 8) * N + col] = l;
            } else if (!WKN) {
                if (col < N) {
                    C[(size_t)r * N + col] = v0;
                    C[(size_t)(r + 8) * N + col] = v2;
                }
                if (col + 1 < N) {
                    C[(size_t)r * N + col + 1] = v1;
                    C[(size_t)(r + 8) * N + col + 1] = v3;
                }
            } else {
                *(float2*)&C[(size_t)r * N + col]       = make_float2(v0, v1);
                *(float2*)&C[(size_t)(r + 8) * N + col] = make_float2(v2, v3);
            }
        }
    }
}

#define GSM_WKN 75776
#define GSM_NT  81920

// ---------------- embedding ----------------
__global__ void embed_k(const int* __restrict__ ids, const float* __restrict__ wte,
                        const float* __restrict__ wpe, float* __restrict__ x) {
    int row = blockIdx.x;
    int t   = row % TT;
    int id  = ids[row];
    const float* we = wte + (size_t)id * DD;
    const float* pe = wpe + (size_t)t * DD;
    float* xr = x + (size_t)row * DD;
    for (int d = threadIdx.x; d < DD; d += blockDim.x)
        xr[d] = we[d] + pe[d];
}

// ---------------- layernorm -> split bf16 planes ----------------
__global__ __launch_bounds__(256) void ln_k(const float* __restrict__ x,
                                            const float* __restrict__ g,
                                            const float* __restrict__ b,
                                            __nv_bfloat16* __restrict__ yh,
                                            __nv_bfloat16* __restrict__ yl) {
    int row = blockIdx.x;
    const float* xr = x + (size_t)row * DD;
    float s = 0.f, ss = 0.f;
    for (int d = threadIdx.x; d < DD; d += 256) {
        float v = xr[d];
        s += v; ss += v * v;
    }
    __shared__ float rs[8], rss[8];
    #pragma unroll
    for (int o = 16; o; o >>= 1) {
        s  += __shfl_xor_sync(0xffffffffu, s,  o);
        ss += __shfl_xor_sync(0xffffffffu, ss, o);
    }
    int w = threadIdx.x >> 5;
    if ((threadIdx.x & 31) == 0) { rs[w] = s; rss[w] = ss; }
    __syncthreads();
    if (threadIdx.x < 32) {
        s  = (threadIdx.x < 8) ? rs[threadIdx.x]  : 0.f;
        ss = (threadIdx.x < 8) ? rss[threadIdx.x] : 0.f;
        #pragma unroll
        for (int o = 4; o; o >>= 1) {
            s  += __shfl_xor_sync(0xffffffffu, s,  o);
            ss += __shfl_xor_sync(0xffffffffu, ss, o);
        }
        if (threadIdx.x == 0) { rs[0] = s; rss[0] = ss; }
    }
    __syncthreads();
    float mu  = rs[0]  * (1.f / DD);
    float var = rss[0] * (1.f / DD) - mu * mu;
    float inv = rsqrtf(var + 1e-5f);
    for (int d = threadIdx.x * 2; d < DD; d += 512) {
        float v0 = g[d]     * (xr[d]     - mu) * inv + b[d];
        float v1 = g[d + 1] * (xr[d + 1] - mu) * inv + b[d + 1];
        __nv_bfloat162 h, l;
        split2(v0, v1, h, l);
        *(__nv_bfloat162*)&yh[(size_t)row * DD + d] = h;
        *(__nv_bfloat162*)&yl[(size_t)row * DD + d] = l;
    }
}

// ---------------- causal flash attention (tile-wise softmax, 128 q/block) -----
// grid (T/128, H, B), 128 threads; thread = one query.
#define ATT_SMEM ((2 * 64 * 68 + 128 * 65) * 4)   // Ks,Vs [64][68] + Ps [128][65]

__global__ __launch_bounds__(128) void attn_k(const float* __restrict__ qkv,
                                              __nv_bfloat16* __restrict__ oh,
                                              __nv_bfloat16* __restrict__ ol) {
    extern __shared__ float smf[];
    float* Ks = smf;
    float* Vs = smf + 64 * 68;
    float* Ps = smf + 2 * 64 * 68;

    int bq = blockIdx.x, h = blockIdx.y, b = blockIdx.z;
    int lq = threadIdx.x;
    int q  = bq * 128 + lq;

    const float* qp = &qkv[(size_t)(b * TT + q) * (3 * DD) + h * HDD];
    float qv[64];
    #pragma unroll
    for (int i = 0; i < 16; i++) {
        float4 t = ((const float4*)qp)[i];
        qv[4 * i] = t.x; qv[4 * i + 1] = t.y; qv[4 * i + 2] = t.z; qv[4 * i + 3] = t.w;
    }

    float acc[64];
    #pragma unroll
    for (int d = 0; d < 64; d++) acc[d] = 0.f;
    float m = -1e30f, l = 0.f;

    int nkt = 2 * bq + 2;
    for (int kt = 0; kt < nkt; kt++) {
        int kb = kt * 64;
        {   // load K/V tile: thread t -> row t/2, half (t&1)
            int r = lq >> 1, off = (lq & 1) * 32;
            const float* kp = &qkv[(size_t)(b * TT + kb + r) * (3 * DD) + DD + h * HDD + off];
            const float* vp = kp + DD;
            float* kd = &Ks[r * 68 + off];
            float* vd = &Vs[r * 68 + off];
            #pragma unroll
            for (int i = 0; i < 8; i++) {
                ((float4*)kd)[i] = ((const float4*)kp)[i];
                ((float4*)vd)[i] = ((const float4*)vp)[i];
            }
        }
        __syncthreads();

        bool diag = (kt >= 2 * bq);
        float mt = -1e30f;
        for (int j = 0; j < 64; j++) {
            const float4* kr = (const float4*)&Ks[j * 68];
            float s = 0.f;
            #pragma unroll
            for (int i = 0; i < 16; i++) {
                float4 kv = kr[i];
                s = fmaf(qv[4 * i], kv.x, s);
                s = fmaf(qv[4 * i + 1], kv.y, s);
                s = fmaf(qv[4 * i + 2], kv.z, s);
                s = fmaf(qv[4 * i + 3], kv.w, s);
            }
            s *= 0.125f;
            if (diag && (kb + j > q)) s = -1e30f;
            Ps[lq * 65 + j] = s;
            mt = fmaxf(mt, s);
        }
        float mn = fmaxf(m, mt);
        float corr = __expf(m - mn);
        l *= corr;
        #pragma unroll
        for (int d = 0; d < 64; d++) acc[d] *= corr;
        for (int j = 0; j < 64; j++) {
            float p = __expf(Ps[lq * 65 + j] - mn);
            l += p;
            const float4* vr = (const float4*)&Vs[j * 68];
            #pragma unroll
            for (int i = 0; i < 16; i++) {
                float4 vv = vr[i];
                acc[4 * i]     = fmaf(p, vv.x, acc[4 * i]);
                acc[4 * i + 1] = fmaf(p, vv.y, acc[4 * i + 1]);
                acc[4 * i + 2] = fmaf(p, vv.z, acc[4 * i + 2]);
                acc[4 * i + 3] = fmaf(p, vv.w, acc[4 * i + 3]);
            }
        }
        m = mn;
        __syncthreads();
    }

    float invl = 1.f / l;
    size_t ro = (size_t)(b * TT + q) * DD + h * HDD;
    #pragma unroll
    for (int d = 0; d < 64; d += 2) {
        float v0 = acc[d] * invl, v1 = acc[d + 1] * invl;
        __nv_bfloat162 hh, ll;
        split2(v0, v1, hh, ll);
        *(__nv_bfloat162*)&oh[ro + d] = hh;
        *(__nv_bfloat162*)&ol[ro + d] = ll;
    }
}

// ---------------- final LN reuses ln_k into planes ----------------

extern "C" void kernel_launch(void* const* d_in, const int* in_sizes, int n_in,
                              void* d_out, int out_size) {
    const int*   ids    = (const int*)  d_in[0];
    const float* wte    = (const float*)d_in[1];
    const float* wpe    = (const float*)d_in[2];
    const float* ln1_g  = (const float*)d_in[3];
    const float* ln1_b  = (const float*)d_in[4];
    const float* attn_w = (const float*)d_in[5];
    const float* attn_b = (const float*)d_in[6];
    const float* proj_w = (const float*)d_in[7];
    const float* proj_b = (const float*)d_in[8];
    const float* ln2_g  = (const float*)d_in[9];
    const float* ln2_b  = (const float*)d_in[10];
    const float* fc_w   = (const float*)d_in[11];
    const float* fc_b   = (const float*)d_in[12];
    const float* out_w  = (const float*)d_in[13];
    const float* out_b  = (const float*)d_in[14];
    const float* lnf_g  = (const float*)d_in[15];
    const float* lnf_b  = (const float*)d_in[16];
    float* logits = (float*)d_out;

    float *x, *qkv;
    __nv_bfloat16 *hh, *hl, *ath, *atl, *mph, *mpl;
    __nv_bfloat16 *wqh, *wql, *wph_, *wpl_, *wfh, *wfl, *woh, *wol, *wth, *wtl;
    cudaGetSymbolAddress((void**)&x,   g_x);
    cudaGetSymbolAddress((void**)&qkv, g_qkv);
    cudaGetSymbolAddress((void**)&hh,  g_hh);  cudaGetSymbolAddress((void**)&hl,  g_hl);
    cudaGetSymbolAddress((void**)&ath, g_ath); cudaGetSymbolAddress((void**)&atl, g_atl);
    cudaGetSymbolAddress((void**)&mph, g_mph); cudaGetSymbolAddress((void**)&mpl, g_mpl);
    cudaGetSymbolAddress((void**)&wqh, g_wqh); cudaGetSymbolAddress((void**)&wql, g_wql);
    cudaGetSymbolAddress((void**)&wph_, g_wph); cudaGetSymbolAddress((void**)&wpl_, g_wpl);
    cudaGetSymbolAddress((void**)&wfh, g_wfh); cudaGetSymbolAddress((void**)&wfl, g_wfl);
    cudaGetSymbolAddress((void**)&woh, g_woh); cudaGetSymbolAddress((void**)&wol, g_wol);
    cudaGetSymbolAddress((void**)&wth, g_wth); cudaGetSymbolAddress((void**)&wtl, g_wtl);

    cudaFuncSetAttribute(gemm_bf16<EPI_BIAS,      true,  false>, cudaFuncAttributeMaxDynamicSharedMemorySize, GSM_WKN);
    cudaFuncSetAttribute(gemm_bf16<EPI_BIAS_RES,  true,  false>, cudaFuncAttributeMaxDynamicSharedMemorySize, GSM_WKN);
    cudaFuncSetAttribute(gemm_bf16<EPI_BIAS_GELU, true,  true >, cudaFuncAttributeMaxDynamicSharedMemorySize, GSM_WKN);
    cudaFuncSetAttribute(gemm_bf16<EPI_NONE,      false, false>, cudaFuncAttributeMaxDynamicSharedMemorySize, GSM_NT);
    cudaFuncSetAttribute(attn_k, cudaFuncAttributeMaxDynamicSharedMemorySize, ATT_SMEM);

    // ---- weight pre-split (once per launch) ----
    auto splitN = [](const float* w, __nv_bfloat16* hi, __nv_bfloat16* lo, long n) {
        int n2 = (int)(n / 2);
        split_w<<<(n2 + 255) / 256, 256>>>(w, hi, lo, n2);
    };
    splitN(attn_w, wqh,  wql,  (long)LL * DD * 3 * DD);
    splitN(proj_w, wph_, wpl_, (long)LL * DD * DD);
    splitN(fc_w,   wfh,  wfl,  (long)LL * DD * 4 * DD);
    splitN(out_w,  woh,  wol,  (long)LL * 4 * DD * DD);
    splitN(wte,    wth,  wtl,  (long)VV * DD);

    embed_k<<<MTOK, 256>>>(ids, wte, wpe, x);

    for (int l = 0; l < LL; l++) {
        // attention block
        ln_k<<<MTOK, 256>>>(x, ln1_g + l * DD, ln1_b + l * DD, hh, hl);
        gemm_bf16<EPI_BIAS, true, false><<<dim3(3 * DD / 128, MTOK / 128), 256, GSM_WKN>>>(
            hh, hl, wqh + (size_t)l * DD * 3 * DD, wql + (size_t)l * DD * 3 * DD,
            attn_b + (size_t)l * 3 * DD, nullptr, qkv, nullptr, nullptr, 3 * DD, DD);
        attn_k<<<dim3(TT / 128, HH, BB), 128, ATT_SMEM>>>(qkv, ath, atl);
        gemm_bf16<EPI_BIAS_RES, true, false><<<dim3(DD / 128, MTOK / 128), 256, GSM_WKN>>>(
            ath, atl, wph_ + (size_t)l * DD * DD, wpl_ + (size_t)l * DD * DD,
            proj_b + (size_t)l * DD, x, x, nullptr, nullptr, DD, DD);
        // mlp block
        ln_k<<<MTOK, 256>>>(x, ln2_g + l * DD, ln2_b + l * DD, hh, hl);
        gemm_bf16<EPI_BIAS_GELU, true, true><<<dim3(4 * DD / 128, MTOK / 128), 256, GSM_WKN>>>(
            hh, hl, wfh + (size_t)l * DD * 4 * DD, wfl + (size_t)l * DD * 4 * DD,
            fc_b + (size_t)l * 4 * DD, nullptr, nullptr, mph, mpl, 4 * DD, DD);
        gemm_bf16<EPI_BIAS_RES, true, false><<<dim3(DD / 128, MTOK / 128), 256, GSM_WKN>>>(
            mph, mpl, woh + (size_t)l * 4 * DD * DD, wol + (size_t)l * 4 * DD * DD,
            out_b + (size_t)l * DD, x, x, nullptr, nullptr, DD, 4 * DD);
    }

    ln_k<<<MTOK, 256>>>(x, lnf_g, lnf_b, hh, hl);
    // lm-head: row tiles fastest so CTAs sharing a wte col-tile are L2-adjacent
    gemm_bf16<EPI_NONE, false, false><<<dim3(MTOK / 128, (VV + 127) / 128), 256, GSM_NT>>>(
        hh, hl, wth, wtl, nullptr, nullptr, logits, nullptr, nullptr, VV, DD);
}

// round 12
// speedup vs baseline: 2.5665x; 1.2631x over previous
#include <cuda_runtime.h>
#include <cuda_fp16.h>
#include <cstdint>
#include <math.h>

#define BB   2
#define TT   1024
#define DD   768
#define LL   4
#define HH   12
#define HDD  64
#define VV   50257
#define MTOK (BB * TT)   // 2048 token rows

// ---------------- scratch (allocation-free: __device__ globals) ----------------
__device__ float g_x  [MTOK * DD];          // residual stream (fp32)
__device__ float g_qkv[MTOK * 3 * DD];      // qkv (fp32, read by attention)
// split fp16 activation planes (GEMM A operands)
__device__ __half g_hh [MTOK * DD],      g_hl [MTOK * DD];       // LN out
__device__ __half g_ath[MTOK * DD],      g_atl[MTOK * DD];       // attn out
__device__ __half g_mph[MTOK * 4 * DD],  g_mpl[MTOK * 4 * DD];   // gelu out
// single fp16 weight planes (GEMM B operands)
__device__ __half g_wq[LL * DD * 3 * DD];
__device__ __half g_wp[LL * DD * DD];
__device__ __half g_wf[LL * DD * 4 * DD];
__device__ __half g_wo[LL * 4 * DD * DD];
__device__ __half g_wt[VV * DD];

// ============================ helpers ============================
__device__ __forceinline__ uint32_t smem_u32(const void* p) {
    uint32_t a;
    asm("{ .reg .u64 t; cvta.to.shared.u64 t, %1; cvt.u32.u64 %0, t; }" : "=r"(a) : "l"(p));
    return a;
}
__device__ __forceinline__ void ldm_x4(uint32_t* r, uint32_t addr) {
    asm volatile("ldmatrix.sync.aligned.m8n8.x4.shared.b16 {%0,%1,%2,%3}, [%4];"
                 : "=r"(r[0]), "=r"(r[1]), "=r"(r[2]), "=r"(r[3]) : "r"(addr));
}
__device__ __forceinline__ void ldm_x4_t(uint32_t* r, uint32_t addr) {
    asm volatile("ldmatrix.sync.aligned.m8n8.x4.trans.shared.b16 {%0,%1,%2,%3}, [%4];"
                 : "=r"(r[0]), "=r"(r[1]), "=r"(r[2]), "=r"(r[3]) : "r"(addr));
}
__device__ __forceinline__ void mma_f16(float* c, const uint32_t* a, const uint32_t* b) {
    asm volatile(
        "mma.sync.aligned.m16n8k16.row.col.f32.f16.f16.f32 "
        "{%0,%1,%2,%3}, {%4,%5,%6,%7}, {%8,%9}, {%0,%1,%2,%3};"
        : "+f"(c[0]), "+f"(c[1]), "+f"(c[2]), "+f"(c[3])
        : "r"(a[0]), "r"(a[1]), "r"(a[2]), "r"(a[3]), "r"(b[0]), "r"(b[1]));
}
__device__ __forceinline__ void cp16(uint32_t dst, const void* src, uint32_t sz) {
    asm volatile("cp.async.cg.shared.global [%0], [%1], 16, %2;"
                 :: "r"(dst), "l"(src), "r"(sz) : "memory");
}
#define CP_COMMIT() asm volatile("cp.async.commit_group;" ::: "memory")
#define CP_WAIT(n)  asm volatile("cp.async.wait_group %0;" :: "n"(n) : "memory")

__device__ __forceinline__ float gelu_exact(float v) {
    return 0.5f * v * (1.0f + erff(v * 0.70710678118654752440f));
}
// fp32 pair -> fp16 hi + fp16 lo planes (A operand split)
__device__ __forceinline__ void split2h(float x, float y, __half2& h, __half2& l) {
    h = __floats2half2_rn(x, y);
    float2 hf = __half22float2(h);
    l = __floats2half2_rn(x - hf.x, y - hf.y);
}

// ---------------- weight convert: fp32 -> single fp16 plane ----------------
__global__ __launch_bounds__(256) void conv_w(const float* __restrict__ w,
                                              __half* __restrict__ o, int n2) {
    int i = blockIdx.x * 256 + threadIdx.x;
    if (i < n2) {
        float2 v = ((const float2*)w)[i];
        ((__half2*)o)[i] = __floats2half2_rn(v.x, v.y);
    }
}

// ============================ mma.sync fp16x2 GEMM ============================
// C = A @ B + epilogue.  A: fp16 hi/lo planes [M,K] (exact to ~2^-23).
// B: SINGLE fp16 plane (error source, ~2^-12 per element).
//   WKN=true : B = W[K,N] (N contiguous), trans-ldmatrix
//   WKN=false: B = B[N,K] (K contiguous), non-trans ldmatrix (lm-head)
// CTA tile 128x128, K-step 32, 8 warps (32x64 each), cp.async double buffer.
// 2 MMAs per fragment pair: Ah*B + Al*B.
#define EPI_NONE      0
#define EPI_BIAS      1
#define EPI_BIAS_GELU 2
#define EPI_BIAS_RES  3

template <int EPI, bool WKN, bool OSPLIT>
__global__ __launch_bounds__(256)
void gemm_f16(const __half* __restrict__ Ah, const __half* __restrict__ Al,
              const __half* __restrict__ Bh,
              const float* __restrict__ bias, const float* __restrict__ res,
              float* __restrict__ C,
              __half* __restrict__ Ch, __half* __restrict__ Cl,
              int N, int K) {
    constexpr int AS   = 80;                    // A smem row stride (32 fp16 + 16B pad)
    constexpr int BRS  = WKN ? 272 : 80;        // B smem row stride
    constexpr int BRN  = WKN ? 32  : 128;       // B smem rows
    constexpr int AHo  = 0;
    constexpr int ALo  = 128 * AS;              // 10240
    constexpr int BHo  = 2 * 128 * AS;          // 20480
    constexpr int STG  = BHo + BRN * BRS;

    extern __shared__ char sm[];
    const uint32_t sb = smem_u32(sm);

    int tid = threadIdx.x, lane = tid & 31, wid = tid >> 5;
    int row0 = (WKN ? blockIdx.y : blockIdx.x) * 128;
    int col0 = (WKN ? blockIdx.x : blockIdx.y) * 128;
    int wr = wid >> 1, wc = wid & 1;
    int mbase = wr * 32, nbase = wc * 64;

    float acc[2][8][4];
    #pragma unroll
    for (int a = 0; a < 2; a++)
        #pragma unroll
        for (int b = 0; b < 8; b++)
            #pragma unroll
            for (int c = 0; c < 4; c++) acc[a][b][c] = 0.f;

    const int nk = K >> 5;

    auto issue = [&](int c) {
        uint32_t st = sb + (uint32_t)(c & 1) * STG;
        int k0 = c << 5;
        // A planes: 128 rows x 64B each plane
        #pragma unroll
        for (int g = 0; g < 2; g++) {
            int ch  = g * 256 + tid;
            int r   = ch >> 2, off = ch & 3;
            size_t  so = (size_t)(row0 + r) * K + k0 + off * 8;
            uint32_t d = st + AHo + (uint32_t)(r * AS + off * 16);
            cp16(d,               Ah + so, 16);
            cp16(d + (ALo - AHo), Al + so, 16);
        }
        if (WKN) {
            // B: 32 k-rows x 256B, single plane
            #pragma unroll
            for (int g = 0; g < 2; g++) {
                int ch = g * 256 + tid;
                int kr = ch >> 4, off = ch & 15;
                size_t  so = (size_t)(k0 + kr) * N + col0 + off * 8;
                uint32_t d = st + BHo + (uint32_t)(kr * BRS + off * 16);
                cp16(d, Bh + so, 16);
            }
        } else {
            // B: 128 n-rows x 64B (K-contig), bounds on n, single plane
            #pragma unroll
            for (int g = 0; g < 2; g++) {
                int ch = g * 256 + tid;
                int r  = ch >> 2, off = ch & 3;
                int gn = col0 + r;
                uint32_t sz = (gn < N) ? 16u : 0u;
                int gcl = (gn < N) ? gn : (N - 1);
                size_t  so = (size_t)gcl * K + k0 + off * 8;
                uint32_t d = st + BHo + (uint32_t)(r * BRS + off * 16);
                cp16(d, Bh + so, sz);
            }
        }
        CP_COMMIT();
    };

    auto compute = [&](int buf) {
        uint32_t st = sb + (uint32_t)buf * STG;
        #pragma unroll
        for (int kk = 0; kk < 2; kk++) {
            uint32_t ah[2][4], al[2][4];
            #pragma unroll
            for (int mt = 0; mt < 2; mt++) {
                int r = mbase + mt * 16 + (lane & 15);
                uint32_t a = st + AHo + (uint32_t)(r * AS + kk * 32 + (lane >> 4) * 16);
                ldm_x4(ah[mt], a);
                ldm_x4(al[mt], a + (ALo - AHo));
            }
            #pragma unroll
            for (int ng = 0; ng < 4; ng++) {
                uint32_t bh[4];
                uint32_t bsh[2][2];
                if (WKN) {
                    int krow = kk * 16 + (lane & 15);
                    uint32_t ba = st + BHo + (uint32_t)(krow * BRS
                                + (nbase + ng * 16) * 2 + (lane >> 4) * 16);
                    ldm_x4_t(bh, ba);
                    bsh[0][0] = bh[0]; bsh[0][1] = bh[1]; bsh[1][0] = bh[2]; bsh[1][1] = bh[3];
                } else {
                    int nrow = nbase + ng * 16 + (lane & 15);
                    uint32_t ba = st + BHo + (uint32_t)(nrow * BRS + kk * 32 + (lane >> 4) * 16);
                    ldm_x4(bh, ba);
                    bsh[0][0] = bh[0]; bsh[0][1] = bh[2]; bsh[1][0] = bh[1]; bsh[1][1] = bh[3];
                }
                #pragma unroll
                for (int mt = 0; mt < 2; mt++) {
                    #pragma unroll
                    for (int h2 = 0; h2 < 2; h2++) {
                        float* a = acc[mt][ng * 2 + h2];
                        mma_f16(a, ah[mt], bsh[h2]);
                        mma_f16(a, al[mt], bsh[h2]);
                    }
                }
            }
        }
    };

    issue(0);
    for (int c = 0; c < nk; c++) {
        if (c + 1 < nk) { issue(c + 1); CP_WAIT(1); }
        else            { CP_WAIT(0); }
        __syncthreads();
        compute(c & 1);
        __syncthreads();
    }

    // ---------------- epilogue (register accumulators) ----------------
    #pragma unroll
    for (int mt = 0; mt < 2; mt++) {
        #pragma unroll
        for (int nf = 0; nf < 8; nf++) {
            int col = col0 + nbase + nf * 8 + (lane & 3) * 2;
            int r   = row0 + mbase + mt * 16 + (lane >> 2);
            float v0 = acc[mt][nf][0], v1 = acc[mt][nf][1];
            float v2 = acc[mt][nf][2], v3 = acc[mt][nf][3];
            if (EPI >= 1) {
                float b0 = bias[col], b1 = bias[col + 1];
                v0 += b0; v1 += b1; v2 += b0; v3 += b1;
            }
            if (EPI == EPI_BIAS_GELU) {
                v0 = gelu_exact(v0); v1 = gelu_exact(v1);
                v2 = gelu_exact(v2); v3 = gelu_exact(v3);
            }
            if (EPI == EPI_BIAS_RES) {
                float2 ra = *(const float2*)&res[(size_t)r * N + col];
                float2 rb = *(const float2*)&res[(size_t)(r + 8) * N + col];
                v0 += ra.x; v1 += ra.y; v2 += rb.x; v3 += rb.y;
            }
            if (OSPLIT) {
                __half2 h, l;
                split2h(v0, v1, h, l);
                *(__half2*)&Ch[(size_t)r * N + col] = h;
                *(__half2*)&Cl[(size_t)r * N + col] = l;
                split2h(v2, v3, h, l);
                *(__half2*)&Ch[(size_t)(r + 8) * N + col] = h;
                *(__half2*)&Cl[(size_t)(r + 8) * N + col] = l;
            } else if (!WKN) {
                if (col < N) {
                    C[(size_t)r * N + col] = v0;
                    C[(size_t)(r + 8) * N + col] = v2;
                }
                if (col + 1 < N) {
                    C[(size_t)r * N + col + 1] = v1;
                    C[(size_t)(r + 8) * N + col + 1] = v3;
                }
            } else {
                *(float2*)&C[(size_t)r * N + col]       = make_float2(v0, v1);
                *(float2*)&C[(size_t)(r + 8) * N + col] = make_float2(v2, v3);
            }
        }
    }
}

#define GSM_WKN (2 * (20480 + 32 * 272))    // 58368
#define GSM_NT  (2 * (20480 + 128 * 80))    // 61440

// ---------------- embedding ----------------
__global__ void embed_k(const int* __restrict__ ids, const float* __restrict__ wte,
                        const float* __restrict__ wpe, float* __restrict__ x) {
    int row = blockIdx.x;
    int t   = row % TT;
    int id  = ids[row];
    const float* we = wte + (size_t)id * DD;
    const float* pe = wpe + (size_t)t * DD;
    float* xr = x + (size_t)row * DD;
    for (int d = threadIdx.x; d < DD; d += blockDim.x)
        xr[d] = we[d] + pe[d];
}

// ---------------- layernorm -> split fp16 planes ----------------
__global__ __launch_bounds__(256) void ln_k(const float* __restrict__ x,
                                            const float* __restrict__ g,
                                            const float* __restrict__ b,
                                            __half* __restrict__ yh,
                                            __half* __restrict__ yl) {
    int row = blockIdx.x;
    const float* xr = x + (size_t)row * DD;
    float s = 0.f, ss = 0.f;
    for (int d = threadIdx.x; d < DD; d += 256) {
        float v = xr[d];
        s += v; ss += v * v;
    }
    __shared__ float rs[8], rss[8];
    #pragma unroll
    for (int o = 16; o; o >>= 1) {
        s  += __shfl_xor_sync(0xffffffffu, s,  o);
        ss += __shfl_xor_sync(0xffffffffu, ss, o);
    }
    int w = threadIdx.x >> 5;
    if ((threadIdx.x & 31) == 0) { rs[w] = s; rss[w] = ss; }
    __syncthreads();
    if (threadIdx.x < 32) {
        s  = (threadIdx.x < 8) ? rs[threadIdx.x]  : 0.f;
        ss = (threadIdx.x < 8) ? rss[threadIdx.x] : 0.f;
        #pragma unroll
        for (int o = 4; o; o >>= 1) {
            s  += __shfl_xor_sync(0xffffffffu, s,  o);
            ss += __shfl_xor_sync(0xffffffffu, ss, o);
        }
        if (threadIdx.x == 0) { rs[0] = s; rss[0] = ss; }
    }
    __syncthreads();
    float mu  = rs[0]  * (1.f / DD);
    float var = rss[0] * (1.f / DD) - mu * mu;
    float inv = rsqrtf(var + 1e-5f);
    for (int d = threadIdx.x * 2; d < DD; d += 512) {
        float v0 = g[d]     * (xr[d]     - mu) * inv + b[d];
        float v1 = g[d + 1] * (xr[d + 1] - mu) * inv + b[d + 1];
        __half2 h, l;
        split2h(v0, v1, h, l);
        *(__half2*)&yh[(size_t)row * DD + d] = h;
        *(__half2*)&yl[(size_t)row * DD + d] = l;
    }
}

// ---------------- causal flash attention (tile-wise softmax, 128 q/block) -----
#define ATT_SMEM ((2 * 64 * 68 + 128 * 65) * 4)   // Ks,Vs [64][68] + Ps [128][65]

__global__ __launch_bounds__(128) void attn_k(const float* __restrict__ qkv,
                                              __half* __restrict__ oh,
                                              __half* __restrict__ ol) {
    extern __shared__ float smf[];
    float* Ks = smf;
    float* Vs = smf + 64 * 68;
    float* Ps = smf + 2 * 64 * 68;

    int bq = blockIdx.x, h = blockIdx.y, b = blockIdx.z;
    int lq = threadIdx.x;
    int q  = bq * 128 + lq;

    const float* qp = &qkv[(size_t)(b * TT + q) * (3 * DD) + h * HDD];
    float qv[64];
    #pragma unroll
    for (int i = 0; i < 16; i++) {
        float4 t = ((const float4*)qp)[i];
        qv[4 * i] = t.x; qv[4 * i + 1] = t.y; qv[4 * i + 2] = t.z; qv[4 * i + 3] = t.w;
    }

    float acc[64];
    #pragma unroll
    for (int d = 0; d < 64; d++) acc[d] = 0.f;
    float m = -1e30f, l = 0.f;

    int nkt = 2 * bq + 2;
    for (int kt = 0; kt < nkt; kt++) {
        int kb = kt * 64;
        {   // load K/V tile: thread t -> row t/2, half (t&1)
            int r = lq >> 1, off = (lq & 1) * 32;
            const float* kp = &qkv[(size_t)(b * TT + kb + r) * (3 * DD) + DD + h * HDD + off];
            const float* vp = kp + DD;
            float* kd = &Ks[r * 68 + off];
            float* vd = &Vs[r * 68 + off];
            #pragma unroll
            for (int i = 0; i < 8; i++) {
                ((float4*)kd)[i] = ((const float4*)kp)[i];
                ((float4*)vd)[i] = ((const float4*)vp)[i];
            }
        }
        __syncthreads();

        bool diag = (kt >= 2 * bq);
        float mt = -1e30f;
        for (int j = 0; j < 64; j++) {
            const float4* kr = (const float4*)&Ks[j * 68];
            float s = 0.f;
            #pragma unroll
            for (int i = 0; i < 16; i++) {
                float4 kv = kr[i];
                s = fmaf(qv[4 * i], kv.x, s);
                s = fmaf(qv[4 * i + 1], kv.y, s);
                s = fmaf(qv[4 * i + 2], kv.z, s);
                s = fmaf(qv[4 * i + 3], kv.w, s);
            }
            s *= 0.125f;
            if (diag && (kb + j > q)) s = -1e30f;
            Ps[lq * 65 + j] = s;
            mt = fmaxf(mt, s);
        }
        float mn = fmaxf(m, mt);
        float corr = __expf(m - mn);
        l *= corr;
        #pragma unroll
        for (int d = 0; d < 64; d++) acc[d] *= corr;
        for (int j = 0; j < 64; j++) {
            float p = __expf(Ps[lq * 65 + j] - mn);
            l += p;
            const float4* vr = (const float4*)&Vs[j * 68];
            #pragma unroll
            for (int i = 0; i < 16; i++) {
                float4 vv = vr[i];
                acc[4 * i]     = fmaf(p, vv.x, acc[4 * i]);
                acc[4 * i + 1] = fmaf(p, vv.y, acc[4 * i + 1]);
                acc[4 * i + 2] = fmaf(p, vv.z, acc[4 * i + 2]);
                acc[4 * i + 3] = fmaf(p, vv.w, acc[4 * i + 3]);
            }
        }
        m = mn;
        __syncthreads();
    }

    float invl = 1.f / l;
    size_t ro = (size_t)(b * TT + q) * DD + h * HDD;
    #pragma unroll
    for (int d = 0; d < 64; d += 2) {
        float v0 = acc[d] * invl, v1 = acc[d + 1] * invl;
        __half2 hh, ll;
        split2h(v0, v1, hh, ll);
        *(__half2*)&oh[ro + d] = hh;
        *(__half2*)&ol[ro + d] = ll;
    }
}

extern "C" void kernel_launch(void* const* d_in, const int* in_sizes, int n_in,
                              void* d_out, int out_size) {
    const int*   ids    = (const int*)  d_in[0];
    const float* wte    = (const float*)d_in[1];
    const float* wpe    = (const float*)d_in[2];
    const float* ln1_g  = (const float*)d_in[3];
    const float* ln1_b  = (const float*)d_in[4];
    const float* attn_w = (const float*)d_in[5];
    const float* attn_b = (const float*)d_in[6];
    const float* proj_w = (const float*)d_in[7];
    const float* proj_b = (const float*)d_in[8];
    const float* ln2_g  = (const float*)d_in[9];
    const float* ln2_b  = (const float*)d_in[10];
    const float* fc_w   = (const float*)d_in[11];
    const float* fc_b   = (const float*)d_in[12];
    const float* out_w  = (const float*)d_in[13];
    const float* out_b  = (const float*)d_in[14];
    const float* lnf_g  = (const float*)d_in[15];
    const float* lnf_b  = (const float*)d_in[16];
    float* logits = (float*)d_out;

    float *x, *qkv;
    __half *hh, *hl, *ath, *atl, *mph, *mpl;
    __half *wq, *wp, *wf, *wo, *wt;
    cudaGetSymbolAddress((void**)&x,   g_x);
    cudaGetSymbolAddress((void**)&qkv, g_qkv);
    cudaGetSymbolAddress((void**)&hh,  g_hh);  cudaGetSymbolAddress((void**)&hl,  g_hl);
    cudaGetSymbolAddress((void**)&ath, g_ath); cudaGetSymbolAddress((void**)&atl, g_atl);
    cudaGetSymbolAddress((void**)&mph, g_mph); cudaGetSymbolAddress((void**)&mpl, g_mpl);
    cudaGetSymbolAddress((void**)&wq,  g_wq);
    cudaGetSymbolAddress((void**)&wp,  g_wp);
    cudaGetSymbolAddress((void**)&wf,  g_wf);
    cudaGetSymbolAddress((void**)&wo,  g_wo);
    cudaGetSymbolAddress((void**)&wt,  g_wt);

    cudaFuncSetAttribute(gemm_f16<EPI_BIAS,      true,  false>, cudaFuncAttributeMaxDynamicSharedMemorySize, GSM_WKN);
    cudaFuncSetAttribute(gemm_f16<EPI_BIAS_RES,  true,  false>, cudaFuncAttributeMaxDynamicSharedMemorySize, GSM_WKN);
    cudaFuncSetAttribute(gemm_f16<EPI_BIAS_GELU, true,  true >, cudaFuncAttributeMaxDynamicSharedMemorySize, GSM_WKN);
    cudaFuncSetAttribute(gemm_f16<EPI_NONE,      false, false>, cudaFuncAttributeMaxDynamicSharedMemorySize, GSM_NT);
    cudaFuncSetAttribute(attn_k, cudaFuncAttributeMaxDynamicSharedMemorySize, ATT_SMEM);

    // ---- weight convert (once per launch) ----
    auto convN = [](const float* w, __half* o, long n) {
        int n2 = (int)(n / 2);
        conv_w<<<(n2 + 255) / 256, 256>>>(w, o, n2);
    };
    convN(attn_w, wq, (long)LL * DD * 3 * DD);
    convN(proj_w, wp, (long)LL * DD * DD);
    convN(fc_w,   wf, (long)LL * DD * 4 * DD);
    convN(out_w,  wo, (long)LL * 4 * DD * DD);
    convN(wte,    wt, (long)VV * DD);

    embed_k<<<MTOK, 256>>>(ids, wte, wpe, x);

    for (int l = 0; l < LL; l++) {
        // attention block
        ln_k<<<MTOK, 256>>>(x, ln1_g + l * DD, ln1_b + l * DD, hh, hl);
        gemm_f16<EPI_BIAS, true, false><<<dim3(3 * DD / 128, MTOK / 128), 256, GSM_WKN>>>(
            hh, hl, wq + (size_t)l * DD * 3 * DD,
            attn_b + (size_t)l * 3 * DD, nullptr, qkv, nullptr, nullptr, 3 * DD, DD);
        attn_k<<<dim3(TT / 128, HH, BB), 128, ATT_SMEM>>>(qkv, ath, atl);
        gemm_f16<EPI_BIAS_RES, true, false><<<dim3(DD / 128, MTOK / 128), 256, GSM_WKN>>>(
            ath, atl, wp + (size_t)l * DD * DD,
            proj_b + (size_t)l * DD, x, x, nullptr, nullptr, DD, DD);
        // mlp block
        ln_k<<<MTOK, 256>>>(x, ln2_g + l * DD, ln2_b + l * DD, hh, hl);
        gemm_f16<EPI_BIAS_GELU, true, true><<<dim3(4 * DD / 128, MTOK / 128), 256, GSM_WKN>>>(
            hh, hl, wf + (size_t)l * DD * 4 * DD,
            fc_b + (size_t)l * 4 * DD, nullptr, nullptr, mph, mpl, 4 * DD, DD);
        gemm_f16<EPI_BIAS_RES, true, false><<<dim3(DD / 128, MTOK / 128), 256, GSM_WKN>>>(
            mph, mpl, wo + (size_t)l * 4 * DD * DD,
            out_b + (size_t)l * DD, x, x, nullptr, nullptr, DD, 4 * DD);
    }

    ln_k<<<MTOK, 256>>>(x, lnf_g, lnf_b, hh, hl);
    // lm-head: row tiles fastest so CTAs sharing a wte col-tile are L2-adjacent
    gemm_f16<EPI_NONE, false, false><<<dim3(MTOK / 128, (VV + 127) / 128), 256, GSM_NT>>>(
        hh, hl, wt, nullptr, nullptr, logits, nullptr, nullptr, VV, DD);
}

// round 13
// speedup vs baseline: 2.8542x; 1.1121x over previous
#include <cuda_runtime.h>
#include <cuda_fp16.h>
#include <cstdint>
#include <math.h>

#define BB   2
#define TT   1024
#define DD   768
#define LL   4
#define HH   12
#define HDD  64
#define VV   50257
#define MTOK (BB * TT)   // 2048 token rows

// ---------------- scratch (allocation-free: __device__ globals) ----------------
__device__ float g_x  [MTOK * DD];          // residual stream (fp32)
__device__ float g_qkv[MTOK * 3 * DD];      // qkv (fp32, read by attention)
// split fp16 activation planes (GEMM A operands)
__device__ __half g_hh [MTOK * DD],      g_hl [MTOK * DD];       // LN out
__device__ __half g_ath[MTOK * DD],      g_atl[MTOK * DD];       // attn out
__device__ __half g_mph[MTOK * 4 * DD],  g_mpl[MTOK * 4 * DD];   // gelu out
// single fp16 weight planes (GEMM B operands)
__device__ __half g_wq[LL * DD * 3 * DD];
__device__ __half g_wp[LL * DD * DD];
__device__ __half g_wf[LL * DD * 4 * DD];
__device__ __half g_wo[LL * 4 * DD * DD];
__device__ __half g_wt[VV * DD];

// ============================ helpers ============================
__device__ __forceinline__ uint32_t smem_u32(const void* p) {
    uint32_t a;
    asm("{ .reg .u64 t; cvta.to.shared.u64 t, %1; cvt.u32.u64 %0, t; }" : "=r"(a) : "l"(p));
    return a;
}
__device__ __forceinline__ void ldm_x4(uint32_t* r, uint32_t addr) {
    asm volatile("ldmatrix.sync.aligned.m8n8.x4.shared.b16 {%0,%1,%2,%3}, [%4];"
                 : "=r"(r[0]), "=r"(r[1]), "=r"(r[2]), "=r"(r[3]) : "r"(addr));
}
__device__ __forceinline__ void ldm_x4_t(uint32_t* r, uint32_t addr) {
    asm volatile("ldmatrix.sync.aligned.m8n8.x4.trans.shared.b16 {%0,%1,%2,%3}, [%4];"
                 : "=r"(r[0]), "=r"(r[1]), "=r"(r[2]), "=r"(r[3]) : "r"(addr));
}
__device__ __forceinline__ void mma_f16(float* c, const uint32_t* a, const uint32_t* b) {
    asm volatile(
        "mma.sync.aligned.m16n8k16.row.col.f32.f16.f16.f32 "
        "{%0,%1,%2,%3}, {%4,%5,%6,%7}, {%8,%9}, {%0,%1,%2,%3};"
        : "+f"(c[0]), "+f"(c[1]), "+f"(c[2]), "+f"(c[3])
        : "r"(a[0]), "r"(a[1]), "r"(a[2]), "r"(a[3]), "r"(b[0]), "r"(b[1]));
}
__device__ __forceinline__ void cp16(uint32_t dst, const void* src, uint32_t sz) {
    asm volatile("cp.async.cg.shared.global [%0], [%1], 16, %2;"
                 :: "r"(dst), "l"(src), "r"(sz) : "memory");
}
#define CP_COMMIT() asm volatile("cp.async.commit_group;" ::: "memory")
#define CP_WAIT(n)  asm volatile("cp.async.wait_group %0;" :: "n"(n) : "memory")

__device__ __forceinline__ float gelu_exact(float v) {
    return 0.5f * v * (1.0f + erff(v * 0.70710678118654752440f));
}
// fp32 pair -> fp16 hi + fp16 lo planes (A operand split)
__device__ __forceinline__ void split2h(float x, float y, __half2& h, __half2& l) {
    h = __floats2half2_rn(x, y);
    float2 hf = __half22float2(h);
    l = __floats2half2_rn(x - hf.x, y - hf.y);
}

// ---------------- weight convert: fp32 -> single fp16 plane ----------------
__global__ __launch_bounds__(256) void conv_w(const float* __restrict__ w,
                                              __half* __restrict__ o, int n2) {
    int i = blockIdx.x * 256 + threadIdx.x;
    if (i < n2) {
        float2 v = ((const float2*)w)[i];
        ((__half2*)o)[i] = __floats2half2_rn(v.x, v.y);
    }
}

// ============================ mma.sync fp16 GEMM ============================
// C = A @ B + epilogue.
//   ASPLIT=true : A = fp16 hi/lo planes (2 MMAs, A exact to ~2^-23)
//   ASPLIT=false: A = fp16 hi plane only (1 MMA; lm-head — error doesn't compound)
//   WKN=true : B = W[K,N] (N contiguous), trans-ldmatrix
//   WKN=false: B = B[N,K] (K contiguous), non-trans ldmatrix (lm-head)
// CTA tile 128x128, K-step 32, 8 warps (32x64 each), cp.async double buffer.
#define EPI_NONE      0
#define EPI_BIAS      1
#define EPI_BIAS_GELU 2
#define EPI_BIAS_RES  3

template <int EPI, bool WKN, bool OSPLIT, bool ASPLIT>
__global__ __launch_bounds__(256)
void gemm_f16(const __half* __restrict__ Ah, const __half* __restrict__ Al,
              const __half* __restrict__ Bh,
              const float* __restrict__ bias, const float* __restrict__ res,
              float* __restrict__ C,
              __half* __restrict__ Ch, __half* __restrict__ Cl,
              int N, int K) {
    constexpr int AS   = 80;                    // A smem row stride (32 fp16 + 16B pad)
    constexpr int BRS  = WKN ? 272 : 80;        // B smem row stride
    constexpr int BRN  = WKN ? 32  : 128;       // B smem rows
    constexpr int AHo  = 0;
    constexpr int ALo  = 128 * AS;              // lo plane (present only if ASPLIT)
    constexpr int BHo  = ASPLIT ? (2 * 128 * AS) : (128 * AS);
    constexpr int STG  = BHo + BRN * BRS;

    extern __shared__ char sm[];
    const uint32_t sb = smem_u32(sm);

    int tid = threadIdx.x, lane = tid & 31, wid = tid >> 5;
    int row0 = (WKN ? blockIdx.y : blockIdx.x) * 128;
    int col0 = (WKN ? blockIdx.x : blockIdx.y) * 128;
    int wr = wid >> 1, wc = wid & 1;
    int mbase = wr * 32, nbase = wc * 64;

    float acc[2][8][4];
    #pragma unroll
    for (int a = 0; a < 2; a++)
        #pragma unroll
        for (int b = 0; b < 8; b++)
            #pragma unroll
            for (int c = 0; c < 4; c++) acc[a][b][c] = 0.f;

    const int nk = K >> 5;

    auto issue = [&](int c) {
        uint32_t st = sb + (uint32_t)(c & 1) * STG;
        int k0 = c << 5;
        // A planes: 128 rows x 64B each plane
        #pragma unroll
        for (int g = 0; g < 2; g++) {
            int ch  = g * 256 + tid;
            int r   = ch >> 2, off = ch & 3;
            size_t  so = (size_t)(row0 + r) * K + k0 + off * 8;
            uint32_t d = st + AHo + (uint32_t)(r * AS + off * 16);
            cp16(d, Ah + so, 16);
            if (ASPLIT) cp16(d + (ALo - AHo), Al + so, 16);
        }
        if (WKN) {
            // B: 32 k-rows x 256B, single plane
            #pragma unroll
            for (int g = 0; g < 2; g++) {
                int ch = g * 256 + tid;
                int kr = ch >> 4, off = ch & 15;
                size_t  so = (size_t)(k0 + kr) * N + col0 + off * 8;
                uint32_t d = st + BHo + (uint32_t)(kr * BRS + off * 16);
                cp16(d, Bh + so, 16);
            }
        } else {
            // B: 128 n-rows x 64B (K-contig), bounds on n, single plane
            #pragma unroll
            for (int g = 0; g < 2; g++) {
                int ch = g * 256 + tid;
                int r  = ch >> 2, off = ch & 3;
                int gn = col0 + r;
                uint32_t sz = (gn < N) ? 16u : 0u;
                int gcl = (gn < N) ? gn : (N - 1);
                size_t  so = (size_t)gcl * K + k0 + off * 8;
                uint32_t d = st + BHo + (uint32_t)(r * BRS + off * 16);
                cp16(d, Bh + so, sz);
            }
        }
        CP_COMMIT();
    };

    auto compute = [&](int buf) {
        uint32_t st = sb + (uint32_t)buf * STG;
        #pragma unroll
        for (int kk = 0; kk < 2; kk++) {
            uint32_t ah[2][4], al[2][4];
            #pragma unroll
            for (int mt = 0; mt < 2; mt++) {
                int r = mbase + mt * 16 + (lane & 15);
                uint32_t a = st + AHo + (uint32_t)(r * AS + kk * 32 + (lane >> 4) * 16);
                ldm_x4(ah[mt], a);
                if (ASPLIT) ldm_x4(al[mt], a + (ALo - AHo));
            }
            #pragma unroll
            for (int ng = 0; ng < 4; ng++) {
                uint32_t bh[4];
                uint32_t bsh[2][2];
                if (WKN) {
                    int krow = kk * 16 + (lane & 15);
                    uint32_t ba = st + BHo + (uint32_t)(krow * BRS
                                + (nbase + ng * 16) * 2 + (lane >> 4) * 16);
                    ldm_x4_t(bh, ba);
                    bsh[0][0] = bh[0]; bsh[0][1] = bh[1]; bsh[1][0] = bh[2]; bsh[1][1] = bh[3];
                } else {
                    int nrow = nbase + ng * 16 + (lane & 15);
                    uint32_t ba = st + BHo + (uint32_t)(nrow * BRS + kk * 32 + (lane >> 4) * 16);
                    ldm_x4(bh, ba);
                    bsh[0][0] = bh[0]; bsh[0][1] = bh[2]; bsh[1][0] = bh[1]; bsh[1][1] = bh[3];
                }
                #pragma unroll
                for (int mt = 0; mt < 2; mt++) {
                    #pragma unroll
                    for (int h2 = 0; h2 < 2; h2++) {
                        float* a = acc[mt][ng * 2 + h2];
                        mma_f16(a, ah[mt], bsh[h2]);
                        if (ASPLIT) mma_f16(a, al[mt], bsh[h2]);
                    }
                }
            }
        }
    };

    issue(0);
    for (int c = 0; c < nk; c++) {
        if (c + 1 < nk) { issue(c + 1); CP_WAIT(1); }
        else            { CP_WAIT(0); }
        __syncthreads();
        compute(c & 1);
        __syncthreads();
    }

    // ---------------- epilogue (register accumulators) ----------------
    #pragma unroll
    for (int mt = 0; mt < 2; mt++) {
        #pragma unroll
        for (int nf = 0; nf < 8; nf++) {
            int col = col0 + nbase + nf * 8 + (lane & 3) * 2;
            int r   = row0 + mbase + mt * 16 + (lane >> 2);
            float v0 = acc[mt][nf][0], v1 = acc[mt][nf][1];
            float v2 = acc[mt][nf][2], v3 = acc[mt][nf][3];
            if (EPI >= 1) {
                float b0 = bias[col], b1 = bias[col + 1];
                v0 += b0; v1 += b1; v2 += b0; v3 += b1;
            }
            if (EPI == EPI_BIAS_GELU) {
                v0 = gelu_exact(v0); v1 = gelu_exact(v1);
                v2 = gelu_exact(v2); v3 = gelu_exact(v3);
            }
            if (EPI == EPI_BIAS_RES) {
                float2 ra = *(const float2*)&res[(size_t)r * N + col];
                float2 rb = *(const float2*)&res[(size_t)(r + 8) * N + col];
                v0 += ra.x; v1 += ra.y; v2 += rb.x; v3 += rb.y;
            }
            if (OSPLIT) {
                __half2 h, l;
                split2h(v0, v1, h, l);
                *(__half2*)&Ch[(size_t)r * N + col] = h;
                *(__half2*)&Cl[(size_t)r * N + col] = l;
                split2h(v2, v3, h, l);
                *(__half2*)&Ch[(size_t)(r + 8) * N + col] = h;
                *(__half2*)&Cl[(size_t)(r + 8) * N + col] = l;
            } else if (!WKN) {
                if (col < N) {
                    C[(size_t)r * N + col] = v0;
                    C[(size_t)(r + 8) * N + col] = v2;
                }
                if (col + 1 < N) {
                    C[(size_t)r * N + col + 1] = v1;
                    C[(size_t)(r + 8) * N + col + 1] = v3;
                }
            } else {
                *(float2*)&C[(size_t)r * N + col]       = make_float2(v0, v1);
                *(float2*)&C[(size_t)(r + 8) * N + col] = make_float2(v2, v3);
            }
        }
    }
}

#define GSM_WKN (2 * (2 * 128 * 80 + 32 * 272))   // 58368 (ASPLIT, W[K,N])
#define GSM_NT  (2 * (128 * 80 + 128 * 80))       // 40960 (no A-lo, B[N,K])

// ---------------- embedding ----------------
__global__ void embed_k(const int* __restrict__ ids, const float* __restrict__ wte,
                        const float* __restrict__ wpe, float* __restrict__ x) {
    int row = blockIdx.x;
    int t   = row % TT;
    int id  = ids[row];
    const float* we = wte + (size_t)id * DD;
    const float* pe = wpe + (size_t)t * DD;
    float* xr = x + (size_t)row * DD;
    for (int d = threadIdx.x; d < DD; d += blockDim.x)
        xr[d] = we[d] + pe[d];
}

// ---------------- layernorm -> split fp16 planes ----------------
__global__ __launch_bounds__(256) void ln_k(const float* __restrict__ x,
                                            const float* __restrict__ g,
                                            const float* __restrict__ b,
                                            __half* __restrict__ yh,
                                            __half* __restrict__ yl) {
    int row = blockIdx.x;
    const float* xr = x + (size_t)row * DD;
    float s = 0.f, ss = 0.f;
    for (int d = threadIdx.x; d < DD; d += 256) {
        float v = xr[d];
        s += v; ss += v * v;
    }
    __shared__ float rs[8], rss[8];
    #pragma unroll
    for (int o = 16; o; o >>= 1) {
        s  += __shfl_xor_sync(0xffffffffu, s,  o);
        ss += __shfl_xor_sync(0xffffffffu, ss, o);
    }
    int w = threadIdx.x >> 5;
    if ((threadIdx.x & 31) == 0) { rs[w] = s; rss[w] = ss; }
    __syncthreads();
    if (threadIdx.x < 32) {
        s  = (threadIdx.x < 8) ? rs[threadIdx.x]  : 0.f;
        ss = (threadIdx.x < 8) ? rss[threadIdx.x] : 0.f;
        #pragma unroll
        for (int o = 4; o; o >>= 1) {
            s  += __shfl_xor_sync(0xffffffffu, s,  o);
            ss += __shfl_xor_sync(0xffffffffu, ss, o);
        }
        if (threadIdx.x == 0) { rs[0] = s; rss[0] = ss; }
    }
    __syncthreads();
    float mu  = rs[0]  * (1.f / DD);
    float var = rss[0] * (1.f / DD) - mu * mu;
    float inv = rsqrtf(var + 1e-5f);
    for (int d = threadIdx.x * 2; d < DD; d += 512) {
        float v0 = g[d]     * (xr[d]     - mu) * inv + b[d];
        float v1 = g[d + 1] * (xr[d + 1] - mu) * inv + b[d + 1];
        __half2 h, l;
        split2h(v0, v1, h, l);
        *(__half2*)&yh[(size_t)row * DD + d] = h;
        *(__half2*)&yl[(size_t)row * DD + d] = l;
    }
}

// ---------------- causal flash attention (tile-wise softmax, 128 q/block) -----
#define ATT_SMEM ((2 * 64 * 68 + 128 * 65) * 4)   // Ks,Vs [64][68] + Ps [128][65]

__global__ __launch_bounds__(128) void attn_k(const float* __restrict__ qkv,
                                              __half* __restrict__ oh,
                                              __half* __restrict__ ol) {
    extern __shared__ float smf[];
    float* Ks = smf;
    float* Vs = smf + 64 * 68;
    float* Ps = smf + 2 * 64 * 68;

    int bq = blockIdx.x, h = blockIdx.y, b = blockIdx.z;
    int lq = threadIdx.x;
    int q  = bq * 128 + lq;

    const float* qp = &qkv[(size_t)(b * TT + q) * (3 * DD) + h * HDD];
    float qv[64];
    #pragma unroll
    for (int i = 0; i < 16; i++) {
        float4 t = ((const float4*)qp)[i];
        qv[4 * i] = t.x; qv[4 * i + 1] = t.y; qv[4 * i + 2] = t.z; qv[4 * i + 3] = t.w;
    }

    float acc[64];
    #pragma unroll
    for (int d = 0; d < 64; d++) acc[d] = 0.f;
    float m = -1e30f, l = 0.f;

    int nkt = 2 * bq + 2;
    for (int kt = 0; kt < nkt; kt++) {
        int kb = kt * 64;
        {   // load K/V tile: thread t -> row t/2, half (t&1)
            int r = lq >> 1, off = (lq & 1) * 32;
            const float* kp = &qkv[(size_t)(b * TT + kb + r) * (3 * DD) + DD + h * HDD + off];
            const float* vp = kp + DD;
            float* kd = &Ks[r * 68 + off];
            float* vd = &Vs[r * 68 + off];
            #pragma unroll
            for (int i = 0; i < 8; i++) {
                ((float4*)kd)[i] = ((const float4*)kp)[i];
                ((float4*)vd)[i] = ((const float4*)vp)[i];
            }
        }
        __syncthreads();

        bool diag = (kt >= 2 * bq);
        float mt = -1e30f;
        for (int j = 0; j < 64; j++) {
            const float4* kr = (const float4*)&Ks[j * 68];
            float s = 0.f;
            #pragma unroll
            for (int i = 0; i < 16; i++) {
                float4 kv = kr[i];
                s = fmaf(qv[4 * i], kv.x, s);
                s = fmaf(qv[4 * i + 1], kv.y, s);
                s = fmaf(qv[4 * i + 2], kv.z, s);
                s = fmaf(qv[4 * i + 3], kv.w, s);
            }
            s *= 0.125f;
            if (diag && (kb + j > q)) s = -1e30f;
            Ps[lq * 65 + j] = s;
            mt = fmaxf(mt, s);
        }
        float mn = fmaxf(m, mt);
        float corr = __expf(m - mn);
        l *= corr;
        #pragma unroll
        for (int d = 0; d < 64; d++) acc[d] *= corr;
        for (int j = 0; j < 64; j++) {
            float p = __expf(Ps[lq * 65 + j] - mn);
            l += p;
            const float4* vr = (const float4*)&Vs[j * 68];
            #pragma unroll
            for (int i = 0; i < 16; i++) {
                float4 vv = vr[i];
                acc[4 * i]     = fmaf(p, vv.x, acc[4 * i]);
                acc[4 * i + 1] = fmaf(p, vv.y, acc[4 * i + 1]);
                acc[4 * i + 2] = fmaf(p, vv.z, acc[4 * i + 2]);
                acc[4 * i + 3] = fmaf(p, vv.w, acc[4 * i + 3]);
            }
        }
        m = mn;
        __syncthreads();
    }

    float invl = 1.f / l;
    size_t ro = (size_t)(b * TT + q) * DD + h * HDD;
    #pragma unroll
    for (int d = 0; d < 64; d += 2) {
        float v0 = acc[d] * invl, v1 = acc[d + 1] * invl;
        __half2 hh, ll;
        split2h(v0, v1, hh, ll);
        *(__half2*)&oh[ro + d] = hh;
        *(__half2*)&ol[ro + d] = ll;
    }
}

extern "C" void kernel_launch(void* const* d_in, const int* in_sizes, int n_in,
                              void* d_out, int out_size) {
    const int*   ids    = (const int*)  d_in[0];
    const float* wte    = (const float*)d_in[1];
    const float* wpe    = (const float*)d_in[2];
    const float* ln1_g  = (const float*)d_in[3];
    const float* ln1_b  = (const float*)d_in[4];
    const float* attn_w = (const float*)d_in[5];
    const float* attn_b = (const float*)d_in[6];
    const float* proj_w = (const float*)d_in[7];
    const float* proj_b = (const float*)d_in[8];
    const float* ln2_g  = (const float*)d_in[9];
    const float* ln2_b  = (const float*)d_in[10];
    const float* fc_w   = (const float*)d_in[11];
    const float* fc_b   = (const float*)d_in[12];
    const float* out_w  = (const float*)d_in[13];
    const float* out_b  = (const float*)d_in[14];
    const float* lnf_g  = (const float*)d_in[15];
    const float* lnf_b  = (const float*)d_in[16];
    float* logits = (float*)d_out;

    float *x, *qkv;
    __half *hh, *hl, *ath, *atl, *mph, *mpl;
    __half *wq, *wp, *wf, *wo, *wt;
    cudaGetSymbolAddress((void**)&x,   g_x);
    cudaGetSymbolAddress((void**)&qkv, g_qkv);
    cudaGetSymbolAddress((void**)&hh,  g_hh);  cudaGetSymbolAddress((void**)&hl,  g_hl);
    cudaGetSymbolAddress((void**)&ath, g_ath); cudaGetSymbolAddress((void**)&atl, g_atl);
    cudaGetSymbolAddress((void**)&mph, g_mph); cudaGetSymbolAddress((void**)&mpl, g_mpl);
    cudaGetSymbolAddress((void**)&wq,  g_wq);
    cudaGetSymbolAddress((void**)&wp,  g_wp);
    cudaGetSymbolAddress((void**)&wf,  g_wf);
    cudaGetSymbolAddress((void**)&wo,  g_wo);
    cudaGetSymbolAddress((void**)&wt,  g_wt);

    cudaFuncSetAttribute(gemm_f16<EPI_BIAS,      true,  false, true >, cudaFuncAttributeMaxDynamicSharedMemorySize, GSM_WKN);
    cudaFuncSetAttribute(gemm_f16<EPI_BIAS_RES,  true,  false, true >, cudaFuncAttributeMaxDynamicSharedMemorySize, GSM_WKN);
    cudaFuncSetAttribute(gemm_f16<EPI_BIAS_GELU, true,  true,  true >, cudaFuncAttributeMaxDynamicSharedMemorySize, GSM_WKN);
    cudaFuncSetAttribute(gemm_f16<EPI_NONE,      false, false, false>, cudaFuncAttributeMaxDynamicSharedMemorySize, GSM_NT);
    cudaFuncSetAttribute(attn_k, cudaFuncAttributeMaxDynamicSharedMemorySize, ATT_SMEM);

    // ---- weight convert (once per launch) ----
    auto convN = [](const float* w, __half* o, long n) {
        int n2 = (int)(n / 2);
        conv_w<<<(n2 + 255) / 256, 256>>>(w, o, n2);
    };
    convN(attn_w, wq, (long)LL * DD * 3 * DD);
    convN(proj_w, wp, (long)LL * DD * DD);
    convN(fc_w,   wf, (long)LL * DD * 4 * DD);
    convN(out_w,  wo, (long)LL * 4 * DD * DD);
    convN(wte,    wt, (long)VV * DD);

    embed_k<<<MTOK, 256>>>(ids, wte, wpe, x);

    for (int l = 0; l < LL; l++) {
        // attention block
        ln_k<<<MTOK, 256>>>(x, ln1_g + l * DD, ln1_b + l * DD, hh, hl);
        gemm_f16<EPI_BIAS, true, false, true><<<dim3(3 * DD / 128, MTOK / 128), 256, GSM_WKN>>>(
            hh, hl, wq + (size_t)l * DD * 3 * DD,
            attn_b + (size_t)l * 3 * DD, nullptr, qkv, nullptr, nullptr, 3 * DD, DD);
        attn_k<<<dim3(TT / 128, HH, BB), 128, ATT_SMEM>>>(qkv, ath, atl);
        gemm_f16<EPI_BIAS_RES, true, false, true><<<dim3(DD / 128, MTOK / 128), 256, GSM_WKN>>>(
            ath, atl, wp + (size_t)l * DD * DD,
            proj_b + (size_t)l * DD, x, x, nullptr, nullptr, DD, DD);
        // mlp block
        ln_k<<<MTOK, 256>>>(x, ln2_g + l * DD, ln2_b + l * DD, hh, hl);
        gemm_f16<EPI_BIAS_GELU, true, true, true><<<dim3(4 * DD / 128, MTOK / 128), 256, GSM_WKN>>>(
            hh, hl, wf + (size_t)l * DD * 4 * DD,
            fc_b + (size_t)l * 4 * DD, nullptr, nullptr, mph, mpl, 4 * DD, DD);
        gemm_f16<EPI_BIAS_RES, true, false, true><<<dim3(DD / 128, MTOK / 128), 256, GSM_WKN>>>(
            mph, mpl, wo + (size_t)l * 4 * DD * DD,
            out_b + (size_t)l * DD, x, x, nullptr, nullptr, DD, 4 * DD);
    }

    ln_k<<<MTOK, 256>>>(x, lnf_g, lnf_b, hh, hl);
    // lm-head: single-MMA (A hi only — final op, error doesn't compound);
    // row tiles fastest so CTAs sharing a wte col-tile are L2-adjacent
    gemm_f16<EPI_NONE, false, false, false><<<dim3(MTOK / 128, (VV + 127) / 128), 256, GSM_NT>>>(
        hh, hl, wt, nullptr, nullptr, logits, nullptr, nullptr, VV, DD);
}

// round 14
// speedup vs baseline: 3.1373x; 1.0992x over previous
#include <cuda_runtime.h>
#include <cuda_fp16.h>
#include <cstdint>
#include <math.h>

#define BB   2
#define TT   1024
#define DD   768
#define LL   4
#define HH   12
#define HDD  64
#define VV   50257
#define MTOK (BB * TT)   // 2048 token rows

// ---------------- scratch (allocation-free: __device__ globals) ----------------
__device__ float g_x  [MTOK * DD];          // residual stream (fp32)
__device__ float g_qkv[MTOK * 3 * DD];      // qkv (fp32, read by attention)
// split fp16 activation planes (GEMM A operands)
__device__ __half g_hh [MTOK * DD],      g_hl [MTOK * DD];       // LN out
__device__ __half g_ath[MTOK * DD],      g_atl[MTOK * DD];       // attn out
__device__ __half g_mph[MTOK * 4 * DD],  g_mpl[MTOK * 4 * DD];   // gelu out
// single fp16 weight planes (GEMM B operands)
__device__ __half g_wq[LL * DD * 3 * DD];
__device__ __half g_wp[LL * DD * DD];
__device__ __half g_wf[LL * DD * 4 * DD];
__device__ __half g_wo[LL * 4 * DD * DD];
__device__ __half g_wt[VV * DD];

// ============================ helpers ============================
__device__ __forceinline__ uint32_t smem_u32(const void* p) {
    uint32_t a;
    asm("{ .reg .u64 t; cvta.to.shared.u64 t, %1; cvt.u32.u64 %0, t; }" : "=r"(a) : "l"(p));
    return a;
}
__device__ __forceinline__ void ldm_x4(uint32_t* r, uint32_t addr) {
    asm volatile("ldmatrix.sync.aligned.m8n8.x4.shared.b16 {%0,%1,%2,%3}, [%4];"
                 : "=r"(r[0]), "=r"(r[1]), "=r"(r[2]), "=r"(r[3]) : "r"(addr));
}
__device__ __forceinline__ void ldm_x4_t(uint32_t* r, uint32_t addr) {
    asm volatile("ldmatrix.sync.aligned.m8n8.x4.trans.shared.b16 {%0,%1,%2,%3}, [%4];"
                 : "=r"(r[0]), "=r"(r[1]), "=r"(r[2]), "=r"(r[3]) : "r"(addr));
}
__device__ __forceinline__ void mma_f16(float* c, const uint32_t* a, const uint32_t* b) {
    asm volatile(
        "mma.sync.aligned.m16n8k16.row.col.f32.f16.f16.f32 "
        "{%0,%1,%2,%3}, {%4,%5,%6,%7}, {%8,%9}, {%0,%1,%2,%3};"
        : "+f"(c[0]), "+f"(c[1]), "+f"(c[2]), "+f"(c[3])
        : "r"(a[0]), "r"(a[1]), "r"(a[2]), "r"(a[3]), "r"(b[0]), "r"(b[1]));
}
__device__ __forceinline__ void cp16(uint32_t dst, const void* src, uint32_t sz) {
    asm volatile("cp.async.cg.shared.global [%0], [%1], 16, %2;"
                 :: "r"(dst), "l"(src), "r"(sz) : "memory");
}
#define CP_COMMIT() asm volatile("cp.async.commit_group;" ::: "memory")
#define CP_WAIT(n)  asm volatile("cp.async.wait_group %0;" :: "n"(n) : "memory")

__device__ __forceinline__ float gelu_exact(float v) {
    return 0.5f * v * (1.0f + erff(v * 0.70710678118654752440f));
}
// fp32 pair -> fp16 hi + fp16 lo planes (A operand split)
__device__ __forceinline__ void split2h(float x, float y, __half2& h, __half2& l) {
    h = __floats2half2_rn(x, y);
    float2 hf = __half22float2(h);
    l = __floats2half2_rn(x - hf.x, y - hf.y);
}
__device__ __forceinline__ uint32_t pack_h2(float x, float y) {
    __half2 h = __floats2half2_rn(x, y);
    return *reinterpret_cast<uint32_t*>(&h);
}

// ---------------- weight convert: fp32 -> single fp16 plane ----------------
__global__ __launch_bounds__(256) void conv_w(const float* __restrict__ w,
                                              __half* __restrict__ o, int n2) {
    int i = blockIdx.x * 256 + threadIdx.x;
    if (i < n2) {
        float2 v = ((const float2*)w)[i];
        ((__half2*)o)[i] = __floats2half2_rn(v.x, v.y);
    }
}

// ============================ mma.sync fp16 GEMM ============================
#define EPI_NONE      0
#define EPI_BIAS      1
#define EPI_BIAS_GELU 2
#define EPI_BIAS_RES  3

template <int EPI, bool WKN, bool OSPLIT, bool ASPLIT>
__global__ __launch_bounds__(256)
void gemm_f16(const __half* __restrict__ Ah, const __half* __restrict__ Al,
              const __half* __restrict__ Bh,
              const float* __restrict__ bias, const float* __restrict__ res,
              float* __restrict__ C,
              __half* __restrict__ Ch, __half* __restrict__ Cl,
              int N, int K) {
    constexpr int AS   = 80;
    constexpr int BRS  = WKN ? 272 : 80;
    constexpr int BRN  = WKN ? 32  : 128;
    constexpr int AHo  = 0;
    constexpr int ALo  = 128 * AS;
    constexpr int BHo  = ASPLIT ? (2 * 128 * AS) : (128 * AS);
    constexpr int STG  = BHo + BRN * BRS;

    extern __shared__ char sm[];
    const uint32_t sb = smem_u32(sm);

    int tid = threadIdx.x, lane = tid & 31, wid = tid >> 5;
    int row0 = (WKN ? blockIdx.y : blockIdx.x) * 128;
    int col0 = (WKN ? blockIdx.x : blockIdx.y) * 128;
    int wr = wid >> 1, wc = wid & 1;
    int mbase = wr * 32, nbase = wc * 64;

    float acc[2][8][4];
    #pragma unroll
    for (int a = 0; a < 2; a++)
        #pragma unroll
        for (int b = 0; b < 8; b++)
            #pragma unroll
            for (int c = 0; c < 4; c++) acc[a][b][c] = 0.f;

    const int nk = K >> 5;

    auto issue = [&](int c) {
        uint32_t st = sb + (uint32_t)(c & 1) * STG;
        int k0 = c << 5;
        #pragma unroll
        for (int g = 0; g < 2; g++) {
            int ch  = g * 256 + tid;
            int r   = ch >> 2, off = ch & 3;
            size_t  so = (size_t)(row0 + r) * K + k0 + off * 8;
            uint32_t d = st + AHo + (uint32_t)(r * AS + off * 16);
            cp16(d, Ah + so, 16);
            if (ASPLIT) cp16(d + (ALo - AHo), Al + so, 16);
        }
        if (WKN) {
            #pragma unroll
            for (int g = 0; g < 2; g++) {
                int ch = g * 256 + tid;
                int kr = ch >> 4, off = ch & 15;
                size_t  so = (size_t)(k0 + kr) * N + col0 + off * 8;
                uint32_t d = st + BHo + (uint32_t)(kr * BRS + off * 16);
                cp16(d, Bh + so, 16);
            }
        } else {
            #pragma unroll
            for (int g = 0; g < 2; g++) {
                int ch = g * 256 + tid;
                int r  = ch >> 2, off = ch & 3;
                int gn = col0 + r;
                uint32_t sz = (gn < N) ? 16u : 0u;
                int gcl = (gn < N) ? gn : (N - 1);
                size_t  so = (size_t)gcl * K + k0 + off * 8;
                uint32_t d = st + BHo + (uint32_t)(r * BRS + off * 16);
                cp16(d, Bh + so, sz);
            }
        }
        CP_COMMIT();
    };

    auto compute = [&](int buf) {
        uint32_t st = sb + (uint32_t)buf * STG;
        #pragma unroll
        for (int kk = 0; kk < 2; kk++) {
            uint32_t ah[2][4], al[2][4];
            #pragma unroll
            for (int mt = 0; mt < 2; mt++) {
                int r = mbase + mt * 16 + (lane & 15);
                uint32_t a = st + AHo + (uint32_t)(r * AS + kk * 32 + (lane >> 4) * 16);
                ldm_x4(ah[mt], a);
                if (ASPLIT) ldm_x4(al[mt], a + (ALo - AHo));
            }
            #pragma unroll
            for (int ng = 0; ng < 4; ng++) {
                uint32_t bh[4];
                uint32_t bsh[2][2];
                if (WKN) {
                    int krow = kk * 16 + (lane & 15);
                    uint32_t ba = st + BHo + (uint32_t)(krow * BRS
                                + (nbase + ng * 16) * 2 + (lane >> 4) * 16);
                    ldm_x4_t(bh, ba);
                    bsh[0][0] = bh[0]; bsh[0][1] = bh[1]; bsh[1][0] = bh[2]; bsh[1][1] = bh[3];
                } else {
                    int nrow = nbase + ng * 16 + (lane & 15);
                    uint32_t ba = st + BHo + (uint32_t)(nrow * BRS + kk * 32 + (lane >> 4) * 16);
                    ldm_x4(bh, ba);
                    bsh[0][0] = bh[0]; bsh[0][1] = bh[2]; bsh[1][0] = bh[1]; bsh[1][1] = bh[3];
                }
                #pragma unroll
                for (int mt = 0; mt < 2; mt++) {
                    #pragma unroll
                    for (int h2 = 0; h2 < 2; h2++) {
                        float* a = acc[mt][ng * 2 + h2];
                        mma_f16(a, ah[mt], bsh[h2]);
                        if (ASPLIT) mma_f16(a, al[mt], bsh[h2]);
                    }
                }
            }
        }
    };

    issue(0);
    for (int c = 0; c < nk; c++) {
        if (c + 1 < nk) { issue(c + 1); CP_WAIT(1); }
        else            { CP_WAIT(0); }
        __syncthreads();
        compute(c & 1);
        __syncthreads();
    }

    #pragma unroll
    for (int mt = 0; mt < 2; mt++) {
        #pragma unroll
        for (int nf = 0; nf < 8; nf++) {
            int col = col0 + nbase + nf * 8 + (lane & 3) * 2;
            int r   = row0 + mbase + mt * 16 + (lane >> 2);
            float v0 = acc[mt][nf][0], v1 = acc[mt][nf][1];
            float v2 = acc[mt][nf][2], v3 = acc[mt][nf][3];
            if (EPI >= 1) {
                float b0 = bias[col], b1 = bias[col + 1];
                v0 += b0; v1 += b1; v2 += b0; v3 += b1;
            }
            if (EPI == EPI_BIAS_GELU) {
                v0 = gelu_exact(v0); v1 = gelu_exact(v1);
                v2 = gelu_exact(v2); v3 = gelu_exact(v3);
            }
            if (EPI == EPI_BIAS_RES) {
                float2 ra = *(const float2*)&res[(size_t)r * N + col];
                float2 rb = *(const float2*)&res[(size_t)(r + 8) * N + col];
                v0 += ra.x; v1 += ra.y; v2 += rb.x; v3 += rb.y;
            }
            if (OSPLIT) {
                __half2 h, l;
                split2h(v0, v1, h, l);
                *(__half2*)&Ch[(size_t)r * N + col] = h;
                *(__half2*)&Cl[(size_t)r * N + col] = l;
                split2h(v2, v3, h, l);
                *(__half2*)&Ch[(size_t)(r + 8) * N + col] = h;
                *(__half2*)&Cl[(size_t)(r + 8) * N + col] = l;
            } else if (!WKN) {
                if (col < N) {
                    C[(size_t)r * N + col] = v0;
                    C[(size_t)(r + 8) * N + col] = v2;
                }
                if (col + 1 < N) {
                    C[(size_t)r * N + col + 1] = v1;
                    C[(size_t)(r + 8) * N + col + 1] = v3;
                }
            } else {
                *(float2*)&C[(size_t)r * N + col]       = make_float2(v0, v1);
                *(float2*)&C[(size_t)(r + 8) * N + col] = make_float2(v2, v3);
            }
        }
    }
}

#define GSM_WKN (2 * (2 * 128 * 80 + 32 * 272))   // 58368 (ASPLIT, W[K,N])
#define GSM_NT  (2 * (128 * 80 + 128 * 80))       // 40960 (no A-lo, B[N,K])

// ---------------- embedding ----------------
__global__ void embed_k(const int* __restrict__ ids, const float* __restrict__ wte,
                        const float* __restrict__ wpe, float* __restrict__ x) {
    int row = blockIdx.x;
    int t   = row % TT;
    int id  = ids[row];
    const float* we = wte + (size_t)id * DD;
    const float* pe = wpe + (size_t)t * DD;
    float* xr = x + (size_t)row * DD;
    for (int d = threadIdx.x; d < DD; d += blockDim.x)
        xr[d] = we[d] + pe[d];
}

// ---------------- layernorm -> split fp16 planes ----------------
__global__ __launch_bounds__(256) void ln_k(const float* __restrict__ x,
                                            const float* __restrict__ g,
                                            const float* __restrict__ b,
                                            __half* __restrict__ yh,
                                            __half* __restrict__ yl) {
    int row = blockIdx.x;
    const float* xr = x + (size_t)row * DD;
    float s = 0.f, ss = 0.f;
    for (int d = threadIdx.x; d < DD; d += 256) {
        float v = xr[d];
        s += v; ss += v * v;
    }
    __shared__ float rs[8], rss[8];
    #pragma unroll
    for (int o = 16; o; o >>= 1) {
        s  += __shfl_xor_sync(0xffffffffu, s,  o);
        ss += __shfl_xor_sync(0xffffffffu, ss, o);
    }
    int w = threadIdx.x >> 5;
    if ((threadIdx.x & 31) == 0) { rs[w] = s; rss[w] = ss; }
    __syncthreads();
    if (threadIdx.x < 32) {
        s  = (threadIdx.x < 8) ? rs[threadIdx.x]  : 0.f;
        ss = (threadIdx.x < 8) ? rss[threadIdx.x] : 0.f;
        #pragma unroll
        for (int o = 4; o; o >>= 1) {
            s  += __shfl_xor_sync(0xffffffffu, s,  o);
            ss += __shfl_xor_sync(0xffffffffu, ss, o);
        }
        if (threadIdx.x == 0) { rs[0] = s; rss[0] = ss; }
    }
    __syncthreads();
    float mu  = rs[0]  * (1.f / DD);
    float var = rss[0] * (1.f / DD) - mu * mu;
    float inv = rsqrtf(var + 1e-5f);
    for (int d = threadIdx.x * 2; d < DD; d += 512) {
        float v0 = g[d]     * (xr[d]     - mu) * inv + b[d];
        float v1 = g[d + 1] * (xr[d + 1] - mu) * inv + b[d + 1];
        __half2 h, l;
        split2h(v0, v1, h, l);
        *(__half2*)&yh[(size_t)row * DD + d] = h;
        *(__half2*)&yl[(size_t)row * DD + d] = l;
    }
}

// ============ tensor-core causal flash attention (fp16 mma, FA2-style) ============
// CTA: 128 queries x 1 head x 1 batch; 4 warps x 32 query rows.
// Q pre-scaled by 1/8, split hi/lo fp16 (2-MMA QK). K,V single fp16.
// One 18.4KB smem buffer: Q staging (twice), then K(rows 0-63)/V(rows 64-127).
__global__ __launch_bounds__(128) void attn_k(const float* __restrict__ qkv,
                                              __half* __restrict__ oh,
                                              __half* __restrict__ ol) {
    __shared__ __align__(16) __half SB[128 * 72];   // 18432 B, row stride 144 B
    const uint32_t sb = smem_u32(SB);

    int bq = blockIdx.x, hd = blockIdx.y, b = blockIdx.z;
    int tid = threadIdx.x, lane = tid & 31, w = tid >> 5;
    int wbase = w * 32;

    uint32_t aqh[2][4][4], aql[2][4][4];
    {   // stage Q hi -> ldm, stage Q lo -> ldm (buffer reused)
        const float* qp = &qkv[(size_t)(b * TT + bq * 128 + tid) * (3 * DD) + hd * HDD];
        __half2 lo_keep[32];
        #pragma unroll
        for (int i = 0; i < 16; i++) {
            float4 v = ((const float4*)qp)[i];
            __half2 h0, l0, h1, l1;
            split2h(v.x * 0.125f, v.y * 0.125f, h0, l0);
            split2h(v.z * 0.125f, v.w * 0.125f, h1, l1);
            *(__half2*)&SB[tid * 72 + i * 4]     = h0;
            *(__half2*)&SB[tid * 72 + i * 4 + 2] = h1;
            lo_keep[2 * i] = l0; lo_keep[2 * i + 1] = l1;
        }
        __syncthreads();
        #pragma unroll
        for (int mt = 0; mt < 2; mt++)
            #pragma unroll
            for (int ks = 0; ks < 4; ks++)
                ldm_x4(aqh[mt][ks], sb + (uint32_t)((wbase + mt * 16 + (lane & 15)) * 144
                                                    + ks * 32 + (lane >> 4) * 16));
        __syncthreads();
        #pragma unroll
        for (int i = 0; i < 32; i++)
            *(__half2*)&SB[tid * 72 + i * 2] = lo_keep[i];
        __syncthreads();
        #pragma unroll
        for (int mt = 0; mt < 2; mt++)
            #pragma unroll
            for (int ks = 0; ks < 4; ks++)
                ldm_x4(aql[mt][ks], sb + (uint32_t)((wbase + mt * 16 + (lane & 15)) * 144
                                                    + ks * 32 + (lane >> 4) * 16));
        __syncthreads();
    }

    float o[2][8][4];
    #pragma unroll
    for (int a = 0; a < 2; a++)
        #pragma unroll
        for (int nt = 0; nt < 8; nt++)
            #pragma unroll
            for (int j = 0; j < 4; j++) o[a][nt][j] = 0.f;
    float m[2][2] = {{-1e30f, -1e30f}, {-1e30f, -1e30f}};
    float lsum[2][2] = {{0.f, 0.f}, {0.f, 0.f}};

    const uint32_t Vbase = sb + 64 * 144;
    int nkt = 2 * bq + 2;
    for (int kt = 0; kt < nkt; kt++) {
        int kb = kt * 64;
        {   // stage K/V tile fp16: thread t -> key t/2, d-half (t&1)*32
            int r = tid >> 1, dh = (tid & 1) * 32;
            const float* kp = &qkv[(size_t)(b * TT + kb + r) * (3 * DD) + DD + hd * HDD + dh];
            const float* vp = kp + DD;
            #pragma unroll
            for (int i = 0; i < 8; i++) {
                float4 kv = ((const float4*)kp)[i];
                float4 vv = ((const float4*)vp)[i];
                *(__half2*)&SB[r * 72 + dh + i * 4]     = __floats2half2_rn(kv.x, kv.y);
                *(__half2*)&SB[r * 72 + dh + i * 4 + 2] = __floats2half2_rn(kv.z, kv.w);
                *(__half2*)&SB[64 * 72 + r * 72 + dh + i * 4]     = __floats2half2_rn(vv.x, vv.y);
                *(__half2*)&SB[64 * 72 + r * 72 + dh + i * 4 + 2] = __floats2half2_rn(vv.z, vv.w);
            }
        }
        __syncthreads();

        // ---- S = Q K^T (fp32 acc) ----
        float c[2][8][4];
        #pragma unroll
        for (int a = 0; a < 2; a++)
            #pragma unroll
            for (int nt = 0; nt < 8; nt++)
                #pragma unroll
                for (int j = 0; j < 4; j++) c[a][nt][j] = 0.f;
        #pragma unroll
        for (int ks = 0; ks < 4; ks++) {
            #pragma unroll
            for (int ng = 0; ng < 4; ng++) {
                uint32_t bh[4], bsh[2][2];
                ldm_x4(bh, sb + (uint32_t)((ng * 16 + (lane & 15)) * 144
                                           + ks * 32 + (lane >> 4) * 16));
                bsh[0][0] = bh[0]; bsh[0][1] = bh[2]; bsh[1][0] = bh[1]; bsh[1][1] = bh[3];
                #pragma unroll
                for (int mt = 0; mt < 2; mt++) {
                    #pragma unroll
                    for (int h2 = 0; h2 < 2; h2++) {
                        mma_f16(c[mt][ng * 2 + h2], aqh[mt][ks], bsh[h2]);
                        mma_f16(c[mt][ng * 2 + h2], aql[mt][ks], bsh[h2]);
                    }
                }
            }
        }

        // ---- causal mask on diagonal tiles ----
        if (kt >= 2 * bq) {
            #pragma unroll
            for (int mt = 0; mt < 2; mt++)
                #pragma unroll
                for (int nt = 0; nt < 8; nt++)
                    #pragma unroll
                    for (int j = 0; j < 4; j++) {
                        int key = kb + nt * 8 + (lane & 3) * 2 + (j & 1);
                        int qr  = bq * 128 + wbase + mt * 16 + (lane >> 2) + ((j >> 1) << 3);
                        if (key > qr) c[mt][nt][j] = -1e30f;
                    }
        }

        // ---- online softmax (row stats via quad shfl) ----
        #pragma unroll
        for (int mt = 0; mt < 2; mt++) {
            #pragma unroll
            for (int h = 0; h < 2; h++) {
                float tm = -1e30f;
                #pragma unroll
                for (int nt = 0; nt < 8; nt++)
                    tm = fmaxf(tm, fmaxf(c[mt][nt][2 * h], c[mt][nt][2 * h + 1]));
                tm = fmaxf(tm, __shfl_xor_sync(0xffffffffu, tm, 1));
                tm = fmaxf(tm, __shfl_xor_sync(0xffffffffu, tm, 2));
                float mn = fmaxf(m[mt][h], tm);
                float corr = __expf(m[mt][h] - mn);
                m[mt][h] = mn;
                float ts = 0.f;
                #pragma unroll
                for (int nt = 0; nt < 8; nt++) {
                    float p0 = __expf(c[mt][nt][2 * h]     - mn);
                    float p1 = __expf(c[mt][nt][2 * h + 1] - mn);
                    c[mt][nt][2 * h] = p0; c[mt][nt][2 * h + 1] = p1;
                    ts += p0 + p1;
                }
                ts += __shfl_xor_sync(0xffffffffu, ts, 1);
                ts += __shfl_xor_sync(0xffffffffu, ts, 2);
                lsum[mt][h] = lsum[mt][h] * corr + ts;
                #pragma unroll
                for (int nt = 0; nt < 8; nt++) {
                    o[mt][nt][2 * h]     *= corr;
                    o[mt][nt][2 * h + 1] *= corr;
                }
            }
        }

        // ---- O += P V  (P packed from S fragments, V via trans-ldm) ----
        #pragma unroll
        for (int ks = 0; ks < 4; ks++) {
            uint32_t ap[2][4];
            #pragma unroll
            for (int mt = 0; mt < 2; mt++) {
                ap[mt][0] = pack_h2(c[mt][2 * ks][0],     c[mt][2 * ks][1]);
                ap[mt][1] = pack_h2(c[mt][2 * ks][2],     c[mt][2 * ks][3]);
                ap[mt][2] = pack_h2(c[mt][2 * ks + 1][0], c[mt][2 * ks + 1][1]);
                ap[mt][3] = pack_h2(c[mt][2 * ks + 1][2], c[mt][2 * ks + 1][3]);
            }
            #pragma unroll
            for (int ng = 0; ng < 4; ng++) {
                uint32_t bh[4], bsh[2][2];
                ldm_x4_t(bh, Vbase + (uint32_t)((ks * 16 + (lane & 15)) * 144
                                                + (ng * 16) * 2 + (lane >> 4) * 16));
                bsh[0][0] = bh[0]; bsh[0][1] = bh[1]; bsh[1][0] = bh[2]; bsh[1][1] = bh[3];
                #pragma unroll
                for (int mt = 0; mt < 2; mt++)
                    #pragma unroll
                    for (int h2 = 0; h2 < 2; h2++)
                        mma_f16(o[mt][ng * 2 + h2], ap[mt], bsh[h2]);
            }
        }
        __syncthreads();
    }

    // ---- normalize + write split fp16 planes ----
    #pragma unroll
    for (int mt = 0; mt < 2; mt++) {
        #pragma unroll
        for (int h = 0; h < 2; h++) {
            float inv = 1.f / lsum[mt][h];
            int row = bq * 128 + wbase + mt * 16 + (lane >> 2) + h * 8;
            size_t ro = (size_t)(b * TT + row) * DD + hd * HDD;
            #pragma unroll
            for (int nt = 0; nt < 8; nt++) {
                int col = nt * 8 + (lane & 3) * 2;
                __half2 hh, ll;
                split2h(o[mt][nt][2 * h] * inv, o[mt][nt][2 * h + 1] * inv, hh, ll);
                *(__half2*)&oh[ro + col] = hh;
                *(__half2*)&ol[ro + col] = ll;
            }
        }
    }
}

extern "C" void kernel_launch(void* const* d_in, const int* in_sizes, int n_in,
                              void* d_out, int out_size) {
    const int*   ids    = (const int*)  d_in[0];
    const float* wte    = (const float*)d_in[1];
    const float* wpe    = (const float*)d_in[2];
    const float* ln1_g  = (const float*)d_in[3];
    const float* ln1_b  = (const float*)d_in[4];
    const float* attn_w = (const float*)d_in[5];
    const float* attn_b = (const float*)d_in[6];
    const float* proj_w = (const float*)d_in[7];
    const float* proj_b = (const float*)d_in[8];
    const float* ln2_g  = (const float*)d_in[9];
    const float* ln2_b  = (const float*)d_in[10];
    const float* fc_w   = (const float*)d_in[11];
    const float* fc_b   = (const float*)d_in[12];
    const float* out_w  = (const float*)d_in[13];
    const float* out_b  = (const float*)d_in[14];
    const float* lnf_g  = (const float*)d_in[15];
    const float* lnf_b  = (const float*)d_in[16];
    float* logits = (float*)d_out;

    float *x, *qkv;
    __half *hh, *hl, *ath, *atl, *mph, *mpl;
    __half *wq, *wp, *wf, *wo, *wt;
    cudaGetSymbolAddress((void**)&x,   g_x);
    cudaGetSymbolAddress((void**)&qkv, g_qkv);
    cudaGetSymbolAddress((void**)&hh,  g_hh);  cudaGetSymbolAddress((void**)&hl,  g_hl);
    cudaGetSymbolAddress((void**)&ath, g_ath); cudaGetSymbolAddress((void**)&atl, g_atl);
    cudaGetSymbolAddress((void**)&mph, g_mph); cudaGetSymbolAddress((void**)&mpl, g_mpl);
    cudaGetSymbolAddress((void**)&wq,  g_wq);
    cudaGetSymbolAddress((void**)&wp,  g_wp);
    cudaGetSymbolAddress((void**)&wf,  g_wf);
    cudaGetSymbolAddress((void**)&wo,  g_wo);
    cudaGetSymbolAddress((void**)&wt,  g_wt);

    cudaFuncSetAttribute(gemm_f16<EPI_BIAS,      true,  false, true >, cudaFuncAttributeMaxDynamicSharedMemorySize, GSM_WKN);
    cudaFuncSetAttribute(gemm_f16<EPI_BIAS_RES,  true,  false, true >, cudaFuncAttributeMaxDynamicSharedMemorySize, GSM_WKN);
    cudaFuncSetAttribute(gemm_f16<EPI_BIAS_GELU, true,  true,  true >, cudaFuncAttributeMaxDynamicSharedMemorySize, GSM_WKN);
    cudaFuncSetAttribute(gemm_f16<EPI_NONE,      false, false, false>, cudaFuncAttributeMaxDynamicSharedMemorySize, GSM_NT);

    // ---- weight convert (once per launch) ----
    auto convN = [](const float* w, __half* o, long n) {
        int n2 = (int)(n / 2);
        conv_w<<<(n2 + 255) / 256, 256>>>(w, o, n2);
    };
    convN(attn_w, wq, (long)LL * DD * 3 * DD);
    convN(proj_w, wp, (long)LL * DD * DD);
    convN(fc_w,   wf, (long)LL * DD * 4 * DD);
    convN(out_w,  wo, (long)LL * 4 * DD * DD);
    convN(wte,    wt, (long)VV * DD);

    embed_k<<<MTOK, 256>>>(ids, wte, wpe, x);

    for (int l = 0; l < LL; l++) {
        // attention block
        ln_k<<<MTOK, 256>>>(x, ln1_g + l * DD, ln1_b + l * DD, hh, hl);
        gemm_f16<EPI_BIAS, true, false, true><<<dim3(3 * DD / 128, MTOK / 128), 256, GSM_WKN>>>(
            hh, hl, wq + (size_t)l * DD * 3 * DD,
            attn_b + (size_t)l * 3 * DD, nullptr, qkv, nullptr, nullptr, 3 * DD, DD);
        attn_k<<<dim3(TT / 128, HH, BB), 128>>>(qkv, ath, atl);
        gemm_f16<EPI_BIAS_RES, true, false, true><<<dim3(DD / 128, MTOK / 128), 256, GSM_WKN>>>(
            ath, atl, wp + (size_t)l * DD * DD,
            proj_b + (size_t)l * DD, x, x, nullptr, nullptr, DD, DD);
        // mlp block
        ln_k<<<MTOK, 256>>>(x, ln2_g + l * DD, ln2_b + l * DD, hh, hl);
        gemm_f16<EPI_BIAS_GELU, true, true, true><<<dim3(4 * DD / 128, MTOK / 128), 256, GSM_WKN>>>(
            hh, hl, wf + (size_t)l * DD * 4 * DD,
            fc_b + (size_t)l * 4 * DD, nullptr, nullptr, mph, mpl, 4 * DD, DD);
        gemm_f16<EPI_BIAS_RES, true, false, true><<<dim3(DD / 128, MTOK / 128), 256, GSM_WKN>>>(
            mph, mpl, wo + (size_t)l * 4 * DD * DD,
            out_b + (size_t)l * DD, x, x, nullptr, nullptr, DD, 4 * DD);
    }

    ln_k<<<MTOK, 256>>>(x, lnf_g, lnf_b, hh, hl);
    // lm-head: single-MMA (A hi only — final op, error doesn't compound);
    // row tiles fastest so CTAs sharing a wte col-tile are L2-adjacent
    gemm_f16<EPI_NONE, false, false, false><<<dim3(MTOK / 128, (VV + 127) / 128), 256, GSM_NT>>>(
        hh, hl, wt, nullptr, nullptr, logits, nullptr, nullptr, VV, DD);
}

// round 15
// speedup vs baseline: 4.7479x; 1.5134x over previous
#include <cuda_runtime.h>
#include <cuda_fp16.h>
#include <cstdint>
#include <math.h>

#define BB   2
#define TT   1024
#define DD   768
#define LL   4
#define HH   12
#define HDD  64
#define VV   50257
#define MTOK (BB * TT)   // 2048 token rows

// ---------------- scratch (allocation-free: __device__ globals) ----------------
__device__ float g_x  [MTOK * DD];          // residual stream (fp32)
__device__ float g_qkv[MTOK * 3 * DD];      // qkv (fp32, read by attention)
// split fp16 activation planes (GEMM A operands)
__device__ __half g_hh [MTOK * DD],      g_hl [MTOK * DD];       // LN out
__device__ __half g_ath[MTOK * DD],      g_atl[MTOK * DD];       // attn out
__device__ __half g_mph[MTOK * 4 * DD],  g_mpl[MTOK * 4 * DD];   // gelu out
// single fp16 weight planes (GEMM B operands)
__device__ __half g_wq[LL * DD * 3 * DD];
__device__ __half g_wp[LL * DD * DD];
__device__ __half g_wf[LL * DD * 4 * DD];
__device__ __half g_wo[LL * 4 * DD * DD];
__device__ __half g_wt[VV * DD];

// ============================ helpers ============================
__device__ __forceinline__ uint32_t smem_u32(const void* p) {
    uint32_t a;
    asm("{ .reg .u64 t; cvta.to.shared.u64 t, %1; cvt.u32.u64 %0, t; }" : "=r"(a) : "l"(p));
    return a;
}
__device__ __forceinline__ void ldm_x4(uint32_t* r, uint32_t addr) {
    asm volatile("ldmatrix.sync.aligned.m8n8.x4.shared.b16 {%0,%1,%2,%3}, [%4];"
                 : "=r"(r[0]), "=r"(r[1]), "=r"(r[2]), "=r"(r[3]) : "r"(addr));
}
__device__ __forceinline__ void ldm_x4_t(uint32_t* r, uint32_t addr) {
    asm volatile("ldmatrix.sync.aligned.m8n8.x4.trans.shared.b16 {%0,%1,%2,%3}, [%4];"
                 : "=r"(r[0]), "=r"(r[1]), "=r"(r[2]), "=r"(r[3]) : "r"(addr));
}
__device__ __forceinline__ void mma_f16(float* c, const uint32_t* a, const uint32_t* b) {
    asm volatile(
        "mma.sync.aligned.m16n8k16.row.col.f32.f16.f16.f32 "
        "{%0,%1,%2,%3}, {%4,%5,%6,%7}, {%8,%9}, {%0,%1,%2,%3};"
        : "+f"(c[0]), "+f"(c[1]), "+f"(c[2]), "+f"(c[3])
        : "r"(a[0]), "r"(a[1]), "r"(a[2]), "r"(a[3]), "r"(b[0]), "r"(b[1]));
}
__device__ __forceinline__ void cp16(uint32_t dst, const void* src, uint32_t sz) {
    asm volatile("cp.async.cg.shared.global [%0], [%1], 16, %2;"
                 :: "r"(dst), "l"(src), "r"(sz) : "memory");
}
#define CP_COMMIT() asm volatile("cp.async.commit_group;" ::: "memory")
#define CP_WAIT(n)  asm volatile("cp.async.wait_group %0;" :: "n"(n) : "memory")

__device__ __forceinline__ float gelu_exact(float v) {
    return 0.5f * v * (1.0f + erff(v * 0.70710678118654752440f));
}
// fp32 pair -> fp16 hi + fp16 lo planes (A operand split)
__device__ __forceinline__ void split2h(float x, float y, __half2& h, __half2& l) {
    h = __floats2half2_rn(x, y);
    float2 hf = __half22float2(h);
    l = __floats2half2_rn(x - hf.x, y - hf.y);
}
__device__ __forceinline__ uint32_t pack_h2(float x, float y) {
    __half2 h = __floats2half2_rn(x, y);
    return *reinterpret_cast<uint32_t*>(&h);
}

// ---------------- fused weight convert: all 5 weight tensors in ONE launch ----
// (also shifts ncu's skip-5 capture onto a GEMM instead of a convert kernel)
#define NQ2 ((long)LL * DD * 3 * DD / 2)
#define NP2 ((long)LL * DD * DD / 2)
#define NF2 ((long)LL * DD * 4 * DD / 2)
#define NO2 ((long)LL * 4 * DD * DD / 2)
#define NT2 ((long)VV * DD / 2)
#define NALL2 (NQ2 + NP2 + NF2 + NO2 + NT2)

__global__ __launch_bounds__(256) void conv_all(
    const float* __restrict__ wq, const float* __restrict__ wp,
    const float* __restrict__ wf, const float* __restrict__ wo,
    const float* __restrict__ wt,
    __half* __restrict__ oq, __half* __restrict__ op, __half* __restrict__ of,
    __half* __restrict__ oo, __half* __restrict__ ot) {
    long i = (long)blockIdx.x * 256 + threadIdx.x;
    if (i >= NALL2) return;
    const float* src; __half* dst; long off;
    if      (i < NQ2)                   { src = wq; dst = oq; off = i; }
    else if (i < NQ2 + NP2)             { src = wp; dst = op; off = i - NQ2; }
    else if (i < NQ2 + NP2 + NF2)       { src = wf; dst = of; off = i - NQ2 - NP2; }
    else if (i < NQ2 + NP2 + NF2 + NO2) { src = wo; dst = oo; off = i - NQ2 - NP2 - NF2; }
    else                                { src = wt; dst = ot; off = i - NQ2 - NP2 - NF2 - NO2; }
    float2 v = ((const float2*)src)[off];
    ((__half2*)dst)[off] = __floats2half2_rn(v.x, v.y);
}

// ============================ mma.sync fp16 GEMM ============================
// 3-stage cp.async ring, ONE __syncthreads per K-chunk.
// TM: CTA row-tile (128, or 64 for narrow-N GEMMs to fill all SMs).
#define EPI_NONE      0
#define EPI_BIAS      1
#define EPI_BIAS_GELU 2
#define EPI_BIAS_RES  3

template <int EPI, bool WKN, bool OSPLIT, bool ASPLIT, int TM>
__global__ __launch_bounds__(256)
void gemm_f16(const __half* __restrict__ Ah, const __half* __restrict__ Al,
              const __half* __restrict__ Bh,
              const float* __restrict__ bias, const float* __restrict__ res,
              float* __restrict__ C,
              __half* __restrict__ Ch, __half* __restrict__ Cl,
              int N, int K) {
    constexpr int AS   = 80;
    constexpr int BRS  = WKN ? 272 : 80;
    constexpr int BRN  = WKN ? 32  : 128;
    constexpr int AHo  = 0;
    constexpr int ALo  = TM * AS;
    constexpr int BHo  = ASPLIT ? (2 * TM * AS) : (TM * AS);
    constexpr int STG  = BHo + BRN * BRS;
    constexpr int MT   = TM / 64;               // m16-fragments per warp (2 or 1)
    constexpr int AG   = TM / 64;               // A cp.async groups of 256 chunks

    extern __shared__ char sm[];
    const uint32_t sb = smem_u32(sm);

    int tid = threadIdx.x, lane = tid & 31, wid = tid >> 5;
    int row0 = (WKN ? blockIdx.y : blockIdx.x) * TM;
    int col0 = (WKN ? blockIdx.x : blockIdx.y) * 128;
    int wr = wid >> 1, wc = wid & 1;
    int mbase = wr * (TM / 4), nbase = wc * 64;

    float acc[MT][8][4];
    #pragma unroll
    for (int a = 0; a < MT; a++)
        #pragma unroll
        for (int b = 0; b < 8; b++)
            #pragma unroll
            for (int c = 0; c < 4; c++) acc[a][b][c] = 0.f;

    const int nk = K >> 5;

    auto issue = [&](int c) {
        uint32_t st = sb + (uint32_t)(c % 3) * STG;
        int k0 = c << 5;
        #pragma unroll
        for (int g = 0; g < AG; g++) {
            int ch  = g * 256 + tid;
            int r   = ch >> 2, off = ch & 3;
            size_t  so = (size_t)(row0 + r) * K + k0 + off * 8;
            uint32_t d = st + AHo + (uint32_t)(r * AS + off * 16);
            cp16(d, Ah + so, 16);
            if (ASPLIT) cp16(d + (ALo - AHo), Al + so, 16);
        }
        if (WKN) {
            #pragma unroll
            for (int g = 0; g < 2; g++) {
                int ch = g * 256 + tid;
                int kr = ch >> 4, off = ch & 15;
                size_t  so = (size_t)(k0 + kr) * N + col0 + off * 8;
                uint32_t d = st + BHo + (uint32_t)(kr * BRS + off * 16);
                cp16(d, Bh + so, 16);
            }
        } else {
            #pragma unroll
            for (int g = 0; g < 2; g++) {
                int ch = g * 256 + tid;
                int r  = ch >> 2, off = ch & 3;
                int gn = col0 + r;
                uint32_t sz = (gn < N) ? 16u : 0u;
                int gcl = (gn < N) ? gn : (N - 1);
                size_t  so = (size_t)gcl * K + k0 + off * 8;
                uint32_t d = st + BHo + (uint32_t)(r * BRS + off * 16);
                cp16(d, Bh + so, sz);
            }
        }
        CP_COMMIT();
    };

    auto compute = [&](int buf) {
        uint32_t st = sb + (uint32_t)buf * STG;
        #pragma unroll
        for (int kk = 0; kk < 2; kk++) {
            uint32_t ah[MT][4], al[MT][4];
            #pragma unroll
            for (int mt = 0; mt < MT; mt++) {
                int r = mbase + mt * 16 + (lane & 15);
                uint32_t a = st + AHo + (uint32_t)(r * AS + kk * 32 + (lane >> 4) * 16);
                ldm_x4(ah[mt], a);
                if (ASPLIT) ldm_x4(al[mt], a + (ALo - AHo));
            }
            #pragma unroll
            for (int ng = 0; ng < 4; ng++) {
                uint32_t bh[4];
                uint32_t bsh[2][2];
                if (WKN) {
                    int krow = kk * 16 + (lane & 15);
                    uint32_t ba = st + BHo + (uint32_t)(krow * BRS
                                + (nbase + ng * 16) * 2 + (lane >> 4) * 16);
                    ldm_x4_t(bh, ba);
                    bsh[0][0] = bh[0]; bsh[0][1] = bh[1]; bsh[1][0] = bh[2]; bsh[1][1] = bh[3];
                } else {
                    int nrow = nbase + ng * 16 + (lane & 15);
                    uint32_t ba = st + BHo + (uint32_t)(nrow * BRS + kk * 32 + (lane >> 4) * 16);
                    ldm_x4(bh, ba);
                    bsh[0][0] = bh[0]; bsh[0][1] = bh[2]; bsh[1][0] = bh[1]; bsh[1][1] = bh[3];
                }
                #pragma unroll
                for (int mt = 0; mt < MT; mt++) {
                    #pragma unroll
                    for (int h2 = 0; h2 < 2; h2++) {
                        float* a = acc[mt][ng * 2 + h2];
                        mma_f16(a, ah[mt], bsh[h2]);
                        if (ASPLIT) mma_f16(a, al[mt], bsh[h2]);
                    }
                }
            }
        }
    };

    // 3-stage ring: issue(c+2) targets buf (c-1)%3, which the per-iteration
    // barrier proves fully consumed (all warps finished compute(c-1)).
    issue(0); issue(1);
    for (int c = 0; c < nk; c++) {
        if (c == nk - 1) { CP_WAIT(0); } else { CP_WAIT(1); }
        __syncthreads();
        if (c + 2 < nk) issue(c + 2);
        compute(c % 3);
    }

    #pragma unroll
    for (int mt = 0; mt < MT; mt++) {
        #pragma unroll
        for (int nf = 0; nf < 8; nf++) {
            int col = col0 + nbase + nf * 8 + (lane & 3) * 2;
            int r   = row0 + mbase + mt * 16 + (lane >> 2);
            float v0 = acc[mt][nf][0], v1 = acc[mt][nf][1];
            float v2 = acc[mt][nf][2], v3 = acc[mt][nf][3];
            if (EPI >= 1) {
                float b0 = bias[col], b1 = bias[col + 1];
                v0 += b0; v1 += b1; v2 += b0; v3 += b1;
            }
            if (EPI == EPI_BIAS_GELU) {
                v0 = gelu_exact(v0); v1 = gelu_exact(v1);
                v2 = gelu_exact(v2); v3 = gelu_exact(v3);
            }
            if (EPI == EPI_BIAS_RES) {
                float2 ra = *(const float2*)&res[(size_t)r * N + col];
                float2 rb = *(const float2*)&res[(size_t)(r + 8) * N + col];
                v0 += ra.x; v1 += ra.y; v2 += rb.x; v3 += rb.y;
            }
            if (OSPLIT) {
                __half2 h, l;
                split2h(v0, v1, h, l);
                *(__half2*)&Ch[(size_t)r * N + col] = h;
                *(__half2*)&Cl[(size_t)r * N + col] = l;
                split2h(v2, v3, h, l);
                *(__half2*)&Ch[(size_t)(r + 8) * N + col] = h;
                *(__half2*)&Cl[(size_t)(r + 8) * N + col] = l;
            } else if (!WKN) {
                if (col < N) {
                    C[(size_t)r * N + col] = v0;
                    C[(size_t)(r + 8) * N + col] = v2;
                }
                if (col + 1 < N) {
                    C[(size_t)r * N + col + 1] = v1;
                    C[(size_t)(r + 8) * N + col + 1] = v3;
                }
            } else {
                *(float2*)&C[(size_t)r * N + col]       = make_float2(v0, v1);
                *(float2*)&C[(size_t)(r + 8) * N + col] = make_float2(v2, v3);
            }
        }
    }
}

#define GSM_WKN128 (3 * (2 * 128 * 80 + 32 * 272))   // 87552
#define GSM_WKN64  (3 * (2 * 64 * 80 + 32 * 272))    // 56832
#define GSM_NT     (3 * (2 * 128 * 80))              // 61440

// ---------------- embedding ----------------
__global__ void embed_k(const int* __restrict__ ids, const float* __restrict__ wte,
                        const float* __restrict__ wpe, float* __restrict__ x) {
    int row = blockIdx.x;
    int t   = row % TT;
    int id  = ids[row];
    const float* we = wte + (size_t)id * DD;
    const float* pe = wpe + (size_t)t * DD;
    float* xr = x + (size_t)row * DD;
    for (int d = threadIdx.x; d < DD; d += blockDim.x)
        xr[d] = we[d] + pe[d];
}

// ---------------- layernorm -> split fp16 planes ----------------
__global__ __launch_bounds__(256) void ln_k(const float* __restrict__ x,
                                            const float* __restrict__ g,
                                            const float* __restrict__ b,
                                            __half* __restrict__ yh,
                                            __half* __restrict__ yl) {
    int row = blockIdx.x;
    const float* xr = x + (size_t)row * DD;
    float s = 0.f, ss = 0.f;
    for (int d = threadIdx.x; d < DD; d += 256) {
        float v = xr[d];
        s += v; ss += v * v;
    }
    __shared__ float rs[8], rss[8];
    #pragma unroll
    for (int o = 16; o; o >>= 1) {
        s  += __shfl_xor_sync(0xffffffffu, s,  o);
        ss += __shfl_xor_sync(0xffffffffu, ss, o);
    }
    int w = threadIdx.x >> 5;
    if ((threadIdx.x & 31) == 0) { rs[w] = s; rss[w] = ss; }
    __syncthreads();
    if (threadIdx.x < 32) {
        s  = (threadIdx.x < 8) ? rs[threadIdx.x]  : 0.f;
        ss = (threadIdx.x < 8) ? rss[threadIdx.x] : 0.f;
        #pragma unroll
        for (int o = 4; o; o >>= 1) {
            s  += __shfl_xor_sync(0xffffffffu, s,  o);
            ss += __shfl_xor_sync(0xffffffffu, ss, o);
        }
        if (threadIdx.x == 0) { rs[0] = s; rss[0] = ss; }
    }
    __syncthreads();
    float mu  = rs[0]  * (1.f / DD);
    float var = rss[0] * (1.f / DD) - mu * mu;
    float inv = rsqrtf(var + 1e-5f);
    for (int d = threadIdx.x * 2; d < DD; d += 512) {
        float v0 = g[d]     * (xr[d]     - mu) * inv + b[d];
        float v1 = g[d + 1] * (xr[d + 1] - mu) * inv + b[d + 1];
        __half2 h, l;
        split2h(v0, v1, h, l);
        *(__half2*)&yh[(size_t)row * DD + d] = h;
        *(__half2*)&yl[(size_t)row * DD + d] = l;
    }
}

// ============ tensor-core causal flash attention (fp16 mma, FA2-style) ============
__global__ __launch_bounds__(128) void attn_k(const float* __restrict__ qkv,
                                              __half* __restrict__ oh,
                                              __half* __restrict__ ol) {
    __shared__ __align__(16) __half SB[128 * 72];   // 18432 B, row stride 144 B
    const uint32_t sb = smem_u32(SB);

    int bq = blockIdx.x, hd = blockIdx.y, b = blockIdx.z;
    int tid = threadIdx.x, lane = tid & 31, w = tid >> 5;
    int wbase = w * 32;

    uint32_t aqh[2][4][4], aql[2][4][4];
    {
        const float* qp = &qkv[(size_t)(b * TT + bq * 128 + tid) * (3 * DD) + hd * HDD];
        __half2 lo_keep[32];
        #pragma unroll
        for (int i = 0; i < 16; i++) {
            float4 v = ((const float4*)qp)[i];
            __half2 h0, l0, h1, l1;
            split2h(v.x * 0.125f, v.y * 0.125f, h0, l0);
            split2h(v.z * 0.125f, v.w * 0.125f, h1, l1);
            *(__half2*)&SB[tid * 72 + i * 4]     = h0;
            *(__half2*)&SB[tid * 72 + i * 4 + 2] = h1;
            lo_keep[2 * i] = l0; lo_keep[2 * i + 1] = l1;
        }
        __syncthreads();
        #pragma unroll
        for (int mt = 0; mt < 2; mt++)
            #pragma unroll
            for (int ks = 0; ks < 4; ks++)
                ldm_x4(aqh[mt][ks], sb + (uint32_t)((wbase + mt * 16 + (lane & 15)) * 144
                                                    + ks * 32 + (lane >> 4) * 16));
        __syncthreads();
        #pragma unroll
        for (int i = 0; i < 32; i++)
            *(__half2*)&SB[tid * 72 + i * 2] = lo_keep[i];
        __syncthreads();
        #pragma unroll
        for (int mt = 0; mt < 2; mt++)
            #pragma unroll
            for (int ks = 0; ks < 4; ks++)
                ldm_x4(aql[mt][ks], sb + (uint32_t)((wbase + mt * 16 + (lane & 15)) * 144
                                                    + ks * 32 + (lane >> 4) * 16));
        __syncthreads();
    }

    float o[2][8][4];
    #pragma unroll
    for (int a = 0; a < 2; a++)
        #pragma unroll
        for (int nt = 0; nt < 8; nt++)
            #pragma unroll
            for (int j = 0; j < 4; j++) o[a][nt][j] = 0.f;
    float m[2][2] = {{-1e30f, -1e30f}, {-1e30f, -1e30f}};
    float lsum[2][2] = {{0.f, 0.f}, {0.f, 0.f}};

    const uint32_t Vbase = sb + 64 * 144;
    int nkt = 2 * bq + 2;
    for (int kt = 0; kt < nkt; kt++) {
        int kb = kt * 64;
        {
            int r = tid >> 1, dh = (tid & 1) * 32;
            const float* kp = &qkv[(size_t)(b * TT + kb + r) * (3 * DD) + DD + hd * HDD + dh];
            const float* vp = kp + DD;
            #pragma unroll
            for (int i = 0; i < 8; i++) {
                float4 kv = ((const float4*)kp)[i];
                float4 vv = ((const float4*)vp)[i];
                *(__half2*)&SB[r * 72 + dh + i * 4]     = __floats2half2_rn(kv.x, kv.y);
                *(__half2*)&SB[r * 72 + dh + i * 4 + 2] = __floats2half2_rn(kv.z, kv.w);
                *(__half2*)&SB[64 * 72 + r * 72 + dh + i * 4]     = __floats2half2_rn(vv.x, vv.y);
                *(__half2*)&SB[64 * 72 + r * 72 + dh + i * 4 + 2] = __floats2half2_rn(vv.z, vv.w);
            }
        }
        __syncthreads();

        float c[2][8][4];
        #pragma unroll
        for (int a = 0; a < 2; a++)
            #pragma unroll
            for (int nt = 0; nt < 8; nt++)
                #pragma unroll
                for (int j = 0; j < 4; j++) c[a][nt][j] = 0.f;
        #pragma unroll
        for (int ks = 0; ks < 4; ks++) {
            #pragma unroll
            for (int ng = 0; ng < 4; ng++) {
                uint32_t bh[4], bsh[2][2];
                ldm_x4(bh, sb + (uint32_t)((ng * 16 + (lane & 15)) * 144
                                           + ks * 32 + (lane >> 4) * 16));
                bsh[0][0] = bh[0]; bsh[0][1] = bh[2]; bsh[1][0] = bh[1]; bsh[1][1] = bh[3];
                #pragma unroll
                for (int mt = 0; mt < 2; mt++) {
                    #pragma unroll
                    for (int h2 = 0; h2 < 2; h2++) {
                        mma_f16(c[mt][ng * 2 + h2], aqh[mt][ks], bsh[h2]);
                        mma_f16(c[mt][ng * 2 + h2], aql[mt][ks], bsh[h2]);
                    }
                }
            }
        }

        if (kt >= 2 * bq) {
            #pragma unroll
            for (int mt = 0; mt < 2; mt++)
                #pragma unroll
                for (int nt = 0; nt < 8; nt++)
                    #pragma unroll
                    for (int j = 0; j < 4; j++) {
                        int key = kb + nt * 8 + (lane & 3) * 2 + (j & 1);
                        int qr  = bq * 128 + wbase + mt * 16 + (lane >> 2) + ((j >> 1) << 3);
                        if (key > qr) c[mt][nt][j] = -1e30f;
                    }
        }

        #pragma unroll
        for (int mt = 0; mt < 2; mt++) {
            #pragma unroll
            for (int h = 0; h < 2; h++) {
                float tm = -1e30f;
                #pragma unroll
                for (int nt = 0; nt < 8; nt++)
                    tm = fmaxf(tm, fmaxf(c[mt][nt][2 * h], c[mt][nt][2 * h + 1]));
                tm = fmaxf(tm, __shfl_xor_sync(0xffffffffu, tm, 1));
                tm = fmaxf(tm, __shfl_xor_sync(0xffffffffu, tm, 2));
                float mn = fmaxf(m[mt][h], tm);
                float corr = __expf(m[mt][h] - mn);
                m[mt][h] = mn;
                float ts = 0.f;
                #pragma unroll
                for (int nt = 0; nt < 8; nt++) {
                    float p0 = __expf(c[mt][nt][2 * h]     - mn);
                    float p1 = __expf(c[mt][nt][2 * h + 1] - mn);
                    c[mt][nt][2 * h] = p0; c[mt][nt][2 * h + 1] = p1;
                    ts += p0 + p1;
                }
                ts += __shfl_xor_sync(0xffffffffu, ts, 1);
                ts += __shfl_xor_sync(0xffffffffu, ts, 2);
                lsum[mt][h] = lsum[mt][h] * corr + ts;
                #pragma unroll
                for (int nt = 0; nt < 8; nt++) {
                    o[mt][nt][2 * h]     *= corr;
                    o[mt][nt][2 * h + 1] *= corr;
                }
            }
        }

        #pragma unroll
        for (int ks = 0; ks < 4; ks++) {
            uint32_t ap[2][4];
            #pragma unroll
            for (int mt = 0; mt < 2; mt++) {
                ap[mt][0] = pack_h2(c[mt][2 * ks][0],     c[mt][2 * ks][1]);
                ap[mt][1] = pack_h2(c[mt][2 * ks][2],     c[mt][2 * ks][3]);
                ap[mt][2] = pack_h2(c[mt][2 * ks + 1][0], c[mt][2 * ks + 1][1]);
                ap[mt][3] = pack_h2(c[mt][2 * ks + 1][2], c[mt][2 * ks + 1][3]);
            }
            #pragma unroll
            for (int ng = 0; ng < 4; ng++) {
                uint32_t bh[4], bsh[2][2];
                ldm_x4_t(bh, Vbase + (uint32_t)((ks * 16 + (lane & 15)) * 144
                                                + (ng * 16) * 2 + (lane >> 4) * 16));
                bsh[0][0] = bh[0]; bsh[0][1] = bh[1]; bsh[1][0] = bh[2]; bsh[1][1] = bh[3];
                #pragma unroll
                for (int mt = 0; mt < 2; mt++)
                    #pragma unroll
                    for (int h2 = 0; h2 < 2; h2++)
                        mma_f16(o[mt][ng * 2 + h2], ap[mt], bsh[h2]);
            }
        }
        __syncthreads();
    }

    #pragma unroll
    for (int mt = 0; mt < 2; mt++) {
        #pragma unroll
        for (int h = 0; h < 2; h++) {
            float inv = 1.f / lsum[mt][h];
            int row = bq * 128 + wbase + mt * 16 + (lane >> 2) + h * 8;
            size_t ro = (size_t)(b * TT + row) * DD + hd * HDD;
            #pragma unroll
            for (int nt = 0; nt < 8; nt++) {
                int col = nt * 8 + (lane & 3) * 2;
                __half2 hh, ll;
                split2h(o[mt][nt][2 * h] * inv, o[mt][nt][2 * h + 1] * inv, hh, ll);
                *(__half2*)&oh[ro + col] = hh;
                *(__half2*)&ol[ro + col] = ll;
            }
        }
    }
}

extern "C" void kernel_launch(void* const* d_in, const int* in_sizes, int n_in,
                              void* d_out, int out_size) {
    const int*   ids    = (const int*)  d_in[0];
    const float* wte    = (const float*)d_in[1];
    const float* wpe    = (const float*)d_in[2];
    const float* ln1_g  = (const float*)d_in[3];
    const float* ln1_b  = (const float*)d_in[4];
    const float* attn_w = (const float*)d_in[5];
    const float* attn_b = (const float*)d_in[6];
    const float* proj_w = (const float*)d_in[7];
    const float* proj_b = (const float*)d_in[8];
    const float* ln2_g  = (const float*)d_in[9];
    const float* ln2_b  = (const float*)d_in[10];
    const float* fc_w   = (const float*)d_in[11];
    const float* fc_b   = (const float*)d_in[12];
    const float* out_w  = (const float*)d_in[13];
    const float* out_b  = (const float*)d_in[14];
    const float* lnf_g  = (const float*)d_in[15];
    const float* lnf_b  = (const float*)d_in[16];
    float* logits = (float*)d_out;

    float *x, *qkv;
    __half *hh, *hl, *ath, *atl, *mph, *mpl;
    __half *wq, *wp, *wf, *wo, *wt;
    cudaGetSymbolAddress((void**)&x,   g_x);
    cudaGetSymbolAddress((void**)&qkv, g_qkv);
    cudaGetSymbolAddress((void**)&hh,  g_hh);  cudaGetSymbolAddress((void**)&hl,  g_hl);
    cudaGetSymbolAddress((void**)&ath, g_ath); cudaGetSymbolAddress((void**)&atl, g_atl);
    cudaGetSymbolAddress((void**)&mph, g_mph); cudaGetSymbolAddress((void**)&mpl, g_mpl);
    cudaGetSymbolAddress((void**)&wq,  g_wq);
    cudaGetSymbolAddress((void**)&wp,  g_wp);
    cudaGetSymbolAddress((void**)&wf,  g_wf);
    cudaGetSymbolAddress((void**)&wo,  g_wo);
    cudaGetSymbolAddress((void**)&wt,  g_wt);

    cudaFuncSetAttribute(gemm_f16<EPI_BIAS,      true,  false, true,  128>, cudaFuncAttributeMaxDynamicSharedMemorySize, GSM_WKN128);
    cudaFuncSetAttribute(gemm_f16<EPI_BIAS_RES,  true,  false, true,  64 >, cudaFuncAttributeMaxDynamicSharedMemorySize, GSM_WKN64);
    cudaFuncSetAttribute(gemm_f16<EPI_BIAS_GELU, true,  true,  true,  128>, cudaFuncAttributeMaxDynamicSharedMemorySize, GSM_WKN128);
    cudaFuncSetAttribute(gemm_f16<EPI_NONE,      false, false, false, 128>, cudaFuncAttributeMaxDynamicSharedMemorySize, GSM_NT);

    // ---- fused weight convert (1 launch) ----
    {
        long blocks = (NALL2 + 255) / 256;
        conv_all<<<(int)blocks, 256>>>(attn_w, proj_w, fc_w, out_w, wte,
                                       wq, wp, wf, wo, wt);
    }

    embed_k<<<MTOK, 256>>>(ids, wte, wpe, x);

    for (int l = 0; l < LL; l++) {
        // attention block
        ln_k<<<MTOK, 256>>>(x, ln1_g + l * DD, ln1_b + l * DD, hh, hl);
        gemm_f16<EPI_BIAS, true, false, true, 128><<<dim3(3 * DD / 128, MTOK / 128), 256, GSM_WKN128>>>(
            hh, hl, wq + (size_t)l * DD * 3 * DD,
            attn_b + (size_t)l * 3 * DD, nullptr, qkv, nullptr, nullptr, 3 * DD, DD);
        attn_k<<<dim3(TT / 128, HH, BB), 128>>>(qkv, ath, atl);
        gemm_f16<EPI_BIAS_RES, true, false, true, 64><<<dim3(DD / 128, MTOK / 64), 256, GSM_WKN64>>>(
            ath, atl, wp + (size_t)l * DD * DD,
            proj_b + (size_t)l * DD, x, x, nullptr, nullptr, DD, DD);
        // mlp block
        ln_k<<<MTOK, 256>>>(x, ln2_g + l * DD, ln2_b + l * DD, hh, hl);
        gemm_f16<EPI_BIAS_GELU, true, true, true, 128><<<dim3(4 * DD / 128, MTOK / 128), 256, GSM_WKN128>>>(
            hh, hl, wf + (size_t)l * DD * 4 * DD,
            fc_b + (size_t)l * 4 * DD, nullptr, nullptr, mph, mpl, 4 * DD, DD);
        gemm_f16<EPI_BIAS_RES, true, false, true, 64><<<dim3(DD / 128, MTOK / 64), 256, GSM_WKN64>>>(
            mph, mpl, wo + (size_t)l * 4 * DD * DD,
            out_b + (size_t)l * DD, x, x, nullptr, nullptr, DD, 4 * DD);
    }

    ln_k<<<MTOK, 256>>>(x, lnf_g, lnf_b, hh, hl);
    // lm-head: single-MMA (A hi only — final op, error doesn't compound);
    // row tiles fastest so CTAs sharing a wte col-tile are L2-adjacent
    gemm_f16<EPI_NONE, false, false, false, 128><<<dim3(MTOK / 128, (VV + 127) / 128), 256, GSM_NT>>>(
        hh, hl, wt, nullptr, nullptr, logits, nullptr, nullptr, VV, DD);
}

// round 16
// speedup vs baseline: 5.2966x; 1.1156x over previous
#include <cuda_runtime.h>
#include <cuda_fp16.h>
#include <cstdint>
#include <math.h>

#define BB   2
#define TT   1024
#define DD   768
#define LL   4
#define HH   12
#define HDD  64
#define VV   50257
#define MTOK (BB * TT)   // 2048 token rows

// ---------------- scratch (allocation-free: __device__ globals) ----------------
__device__ float g_x  [MTOK * DD];          // residual stream (fp32)
__device__ float g_qkv[MTOK * 3 * DD];      // qkv (fp32, read by attention)
// fp16 activation planes
__device__ __half g_hh [MTOK * DD],      g_hl [MTOK * DD];       // LN out (split)
__device__ __half g_ath[MTOK * DD],      g_atl[MTOK * DD];       // attn out (split)
__device__ __half g_mph[MTOK * 4 * DD];                          // gelu out (hi only)
// single fp16 weight planes (GEMM B operands)
__device__ __half g_wq[LL * DD * 3 * DD];
__device__ __half g_wp[LL * DD * DD];
__device__ __half g_wf[LL * DD * 4 * DD];
__device__ __half g_wo[LL * 4 * DD * DD];
__device__ __half g_wt[VV * DD];

// ============================ helpers ============================
__device__ __forceinline__ uint32_t smem_u32(const void* p) {
    uint32_t a;
    asm("{ .reg .u64 t; cvta.to.shared.u64 t, %1; cvt.u32.u64 %0, t; }" : "=r"(a) : "l"(p));
    return a;
}
__device__ __forceinline__ void ldm_x4(uint32_t* r, uint32_t addr) {
    asm volatile("ldmatrix.sync.aligned.m8n8.x4.shared.b16 {%0,%1,%2,%3}, [%4];"
                 : "=r"(r[0]), "=r"(r[1]), "=r"(r[2]), "=r"(r[3]) : "r"(addr));
}
__device__ __forceinline__ void ldm_x4_t(uint32_t* r, uint32_t addr) {
    asm volatile("ldmatrix.sync.aligned.m8n8.x4.trans.shared.b16 {%0,%1,%2,%3}, [%4];"
                 : "=r"(r[0]), "=r"(r[1]), "=r"(r[2]), "=r"(r[3]) : "r"(addr));
}
__device__ __forceinline__ void mma_f16(float* c, const uint32_t* a, const uint32_t* b) {
    asm volatile(
        "mma.sync.aligned.m16n8k16.row.col.f32.f16.f16.f32 "
        "{%0,%1,%2,%3}, {%4,%5,%6,%7}, {%8,%9}, {%0,%1,%2,%3};"
        : "+f"(c[0]), "+f"(c[1]), "+f"(c[2]), "+f"(c[3])
        : "r"(a[0]), "r"(a[1]), "r"(a[2]), "r"(a[3]), "r"(b[0]), "r"(b[1]));
}
__device__ __forceinline__ void cp16(uint32_t dst, const void* src, uint32_t sz) {
    asm volatile("cp.async.cg.shared.global [%0], [%1], 16, %2;"
                 :: "r"(dst), "l"(src), "r"(sz) : "memory");
}
#define CP_COMMIT() asm volatile("cp.async.commit_group;" ::: "memory")
#define CP_WAIT(n)  asm volatile("cp.async.wait_group %0;" :: "n"(n) : "memory")

__device__ __forceinline__ float gelu_exact(float v) {
    return 0.5f * v * (1.0f + erff(v * 0.70710678118654752440f));
}
__device__ __forceinline__ void split2h(float x, float y, __half2& h, __half2& l) {
    h = __floats2half2_rn(x, y);
    float2 hf = __half22float2(h);
    l = __floats2half2_rn(x - hf.x, y - hf.y);
}
__device__ __forceinline__ uint32_t pack_h2(float x, float y) {
    __half2 h = __floats2half2_rn(x, y);
    return *reinterpret_cast<uint32_t*>(&h);
}

// ---------------- fused weight convert (one launch) ----------------
#define NQ2 ((long)LL * DD * 3 * DD / 2)
#define NP2 ((long)LL * DD * DD / 2)
#define NF2 ((long)LL * DD * 4 * DD / 2)
#define NO2 ((long)LL * 4 * DD * DD / 2)
#define NT2 ((long)VV * DD / 2)
#define NALL2 (NQ2 + NP2 + NF2 + NO2 + NT2)

__global__ __launch_bounds__(256) void conv_all(
    const float* __restrict__ wq, const float* __restrict__ wp,
    const float* __restrict__ wf, const float* __restrict__ wo,
    const float* __restrict__ wt,
    __half* __restrict__ oq, __half* __restrict__ op, __half* __restrict__ of,
    __half* __restrict__ oo, __half* __restrict__ ot) {
    long i = (long)blockIdx.x * 256 + threadIdx.x;
    if (i >= NALL2) return;
    const float* src; __half* dst; long off;
    if      (i < NQ2)                   { src = wq; dst = oq; off = i; }
    else if (i < NQ2 + NP2)             { src = wp; dst = op; off = i - NQ2; }
    else if (i < NQ2 + NP2 + NF2)       { src = wf; dst = of; off = i - NQ2 - NP2; }
    else if (i < NQ2 + NP2 + NF2 + NO2) { src = wo; dst = oo; off = i - NQ2 - NP2 - NF2; }
    else                                { src = wt; dst = ot; off = i - NQ2 - NP2 - NF2 - NO2; }
    float2 v = ((const float2*)src)[off];
    ((__half2*)dst)[off] = __floats2half2_rn(v.x, v.y);
}

// ============================ mma.sync fp16 GEMM ============================
// 3-stage cp.async ring, one __syncthreads per 32-K chunk.
// TM: CTA row tile (128 / 64).  TN: CTA col tile (128, or 256 for lm-head).
// OMODE: 0 = fp32 C (float2 if WKN, bounded scalar otherwise)
//        1 = split fp16 hi/lo planes      2 = fp16 hi plane only
#define EPI_NONE      0
#define EPI_BIAS      1
#define EPI_BIAS_GELU 2
#define EPI_BIAS_RES  3

template <int EPI, bool WKN, int OMODE, bool ASPLIT, int TM, int TN>
__global__ __launch_bounds__(256)
void gemm_f16(const __half* __restrict__ Ah, const __half* __restrict__ Al,
              const __half* __restrict__ Bh,
              const float* __restrict__ bias, const float* __restrict__ res,
              float* __restrict__ C,
              __half* __restrict__ Ch, __half* __restrict__ Cl,
              int N, int K) {
    constexpr int AS   = 80;
    constexpr int BRS  = WKN ? (TN * 2 + 16) : 80;   // WKN: TN fp16 + 16B pad
    constexpr int BRN  = WKN ? 32 : TN;
    constexpr int AHo  = 0;
    constexpr int ALo  = TM * AS;
    constexpr int BHo  = ASPLIT ? (2 * TM * AS) : (TM * AS);
    constexpr int STG  = BHo + BRN * BRS;
    constexpr int MT   = TM / 64;          // m16 fragments per warp
    constexpr int AG   = TM / 64;          // A cp.async groups
    constexpr int BG   = WKN ? 2 : (TN / 64);   // B cp.async groups
    constexpr int NG   = TN / 32;          // 16-col groups per warp
    constexpr int NF   = TN / 16;          // n8 fragments per warp

    extern __shared__ char sm[];
    const uint32_t sb = smem_u32(sm);

    int tid = threadIdx.x, lane = tid & 31, wid = tid >> 5;
    int row0 = (WKN ? blockIdx.y : blockIdx.x) * TM;
    int col0 = (WKN ? blockIdx.x : blockIdx.y) * TN;
    int wr = wid >> 1, wc = wid & 1;
    int mbase = wr * (TM / 4), nbase = wc * (TN / 2);

    float acc[MT][NF][4];
    #pragma unroll
    for (int a = 0; a < MT; a++)
        #pragma unroll
        for (int b = 0; b < NF; b++)
            #pragma unroll
            for (int c = 0; c < 4; c++) acc[a][b][c] = 0.f;

    const int nk = K >> 5;

    auto issue = [&](int c) {
        uint32_t st = sb + (uint32_t)(c % 3) * STG;
        int k0 = c << 5;
        #pragma unroll
        for (int g = 0; g < AG; g++) {
            int ch  = g * 256 + tid;
            int r   = ch >> 2, off = ch & 3;
            size_t  so = (size_t)(row0 + r) * K + k0 + off * 8;
            uint32_t d = st + AHo + (uint32_t)(r * AS + off * 16);
            cp16(d, Ah + so, 16);
            if (ASPLIT) cp16(d + (ALo - AHo), Al + so, 16);
        }
        if (WKN) {
            #pragma unroll
            for (int g = 0; g < BG; g++) {
                int ch = g * 256 + tid;
                int kr = ch >> 4, off = ch & 15;
                size_t  so = (size_t)(k0 + kr) * N + col0 + off * 8;
                uint32_t d = st + BHo + (uint32_t)(kr * BRS + off * 16);
                cp16(d, Bh + so, 16);
            }
        } else {
            #pragma unroll
            for (int g = 0; g < BG; g++) {
                int ch = g * 256 + tid;
                int r  = ch >> 2, off = ch & 3;
                int gn = col0 + r;
                uint32_t sz = (gn < N) ? 16u : 0u;
                int gcl = (gn < N) ? gn : (N - 1);
                size_t  so = (size_t)gcl * K + k0 + off * 8;
                uint32_t d = st + BHo + (uint32_t)(r * BRS + off * 16);
                cp16(d, Bh + so, sz);
            }
        }
        CP_COMMIT();
    };

    auto compute = [&](int buf) {
        uint32_t st = sb + (uint32_t)buf * STG;
        #pragma unroll
        for (int kk = 0; kk < 2; kk++) {
            uint32_t ah[MT][4], al[MT][4];
            #pragma unroll
            for (int mt = 0; mt < MT; mt++) {
                int r = mbase + mt * 16 + (lane & 15);
                uint32_t a = st + AHo + (uint32_t)(r * AS + kk * 32 + (lane >> 4) * 16);
                ldm_x4(ah[mt], a);
                if (ASPLIT) ldm_x4(al[mt], a + (ALo - AHo));
            }
            #pragma unroll
            for (int ng = 0; ng < NG; ng++) {
                uint32_t bh[4];
                uint32_t bsh[2][2];
                if (WKN) {
                    int krow = kk * 16 + (lane & 15);
                    uint32_t ba = st + BHo + (uint32_t)(krow * BRS
                                + (nbase + ng * 16) * 2 + (lane >> 4) * 16);
                    ldm_x4_t(bh, ba);
                    bsh[0][0] = bh[0]; bsh[0][1] = bh[1]; bsh[1][0] = bh[2]; bsh[1][1] = bh[3];
                } else {
                    int nrow = nbase + ng * 16 + (lane & 15);
                    uint32_t ba = st + BHo + (uint32_t)(nrow * BRS + kk * 32 + (lane >> 4) * 16);
                    ldm_x4(bh, ba);
                    bsh[0][0] = bh[0]; bsh[0][1] = bh[2]; bsh[1][0] = bh[1]; bsh[1][1] = bh[3];
                }
                #pragma unroll
                for (int mt = 0; mt < MT; mt++) {
                    #pragma unroll
                    for (int h2 = 0; h2 < 2; h2++) {
                        float* a = acc[mt][ng * 2 + h2];
                        mma_f16(a, ah[mt], bsh[h2]);
                        if (ASPLIT) mma_f16(a, al[mt], bsh[h2]);
                    }
                }
            }
        }
    };

    issue(0); issue(1);
    for (int c = 0; c < nk; c++) {
        if (c == nk - 1) { CP_WAIT(0); } else { CP_WAIT(1); }
        __syncthreads();
        if (c + 2 < nk) issue(c + 2);
        compute(c % 3);
    }

    #pragma unroll
    for (int mt = 0; mt < MT; mt++) {
        #pragma unroll
        for (int nf = 0; nf < NF; nf++) {
            int col = col0 + nbase + nf * 8 + (lane & 3) * 2;
            int r   = row0 + mbase + mt * 16 + (lane >> 2);
            float v0 = acc[mt][nf][0], v1 = acc[mt][nf][1];
            float v2 = acc[mt][nf][2], v3 = acc[mt][nf][3];
            if (EPI >= 1) {
                float b0 = bias[col], b1 = bias[col + 1];
                v0 += b0; v1 += b1; v2 += b0; v3 += b1;
            }
            if (EPI == EPI_BIAS_GELU) {
                v0 = gelu_exact(v0); v1 = gelu_exact(v1);
                v2 = gelu_exact(v2); v3 = gelu_exact(v3);
            }
            if (EPI == EPI_BIAS_RES) {
                float2 ra = *(const float2*)&res[(size_t)r * N + col];
                float2 rb = *(const float2*)&res[(size_t)(r + 8) * N + col];
                v0 += ra.x; v1 += ra.y; v2 += rb.x; v3 += rb.y;
            }
            if (OMODE == 1) {
                __half2 h, l;
                split2h(v0, v1, h, l);
                *(__half2*)&Ch[(size_t)r * N + col] = h;
                *(__half2*)&Cl[(size_t)r * N + col] = l;
                split2h(v2, v3, h, l);
                *(__half2*)&Ch[(size_t)(r + 8) * N + col] = h;
                *(__half2*)&Cl[(size_t)(r + 8) * N + col] = l;
            } else if (OMODE == 2) {
                *(__half2*)&Ch[(size_t)r * N + col]       = __floats2half2_rn(v0, v1);
                *(__half2*)&Ch[(size_t)(r + 8) * N + col] = __floats2half2_rn(v2, v3);
            } else if (!WKN) {
                if (col < N) {
                    C[(size_t)r * N + col] = v0;
                    C[(size_t)(r + 8) * N + col] = v2;
                }
                if (col + 1 < N) {
                    C[(size_t)r * N + col + 1] = v1;
                    C[(size_t)(r + 8) * N + col + 1] = v3;
                }
            } else {
                *(float2*)&C[(size_t)r * N + col]       = make_float2(v0, v1);
                *(float2*)&C[(size_t)(r + 8) * N + col] = make_float2(v2, v3);
            }
        }
    }
}

// smem per variant (3-stage ring)
#define GSM_QKV  (3 * (2 * 128 * 80 + 32 * 272))   // 87552  (split A, W[K,N])
#define GSM_PROJ (3 * (2 * 64 * 80 + 32 * 272))    // 56832
#define GSM_FC   (3 * (128 * 80 + 32 * 272))       // 56832  (unsplit A)
#define GSM_OUT  (3 * (64 * 80 + 32 * 272))        // 41472
#define GSM_LMH  (3 * (128 * 80 + 256 * 80))       // 92160  (TN=256, B[N,K])

// ---------------- embedding ----------------
__global__ void embed_k(const int* __restrict__ ids, const float* __restrict__ wte,
                        const float* __restrict__ wpe, float* __restrict__ x) {
    int row = blockIdx.x;
    int t   = row % TT;
    int id  = ids[row];
    const float* we = wte + (size_t)id * DD;
    const float* pe = wpe + (size_t)t * DD;
    float* xr = x + (size_t)row * DD;
    for (int d = threadIdx.x; d < DD; d += blockDim.x)
        xr[d] = we[d] + pe[d];
}

// ---------------- layernorm -> split fp16 planes ----------------
__global__ __launch_bounds__(256) void ln_k(const float* __restrict__ x,
                                            const float* __restrict__ g,
                                            const float* __restrict__ b,
                                            __half* __restrict__ yh,
                                            __half* __restrict__ yl) {
    int row = blockIdx.x;
    const float* xr = x + (size_t)row * DD;
    float s = 0.f, ss = 0.f;
    for (int d = threadIdx.x; d < DD; d += 256) {
        float v = xr[d];
        s += v; ss += v * v;
    }
    __shared__ float rs[8], rss[8];
    #pragma unroll
    for (int o = 16; o; o >>= 1) {
        s  += __shfl_xor_sync(0xffffffffu, s,  o);
        ss += __shfl_xor_sync(0xffffffffu, ss, o);
    }
    int w = threadIdx.x >> 5;
    if ((threadIdx.x & 31) == 0) { rs[w] = s; rss[w] = ss; }
    __syncthreads();
    if (threadIdx.x < 32) {
        s  = (threadIdx.x < 8) ? rs[threadIdx.x]  : 0.f;
        ss = (threadIdx.x < 8) ? rss[threadIdx.x] : 0.f;
        #pragma unroll
        for (int o = 4; o; o >>= 1) {
            s  += __shfl_xor_sync(0xffffffffu, s,  o);
            ss += __shfl_xor_sync(0xffffffffu, ss, o);
        }
        if (threadIdx.x == 0) { rs[0] = s; rss[0] = ss; }
    }
    __syncthreads();
    float mu  = rs[0]  * (1.f / DD);
    float var = rss[0] * (1.f / DD) - mu * mu;
    float inv = rsqrtf(var + 1e-5f);
    for (int d = threadIdx.x * 2; d < DD; d += 512) {
        float v0 = g[d]     * (xr[d]     - mu) * inv + b[d];
        float v1 = g[d + 1] * (xr[d + 1] - mu) * inv + b[d + 1];
        __half2 h, l;
        split2h(v0, v1, h, l);
        *(__half2*)&yh[(size_t)row * DD + d] = h;
        *(__half2*)&yl[(size_t)row * DD + d] = l;
    }
}

// ============ tensor-core causal flash attention (fp16 mma, FA2-style) ============
__global__ __launch_bounds__(128) void attn_k(const float* __restrict__ qkv,
                                              __half* __restrict__ oh,
                                              __half* __restrict__ ol) {
    __shared__ __align__(16) __half SB[128 * 72];   // 18432 B, row stride 144 B
    const uint32_t sb = smem_u32(SB);

    int bq = blockIdx.x, hd = blockIdx.y, b = blockIdx.z;
    int tid = threadIdx.x, lane = tid & 31, w = tid >> 5;
    int wbase = w * 32;

    uint32_t aqh[2][4][4], aql[2][4][4];
    {
        const float* qp = &qkv[(size_t)(b * TT + bq * 128 + tid) * (3 * DD) + hd * HDD];
        __half2 lo_keep[32];
        #pragma unroll
        for (int i = 0; i < 16; i++) {
            float4 v = ((const float4*)qp)[i];
            __half2 h0, l0, h1, l1;
            split2h(v.x * 0.125f, v.y * 0.125f, h0, l0);
            split2h(v.z * 0.125f, v.w * 0.125f, h1, l1);
            *(__half2*)&SB[tid * 72 + i * 4]     = h0;
            *(__half2*)&SB[tid * 72 + i * 4 + 2] = h1;
            lo_keep[2 * i] = l0; lo_keep[2 * i + 1] = l1;
        }
        __syncthreads();
        #pragma unroll
        for (int mt = 0; mt < 2; mt++)
            #pragma unroll
            for (int ks = 0; ks < 4; ks++)
                ldm_x4(aqh[mt][ks], sb + (uint32_t)((wbase + mt * 16 + (lane & 15)) * 144
                                                    + ks * 32 + (lane >> 4) * 16));
        __syncthreads();
        #pragma unroll
        for (int i = 0; i < 32; i++)
            *(__half2*)&SB[tid * 72 + i * 2] = lo_keep[i];
        __syncthreads();
        #pragma unroll
        for (int mt = 0; mt < 2; mt++)
            #pragma unroll
            for (int ks = 0; ks < 4; ks++)
                ldm_x4(aql[mt][ks], sb + (uint32_t)((wbase + mt * 16 + (lane & 15)) * 144
                                                    + ks * 32 + (lane >> 4) * 16));
        __syncthreads();
    }

    float o[2][8][4];
    #pragma unroll
    for (int a = 0; a < 2; a++)
        #pragma unroll
        for (int nt = 0; nt < 8; nt++)
            #pragma unroll
            for (int j = 0; j < 4; j++) o[a][nt][j] = 0.f;
    float m[2][2] = {{-1e30f, -1e30f}, {-1e30f, -1e30f}};
    float lsum[2][2] = {{0.f, 0.f}, {0.f, 0.f}};

    const uint32_t Vbase = sb + 64 * 144;
    int nkt = 2 * bq + 2;
    for (int kt = 0; kt < nkt; kt++) {
        int kb = kt * 64;
        {
            int r = tid >> 1, dh = (tid & 1) * 32;
            const float* kp = &qkv[(size_t)(b * TT + kb + r) * (3 * DD) + DD + hd * HDD + dh];
            const float* vp = kp + DD;
            #pragma unroll
            for (int i = 0; i < 8; i++) {
                float4 kv = ((const float4*)kp)[i];
                float4 vv = ((const float4*)vp)[i];
                *(__half2*)&SB[r * 72 + dh + i * 4]     = __floats2half2_rn(kv.x, kv.y);
                *(__half2*)&SB[r * 72 + dh + i * 4 + 2] = __floats2half2_rn(kv.z, kv.w);
                *(__half2*)&SB[64 * 72 + r * 72 + dh + i * 4]     = __floats2half2_rn(vv.x, vv.y);
                *(__half2*)&SB[64 * 72 + r * 72 + dh + i * 4 + 2] = __floats2half2_rn(vv.z, vv.w);
            }
        }
        __syncthreads();

        float c[2][8][4];
        #pragma unroll
        for (int a = 0; a < 2; a++)
            #pragma unroll
            for (int nt = 0; nt < 8; nt++)
                #pragma unroll
                for (int j = 0; j < 4; j++) c[a][nt][j] = 0.f;
        #pragma unroll
        for (int ks = 0; ks < 4; ks++) {
            #pragma unroll
            for (int ng = 0; ng < 4; ng++) {
                uint32_t bh[4], bsh[2][2];
                ldm_x4(bh, sb + (uint32_t)((ng * 16 + (lane & 15)) * 144
                                           + ks * 32 + (lane >> 4) * 16));
                bsh[0][0] = bh[0]; bsh[0][1] = bh[2]; bsh[1][0] = bh[1]; bsh[1][1] = bh[3];
                #pragma unroll
                for (int mt = 0; mt < 2; mt++) {
                    #pragma unroll
                    for (int h2 = 0; h2 < 2; h2++) {
                        mma_f16(c[mt][ng * 2 + h2], aqh[mt][ks], bsh[h2]);
                        mma_f16(c[mt][ng * 2 + h2], aql[mt][ks], bsh[h2]);
                    }
                }
            }
        }

        if (kt >= 2 * bq) {
            #pragma unroll
            for (int mt = 0; mt < 2; mt++)
                #pragma unroll
                for (int nt = 0; nt < 8; nt++)
                    #pragma unroll
                    for (int j = 0; j < 4; j++) {
                        int key = kb + nt * 8 + (lane & 3) * 2 + (j & 1);
                        int qr  = bq * 128 + wbase + mt * 16 + (lane >> 2) + ((j >> 1) << 3);
                        if (key > qr) c[mt][nt][j] = -1e30f;
                    }
        }

        #pragma unroll
        for (int mt = 0; mt < 2; mt++) {
            #pragma unroll
            for (int h = 0; h < 2; h++) {
                float tm = -1e30f;
                #pragma unroll
                for (int nt = 0; nt < 8; nt++)
                    tm = fmaxf(tm, fmaxf(c[mt][nt][2 * h], c[mt][nt][2 * h + 1]));
                tm = fmaxf(tm, __shfl_xor_sync(0xffffffffu, tm, 1));
                tm = fmaxf(tm, __shfl_xor_sync(0xffffffffu, tm, 2));
                float mn = fmaxf(m[mt][h], tm);
                float corr = __expf(m[mt][h] - mn);
                m[mt][h] = mn;
                float ts = 0.f;
                #pragma unroll
                for (int nt = 0; nt < 8; nt++) {
                    float p0 = __expf(c[mt][nt][2 * h]     - mn);
                    float p1 = __expf(c[mt][nt][2 * h + 1] - mn);
                    c[mt][nt][2 * h] = p0; c[mt][nt][2 * h + 1] = p1;
                    ts += p0 + p1;
                }
                ts += __shfl_xor_sync(0xffffffffu, ts, 1);
                ts += __shfl_xor_sync(0xffffffffu, ts, 2);
                lsum[mt][h] = lsum[mt][h] * corr + ts;
                #pragma unroll
                for (int nt = 0; nt < 8; nt++) {
                    o[mt][nt][2 * h]     *= corr;
                    o[mt][nt][2 * h + 1] *= corr;
                }
            }
        }

        #pragma unroll
        for (int ks = 0; ks < 4; ks++) {
            uint32_t ap[2][4];
            #pragma unroll
            for (int mt = 0; mt < 2; mt++) {
                ap[mt][0] = pack_h2(c[mt][2 * ks][0],     c[mt][2 * ks][1]);
                ap[mt][1] = pack_h2(c[mt][2 * ks][2],     c[mt][2 * ks][3]);
                ap[mt][2] = pack_h2(c[mt][2 * ks + 1][0], c[mt][2 * ks + 1][1]);
                ap[mt][3] = pack_h2(c[mt][2 * ks + 1][2], c[mt][2 * ks + 1][3]);
            }
            #pragma unroll
            for (int ng = 0; ng < 4; ng++) {
                uint32_t bh[4], bsh[2][2];
                ldm_x4_t(bh, Vbase + (uint32_t)((ks * 16 + (lane & 15)) * 144
                                                + (ng * 16) * 2 + (lane >> 4) * 16));
                bsh[0][0] = bh[0]; bsh[0][1] = bh[1]; bsh[1][0] = bh[2]; bsh[1][1] = bh[3];
                #pragma unroll
                for (int mt = 0; mt < 2; mt++)
                    #pragma unroll
                    for (int h2 = 0; h2 < 2; h2++)
                        mma_f16(o[mt][ng * 2 + h2], ap[mt], bsh[h2]);
            }
        }
        __syncthreads();
    }

    #pragma unroll
    for (int mt = 0; mt < 2; mt++) {
        #pragma unroll
        for (int h = 0; h < 2; h++) {
            float inv = 1.f / lsum[mt][h];
            int row = bq * 128 + wbase + mt * 16 + (lane >> 2) + h * 8;
            size_t ro = (size_t)(b * TT + row) * DD + hd * HDD;
            #pragma unroll
            for (int nt = 0; nt < 8; nt++) {
                int col = nt * 8 + (lane & 3) * 2;
                __half2 hh, ll;
                split2h(o[mt][nt][2 * h] * inv, o[mt][nt][2 * h + 1] * inv, hh, ll);
                *(__half2*)&oh[ro + col] = hh;
                *(__half2*)&ol[ro + col] = ll;
            }
        }
    }
}

extern "C" void kernel_launch(void* const* d_in, const int* in_sizes, int n_in,
                              void* d_out, int out_size) {
    const int*   ids    = (const int*)  d_in[0];
    const float* wte    = (const float*)d_in[1];
    const float* wpe    = (const float*)d_in[2];
    const float* ln1_g  = (const float*)d_in[3];
    const float* ln1_b  = (const float*)d_in[4];
    const float* attn_w = (const float*)d_in[5];
    const float* attn_b = (const float*)d_in[6];
    const float* proj_w = (const float*)d_in[7];
    const float* proj_b = (const float*)d_in[8];
    const float* ln2_g  = (const float*)d_in[9];
    const float* ln2_b  = (const float*)d_in[10];
    const float* fc_w   = (const float*)d_in[11];
    const float* fc_b   = (const float*)d_in[12];
    const float* out_w  = (const float*)d_in[13];
    const float* out_b  = (const float*)d_in[14];
    const float* lnf_g  = (const float*)d_in[15];
    const float* lnf_b  = (const float*)d_in[16];
    float* logits = (float*)d_out;

    float *x, *qkv;
    __half *hh, *hl, *ath, *atl, *mph;
    __half *wq, *wp, *wf, *wo, *wt;
    cudaGetSymbolAddress((void**)&x,   g_x);
    cudaGetSymbolAddress((void**)&qkv, g_qkv);
    cudaGetSymbolAddress((void**)&hh,  g_hh);  cudaGetSymbolAddress((void**)&hl,  g_hl);
    cudaGetSymbolAddress((void**)&ath, g_ath); cudaGetSymbolAddress((void**)&atl, g_atl);
    cudaGetSymbolAddress((void**)&mph, g_mph);
    cudaGetSymbolAddress((void**)&wq,  g_wq);
    cudaGetSymbolAddress((void**)&wp,  g_wp);
    cudaGetSymbolAddress((void**)&wf,  g_wf);
    cudaGetSymbolAddress((void**)&wo,  g_wo);
    cudaGetSymbolAddress((void**)&wt,  g_wt);

    cudaFuncSetAttribute(gemm_f16<EPI_BIAS,      true,  0, true,  128, 128>, cudaFuncAttributeMaxDynamicSharedMemorySize, GSM_QKV);
    cudaFuncSetAttribute(gemm_f16<EPI_BIAS_RES,  true,  0, true,  64,  128>, cudaFuncAttributeMaxDynamicSharedMemorySize, GSM_PROJ);
    cudaFuncSetAttribute(gemm_f16<EPI_BIAS_GELU, true,  2, false, 128, 128>, cudaFuncAttributeMaxDynamicSharedMemorySize, GSM_FC);
    cudaFuncSetAttribute(gemm_f16<EPI_BIAS_RES,  true,  0, false, 64,  128>, cudaFuncAttributeMaxDynamicSharedMemorySize, GSM_OUT);
    cudaFuncSetAttribute(gemm_f16<EPI_NONE,      false, 0, false, 128, 256>, cudaFuncAttributeMaxDynamicSharedMemorySize, GSM_LMH);

    {
        long blocks = (NALL2 + 255) / 256;
        conv_all<<<(int)blocks, 256>>>(attn_w, proj_w, fc_w, out_w, wte,
                                       wq, wp, wf, wo, wt);
    }

    embed_k<<<MTOK, 256>>>(ids, wte, wpe, x);

    for (int l = 0; l < LL; l++) {
        // attention block
        ln_k<<<MTOK, 256>>>(x, ln1_g + l * DD, ln1_b + l * DD, hh, hl);
        gemm_f16<EPI_BIAS, true, 0, true, 128, 128><<<dim3(3 * DD / 128, MTOK / 128), 256, GSM_QKV>>>(
            hh, hl, wq + (size_t)l * DD * 3 * DD,
            attn_b + (size_t)l * 3 * DD, nullptr, qkv, nullptr, nullptr, 3 * DD, DD);
        attn_k<<<dim3(TT / 128, HH, BB), 128>>>(qkv, ath, atl);
        gemm_f16<EPI_BIAS_RES, true, 0, true, 64, 128><<<dim3(DD / 128, MTOK / 64), 256, GSM_PROJ>>>(
            ath, atl, wp + (size_t)l * DD * DD,
            proj_b + (size_t)l * DD, x, x, nullptr, nullptr, DD, DD);
        // mlp block (A unsplit: fc reads hi plane only; gelu out stored hi-only)
        ln_k<<<MTOK, 256>>>(x, ln2_g + l * DD, ln2_b + l * DD, hh, hl);
        gemm_f16<EPI_BIAS_GELU, true, 2, false, 128, 128><<<dim3(4 * DD / 128, MTOK / 128), 256, GSM_FC>>>(
            hh, nullptr, wf + (size_t)l * DD * 4 * DD,
            fc_b + (size_t)l * 4 * DD, nullptr, nullptr, mph, nullptr, 4 * DD, DD);
        gemm_f16<EPI_BIAS_RES, true, 0, false, 64, 128><<<dim3(DD / 128, MTOK / 64), 256, GSM_OUT>>>(
            mph, nullptr, wo + (size_t)l * 4 * DD * DD,
            out_b + (size_t)l * DD, x, x, nullptr, nullptr, DD, 4 * DD);
    }

    ln_k<<<MTOK, 256>>>(x, lnf_g, lnf_b, hh, hl);
    // lm-head: 128x256 tiles, single-MMA; row tiles fastest for wte L2 reuse
    gemm_f16<EPI_NONE, false, 0, false, 128, 256><<<dim3(MTOK / 128, (VV + 255) / 256), 256, GSM_LMH>>>(
        hh, nullptr, wt, nullptr, nullptr, logits, nullptr, nullptr, VV, DD);
}